// round 1
// baseline (speedup 1.0000x reference)
#include <cuda_runtime.h>
#include <cstdint>
#include <cstddef>

// ---------------------------------------------------------------------------
// GraphMoEDualRouter — GB300 sm_103a
//
// Pipeline per call (all on stream 0, graph-capturable, no allocations):
//   1. per-graph node/edge histograms -> structural router logits (64 graphs)
//   2. h = relu(x[:,4:10] @ W_enc + b_enc)
//   3. hs = relu(h @ Ws1 + bs1)  (GEMM) ; logits -> top-2 sparse gates
//   4. counting-sort edges by dst -> CSR (rowptr, colsrc)   [no float atomics]
//   5. agg0 = segsum(h)   (shared across all experts: layer-0 z == h)
//   6. per expert e: 3 fused dual-GEMM layers + 2 per-expert aggs,
//      final layer fused with   out += sparse[:,e] * z3
//
// GEMM inner loop uses packed fma.rn.f32x2 (2x scalar FFMA throughput).
// ---------------------------------------------------------------------------

#define HDIM 256
#define NEXP 8
#define NGRAPH 64
#define MAXN 50176
#define MAXE 1600000

typedef unsigned long long ull;

// ---- scratch (static device memory; allocation is forbidden) ----
__device__ float g_h   [MAXN * HDIM];
__device__ float g_z1  [MAXN * HDIM];
__device__ float g_z2  [MAXN * HDIM];
__device__ float g_agg0[MAXN * HDIM];
__device__ float g_aggT[MAXN * HDIM];
__device__ float g_sparse[MAXN * NEXP];
__device__ int   g_deg   [MAXN];
__device__ int   g_rowptr[MAXN + 1];
__device__ int   g_cursor[MAXN];
__device__ int   g_colsrc[MAXE];
__device__ int   g_ng[NGRAPH];
__device__ int   g_eg[NGRAPH];
__device__ float g_strug[NGRAPH * NEXP];

// ---- f32x2 helpers ----
__device__ __forceinline__ ull pack2(float lo, float hi) {
    ull r; asm("mov.b64 %0, {%1, %2};" : "=l"(r) : "f"(lo), "f"(hi)); return r;
}
__device__ __forceinline__ void fma2acc(ull& d, ull a, ull b) {
    asm("fma.rn.f32x2 %0, %1, %2, %0;" : "+l"(d) : "l"(a), "l"(b));
}
__device__ __forceinline__ void unpack2(ull v, float& lo, float& hi) {
    asm("mov.b64 {%0, %1}, %2;" : "=f"(lo), "=f"(hi) : "l"(v));
}

// ---------------------------------------------------------------------------
// Histograms (shared-memory 64-bin, then global atomics)
// ---------------------------------------------------------------------------
__global__ void k_hist_nodes(const int* __restrict__ batch, int* __restrict__ ng, int n) {
    __shared__ int sh[NGRAPH];
    if (threadIdx.x < NGRAPH) sh[threadIdx.x] = 0;
    __syncthreads();
    for (int i = blockIdx.x * blockDim.x + threadIdx.x; i < n; i += gridDim.x * blockDim.x)
        atomicAdd(&sh[batch[i]], 1);
    __syncthreads();
    if (threadIdx.x < NGRAPH) atomicAdd(&ng[threadIdx.x], sh[threadIdx.x]);
}

__global__ void k_hist_edges(const int* __restrict__ batch, const int* __restrict__ src,
                             int* __restrict__ eg, int e) {
    __shared__ int sh[NGRAPH];
    if (threadIdx.x < NGRAPH) sh[threadIdx.x] = 0;
    __syncthreads();
    for (int i = blockIdx.x * blockDim.x + threadIdx.x; i < e; i += gridDim.x * blockDim.x)
        atomicAdd(&sh[batch[src[i]]], 1);
    __syncthreads();
    if (threadIdx.x < NGRAPH) atomicAdd(&eg[threadIdx.x], sh[threadIdx.x]);
}

// ---------------------------------------------------------------------------
// Structural router: 64 graphs x (2 -> 256 relu -> 8). One block per graph.
// Output includes bt2 (raw structural logits, pre-0.5 scaling).
// ---------------------------------------------------------------------------
__global__ void k_stru(const int* __restrict__ ng, const int* __restrict__ eg,
                       const float* __restrict__ Wt1, const float* __restrict__ bt1,
                       const float* __restrict__ Wt2, const float* __restrict__ bt2,
                       float* __restrict__ strug) {
    int g = blockIdx.x;
    float fn = log1pf((float)ng[g]);
    float fe = log1pf((float)eg[g]);
    __shared__ float hid[HDIM];
    int j = threadIdx.x;
    hid[j] = fmaxf(fmaf(fn, Wt1[j], fmaf(fe, Wt1[HDIM + j], bt1[j])), 0.0f);
    __syncthreads();
    int w = threadIdx.x >> 5, lane = threadIdx.x & 31;
    if (w < NEXP) {
        float acc = 0.f;
        for (int k = lane; k < HDIM; k += 32) acc = fmaf(hid[k], Wt2[k * NEXP + w], acc);
        #pragma unroll
        for (int off = 16; off; off >>= 1) acc += __shfl_down_sync(0xffffffffu, acc, off);
        if (lane == 0) strug[g * NEXP + w] = acc + bt2[w];
    }
}

// ---------------------------------------------------------------------------
// Shared bus encoder: h = relu(x[:,4:10] @ W_enc + b_enc). One block per node.
// ---------------------------------------------------------------------------
__global__ void k_encode(const float* __restrict__ x, const float* __restrict__ W,
                         const float* __restrict__ b, float* __restrict__ h, int n) {
    int node = blockIdx.x;
    if (node >= n) return;
    __shared__ float xs[6];
    if (threadIdx.x < 6) xs[threadIdx.x] = x[node * 10 + 4 + threadIdx.x];
    __syncthreads();
    int j = threadIdx.x;
    float acc = b[j];
    #pragma unroll
    for (int k = 0; k < 6; k++) acc = fmaf(xs[k], W[k * HDIM + j], acc);
    h[(size_t)node * HDIM + j] = fmaxf(acc, 0.0f);
}

// ---------------------------------------------------------------------------
// Fused dual GEMM:  C = op( A @ W1 + B @ W2 + bias )       K = 256 fixed
//   - B may be null (single GEMM, router path)
//   - if sparse != null: final-layer combine
//       C[row,col] = (accum ? C[row,col] : 0) + sparse[row,expert] * val
// Tile: 128(M) x 64(N), BK=16, 256 threads, 8x4 outputs/thread,
// row-paired f32x2 accumulators.
// ---------------------------------------------------------------------------
#define BM 128
#define BN 64
#define BK 16

__global__ __launch_bounds__(256) void k_gemm(
    const float* __restrict__ A, const float* __restrict__ W1,
    const float* __restrict__ B, const float* __restrict__ W2,
    const float* __restrict__ bias, int n, int relu,
    float* __restrict__ C,
    const float* __restrict__ sparse, int expert, int accum)
{
    __shared__ __align__(16) float As[BK][BM + 2];
    __shared__ __align__(16) float Ws[BK][BN];

    int m0 = blockIdx.x * BM;
    int n0 = blockIdx.y * BN;
    int tid = threadIdx.x;
    int tm = tid >> 4;      // 0..15 -> rows tm*8 .. tm*8+7
    int tn = tid & 15;      // 0..15 -> cols tn*4 .. tn*4+3

    ull acc2[4][4];         // [row-pair][col], each packs rows (2*i2, 2*i2+1)
    #pragma unroll
    for (int i = 0; i < 4; i++)
        #pragma unroll
        for (int j = 0; j < 4; j++) acc2[i][j] = 0ull;

    int npass = (B != nullptr) ? 2 : 1;
    for (int pass = 0; pass < npass; pass++) {
        const float* Ap = pass ? B : A;
        const float* Wp = pass ? W2 : W1;
        for (int kc = 0; kc < HDIM; kc += BK) {
            // load A tile: 128 rows x 16 k  (512 float4 / 256 threads)
            #pragma unroll
            for (int u = 0; u < 2; u++) {
                int idx = tid + u * 256;
                int row = idx >> 2;
                int kq  = idx & 3;
                float4 v = make_float4(0.f, 0.f, 0.f, 0.f);
                int gr = m0 + row;
                if (gr < n) v = *(const float4*)(Ap + (size_t)gr * HDIM + kc + kq * 4);
                As[kq * 4 + 0][row] = v.x;
                As[kq * 4 + 1][row] = v.y;
                As[kq * 4 + 2][row] = v.z;
                As[kq * 4 + 3][row] = v.w;
            }
            // load W tile: 16 k x 64 cols (256 float4 / 256 threads)
            {
                int kk = tid >> 4, nq = tid & 15;
                float4 w = *(const float4*)(Wp + (size_t)(kc + kk) * HDIM + n0 + nq * 4);
                *(float4*)&Ws[kk][nq * 4] = w;
            }
            __syncthreads();
            #pragma unroll
            for (int kk = 0; kk < BK; kk++) {
                ull a2[4];
                #pragma unroll
                for (int i2 = 0; i2 < 4; i2++)
                    a2[i2] = *(const ull*)&As[kk][tm * 8 + i2 * 2];
                #pragma unroll
                for (int j = 0; j < 4; j++) {
                    float bb = Ws[kk][tn * 4 + j];
                    ull b2 = pack2(bb, bb);
                    #pragma unroll
                    for (int i2 = 0; i2 < 4; i2++) fma2acc(acc2[i2][j], a2[i2], b2);
                }
            }
            __syncthreads();
        }
    }

    float4 bb4 = *(const float4*)&bias[n0 + tn * 4];
    #pragma unroll
    for (int i2 = 0; i2 < 4; i2++) {
        float4 vlo, vhi;
        unpack2(acc2[i2][0], vlo.x, vhi.x);
        unpack2(acc2[i2][1], vlo.y, vhi.y);
        unpack2(acc2[i2][2], vlo.z, vhi.z);
        unpack2(acc2[i2][3], vlo.w, vhi.w);
        #pragma unroll
        for (int rr = 0; rr < 2; rr++) {
            int row = m0 + tm * 8 + i2 * 2 + rr;
            if (row >= n) continue;
            float4 v = rr ? vhi : vlo;
            v.x += bb4.x; v.y += bb4.y; v.z += bb4.z; v.w += bb4.w;
            if (relu) {
                v.x = fmaxf(v.x, 0.f); v.y = fmaxf(v.y, 0.f);
                v.z = fmaxf(v.z, 0.f); v.w = fmaxf(v.w, 0.f);
            }
            float4* op = (float4*)(C + (size_t)row * HDIM + n0 + tn * 4);
            if (sparse) {
                float s = sparse[(size_t)row * NEXP + expert];
                float4 o = accum ? *op : make_float4(0.f, 0.f, 0.f, 0.f);
                o.x = fmaf(s, v.x, o.x); o.y = fmaf(s, v.y, o.y);
                o.z = fmaf(s, v.z, o.z); o.w = fmaf(s, v.w, o.w);
                *op = o;
            } else {
                *op = v;
            }
        }
    }
}

// ---------------------------------------------------------------------------
// Router logits + top-2 sparse gates. One warp per node.
// ---------------------------------------------------------------------------
__global__ void k_logits(const float* __restrict__ hs, const float* __restrict__ Ws2,
                         const float* __restrict__ bs2, const float* __restrict__ strug,
                         const int* __restrict__ batch, float* __restrict__ sparse, int n) {
    int warp = (blockIdx.x * blockDim.x + threadIdx.x) >> 5;
    int lane = threadIdx.x & 31;
    if (warp >= n) return;
    const float* row = hs + (size_t)warp * HDIM;
    float acc[NEXP];
    #pragma unroll
    for (int o = 0; o < NEXP; o++) acc[o] = 0.f;
    for (int k = lane; k < HDIM; k += 32) {
        float v = row[k];
        const float* w2 = Ws2 + k * NEXP;
        #pragma unroll
        for (int o = 0; o < NEXP; o++) acc[o] = fmaf(v, w2[o], acc[o]);
    }
    #pragma unroll
    for (int o = 0; o < NEXP; o++)
        #pragma unroll
        for (int off = 16; off; off >>= 1) acc[o] += __shfl_down_sync(0xffffffffu, acc[o], off);
    if (lane == 0) {
        int g = batch[warp];
        float lg[NEXP];
        #pragma unroll
        for (int o = 0; o < NEXP; o++)
            lg[o] = 0.5f * (acc[o] + bs2[o]) + 0.5f * strug[g * NEXP + o];
        // top-2 (lowest index wins ties, matching lax.top_k)
        float m1 = -3.4e38f; int i1 = 0;
        #pragma unroll
        for (int o = 0; o < NEXP; o++) if (lg[o] > m1) { m1 = lg[o]; i1 = o; }
        float m2 = -3.4e38f; int i2 = 0;
        #pragma unroll
        for (int o = 0; o < NEXP; o++) if (o != i1 && lg[o] > m2) { m2 = lg[o]; i2 = o; }
        float e2 = __expf(m2 - m1);          // m1 >= m2, stable
        float inv = 1.0f / (1.0f + e2);
        float* srow = sparse + (size_t)warp * NEXP;
        #pragma unroll
        for (int o = 0; o < NEXP; o++) srow[o] = 0.f;
        srow[i1] = inv;
        srow[i2] = e2 * inv;
    }
}

// ---------------------------------------------------------------------------
// Counting sort of edges by dst -> CSR
// ---------------------------------------------------------------------------
__global__ void k_deg(const int* __restrict__ dst, int* __restrict__ deg, int e) {
    int i = blockIdx.x * blockDim.x + threadIdx.x;
    if (i < e) atomicAdd(&deg[dst[i]], 1);
}

__global__ void k_scan(const int* __restrict__ deg, int* __restrict__ rowptr,
                       int* __restrict__ cursor, int n) {
    __shared__ int sh[1024];
    __shared__ int carry;
    if (threadIdx.x == 0) { carry = 0; rowptr[0] = 0; }
    __syncthreads();
    for (int base = 0; base < n; base += 1024) {
        int i = base + (int)threadIdx.x;
        int v = (i < n) ? deg[i] : 0;
        sh[threadIdx.x] = v;
        __syncthreads();
        #pragma unroll
        for (int off = 1; off < 1024; off <<= 1) {
            int t = (threadIdx.x >= (unsigned)off) ? sh[threadIdx.x - off] : 0;
            __syncthreads();
            sh[threadIdx.x] += t;
            __syncthreads();
        }
        int inc = sh[threadIdx.x] + carry;
        if (i < n) { rowptr[i + 1] = inc; cursor[i] = inc - v; }
        __syncthreads();
        if (threadIdx.x == 1023) carry = inc;
        __syncthreads();
    }
}

__global__ void k_sortedges(const int* __restrict__ src, const int* __restrict__ dst,
                            int* __restrict__ cursor, int* __restrict__ colsrc, int e) {
    int i = blockIdx.x * blockDim.x + threadIdx.x;
    if (i < e) {
        int d = dst[i];
        int p = atomicAdd(&cursor[d], 1);
        colsrc[p] = src[i];
    }
}

// ---------------------------------------------------------------------------
// CSR gather aggregation: agg[n,:] = sum over in-edges of z[src,:]
// One block (256 threads = 256 feature cols) per node. No atomics.
// ---------------------------------------------------------------------------
__global__ __launch_bounds__(256) void k_agg(const float* __restrict__ z,
                                             float* __restrict__ agg,
                                             const int* __restrict__ rowptr,
                                             const int* __restrict__ colsrc, int n) {
    int node = blockIdx.x;
    if (node >= n) return;
    int c = threadIdx.x;
    int s0 = rowptr[node], s1 = rowptr[node + 1];
    float a0 = 0.f, a1 = 0.f, a2 = 0.f, a3 = 0.f;
    int i = s0;
    for (; i + 3 < s1; i += 4) {
        int sA = colsrc[i], sB = colsrc[i + 1], sC = colsrc[i + 2], sD = colsrc[i + 3];
        a0 += z[(size_t)sA * HDIM + c];
        a1 += z[(size_t)sB * HDIM + c];
        a2 += z[(size_t)sC * HDIM + c];
        a3 += z[(size_t)sD * HDIM + c];
    }
    for (; i < s1; i++) a0 += z[(size_t)colsrc[i] * HDIM + c];
    agg[(size_t)node * HDIM + c] = (a0 + a1) + (a2 + a3);
}

// ---------------------------------------------------------------------------
// host launch
// ---------------------------------------------------------------------------
extern "C" void kernel_launch(void* const* d_in, const int* in_sizes, int n_in,
                              void* d_out, int out_size) {
    const float* x      = (const float*)d_in[0];
    const int*   ei     = (const int*)  d_in[1];
    const int*   batch  = (const int*)  d_in[2];
    const float* W_enc  = (const float*)d_in[3];
    const float* b_enc  = (const float*)d_in[4];
    const float* Ws1    = (const float*)d_in[5];
    const float* bs1    = (const float*)d_in[6];
    const float* Ws2    = (const float*)d_in[7];
    const float* bs2    = (const float*)d_in[8];
    const float* Wt1    = (const float*)d_in[9];
    const float* bt1    = (const float*)d_in[10];
    const float* Wt2    = (const float*)d_in[11];
    const float* bt2    = (const float*)d_in[12];
    const float* W_self = (const float*)d_in[13];
    const float* W_nei  = (const float*)d_in[14];
    const float* b_exp  = (const float*)d_in[15];

    int N = in_sizes[0] / 10;
    int E = in_sizes[1] / 2;
    const int* src = ei;
    const int* dst = ei + E;
    float* out = (float*)d_out;

    float *h, *z1, *z2, *agg0, *aggT, *sparse, *strug;
    int *deg, *rowptr, *cursor, *colsrc, *ng, *eg;
    cudaGetSymbolAddress((void**)&h,      g_h);
    cudaGetSymbolAddress((void**)&z1,     g_z1);
    cudaGetSymbolAddress((void**)&z2,     g_z2);
    cudaGetSymbolAddress((void**)&agg0,   g_agg0);
    cudaGetSymbolAddress((void**)&aggT,   g_aggT);
    cudaGetSymbolAddress((void**)&sparse, g_sparse);
    cudaGetSymbolAddress((void**)&strug,  g_strug);
    cudaGetSymbolAddress((void**)&deg,    g_deg);
    cudaGetSymbolAddress((void**)&rowptr, g_rowptr);
    cudaGetSymbolAddress((void**)&cursor, g_cursor);
    cudaGetSymbolAddress((void**)&colsrc, g_colsrc);
    cudaGetSymbolAddress((void**)&ng,     g_ng);
    cudaGetSymbolAddress((void**)&eg,     g_eg);

    cudaMemsetAsync(ng,  0, NGRAPH * sizeof(int), 0);
    cudaMemsetAsync(eg,  0, NGRAPH * sizeof(int), 0);
    cudaMemsetAsync(deg, 0, (size_t)N * sizeof(int), 0);

    // routers' structural branch + encoder
    k_hist_nodes<<<128, 256>>>(batch, ng, N);
    k_hist_edges<<<256, 256>>>(batch, src, eg, E);
    k_stru<<<NGRAPH, 256>>>(ng, eg, Wt1, bt1, Wt2, bt2, strug);
    k_encode<<<N, 256>>>(x, W_enc, b_enc, h, N);

    dim3 ggrid((N + BM - 1) / BM, HDIM / BN);

    // semantic router: hs = relu(h @ Ws1 + bs1) -> z1, then gates
    k_gemm<<<ggrid, 256>>>(h, Ws1, nullptr, nullptr, bs1, N, 1, z1, nullptr, 0, 0);
    k_logits<<<(N + 7) / 8, 256>>>(z1, Ws2, bs2, strug, batch, sparse, N);

    // CSR build
    k_deg<<<(E + 255) / 256, 256>>>(dst, deg, E);
    k_scan<<<1, 1024>>>(deg, rowptr, cursor, N);
    k_sortedges<<<(E + 255) / 256, 256>>>(src, dst, cursor, colsrc, E);

    // layer-0 aggregation shared by all experts (z == h)
    k_agg<<<N, 256>>>(h, agg0, rowptr, colsrc, N);

    for (int e = 0; e < NEXP; e++) {
        const float* Ws_l0 = W_self + (size_t)(e * 3 + 0) * HDIM * HDIM;
        const float* Ws_l1 = W_self + (size_t)(e * 3 + 1) * HDIM * HDIM;
        const float* Ws_l2 = W_self + (size_t)(e * 3 + 2) * HDIM * HDIM;
        const float* Wn_l0 = W_nei  + (size_t)(e * 3 + 0) * HDIM * HDIM;
        const float* Wn_l1 = W_nei  + (size_t)(e * 3 + 1) * HDIM * HDIM;
        const float* Wn_l2 = W_nei  + (size_t)(e * 3 + 2) * HDIM * HDIM;
        const float* b_l0  = b_exp + (size_t)(e * 3 + 0) * HDIM;
        const float* b_l1  = b_exp + (size_t)(e * 3 + 1) * HDIM;
        const float* b_l2  = b_exp + (size_t)(e * 3 + 2) * HDIM;

        k_gemm<<<ggrid, 256>>>(h, Ws_l0, agg0, Wn_l0, b_l0, N, 1, z1, nullptr, 0, 0);
        k_agg<<<N, 256>>>(z1, aggT, rowptr, colsrc, N);
        k_gemm<<<ggrid, 256>>>(z1, Ws_l1, aggT, Wn_l1, b_l1, N, 1, z2, nullptr, 0, 0);
        k_agg<<<N, 256>>>(z2, aggT, rowptr, colsrc, N);
        // final layer fused with sparse gating into out
        k_gemm<<<ggrid, 256>>>(z2, Ws_l2, aggT, Wn_l2, b_l2, N, 0, out, sparse, e, (e > 0) ? 1 : 0);
    }
}

// round 4
// speedup vs baseline: 1.8555x; 1.8555x over previous
#include <cuda_runtime.h>
#include <cstdint>
#include <cstddef>

// ---------------------------------------------------------------------------
// GraphMoEDualRouter — GB300 sm_103a (family-generic build: no tcgen05).
// Expert GEMMs on mma.sync.m16n8k8 tf32 (fallback HMMA pipe).
// ---------------------------------------------------------------------------

#define HDIM 256
#define NEXP 8
#define NGRAPH 64
#define MAXN 50176
#define MAXE 1600000

typedef unsigned long long ull;

// ---- scratch (static device memory; allocation is forbidden) ----
__device__ float g_h   [MAXN * HDIM];
__device__ float g_z1  [MAXN * HDIM];
__device__ float g_z2  [MAXN * HDIM];
__device__ float g_agg0[MAXN * HDIM];
__device__ float g_aggT[MAXN * HDIM];
__device__ float g_sparse[MAXN * NEXP];
__device__ int   g_deg   [MAXN];
__device__ int   g_rowptr[MAXN + 1];
__device__ int   g_cursor[MAXN];
__device__ int   g_colsrc[MAXE];
__device__ int   g_ng[NGRAPH];
__device__ int   g_eg[NGRAPH];
__device__ float g_strug[NGRAPH * NEXP];
// packed transposed weights, tf32-converted bit patterns: [24 mats][256 n][512 k]
__device__ float g_wT[24 * 256 * 512];

// ---- helpers ----
__device__ __forceinline__ uint32_t f2tf32(float f) {
    uint32_t u; asm("cvt.rna.tf32.f32 %0, %1;" : "=r"(u) : "f"(f)); return u;
}
__device__ __forceinline__ ull pack2(float lo, float hi) {
    ull r; asm("mov.b64 %0, {%1, %2};" : "=l"(r) : "f"(lo), "f"(hi)); return r;
}
__device__ __forceinline__ void fma2acc(ull& d, ull a, ull b) {
    asm("fma.rn.f32x2 %0, %1, %2, %0;" : "+l"(d) : "l"(a), "l"(b));
}
__device__ __forceinline__ void unpack2(ull v, float& lo, float& hi) {
    asm("mov.b64 {%0, %1}, %2;" : "=f"(lo), "=f"(hi) : "l"(v));
}
__device__ __forceinline__ void mma_tf32(float* d, const uint32_t* a, const uint32_t* b) {
    asm volatile(
        "mma.sync.aligned.m16n8k8.row.col.f32.tf32.tf32.f32 "
        "{%0,%1,%2,%3}, {%4,%5,%6,%7}, {%8,%9}, {%0,%1,%2,%3};"
        : "+f"(d[0]), "+f"(d[1]), "+f"(d[2]), "+f"(d[3])
        : "r"(a[0]), "r"(a[1]), "r"(a[2]), "r"(a[3]), "r"(b[0]), "r"(b[1]));
}

// ===========================================================================
// Small kernels
// ===========================================================================
__global__ void k_hist_nodes(const int* __restrict__ batch, int* __restrict__ ng, int n) {
    __shared__ int sh[NGRAPH];
    if (threadIdx.x < NGRAPH) sh[threadIdx.x] = 0;
    __syncthreads();
    for (int i = blockIdx.x * blockDim.x + threadIdx.x; i < n; i += gridDim.x * blockDim.x)
        atomicAdd(&sh[batch[i]], 1);
    __syncthreads();
    if (threadIdx.x < NGRAPH) atomicAdd(&ng[threadIdx.x], sh[threadIdx.x]);
}

__global__ void k_hist_edges(const int* __restrict__ batch, const int* __restrict__ src,
                             int* __restrict__ eg, int e) {
    __shared__ int sh[NGRAPH];
    if (threadIdx.x < NGRAPH) sh[threadIdx.x] = 0;
    __syncthreads();
    for (int i = blockIdx.x * blockDim.x + threadIdx.x; i < e; i += gridDim.x * blockDim.x)
        atomicAdd(&sh[batch[src[i]]], 1);
    __syncthreads();
    if (threadIdx.x < NGRAPH) atomicAdd(&eg[threadIdx.x], sh[threadIdx.x]);
}

__global__ void k_stru(const int* __restrict__ ng, const int* __restrict__ eg,
                       const float* __restrict__ Wt1, const float* __restrict__ bt1,
                       const float* __restrict__ Wt2, const float* __restrict__ bt2,
                       float* __restrict__ strug) {
    int g = blockIdx.x;
    float fn = log1pf((float)ng[g]);
    float fe = log1pf((float)eg[g]);
    __shared__ float hid[HDIM];
    int j = threadIdx.x;
    hid[j] = fmaxf(fmaf(fn, Wt1[j], fmaf(fe, Wt1[HDIM + j], bt1[j])), 0.0f);
    __syncthreads();
    int w = threadIdx.x >> 5, lane = threadIdx.x & 31;
    if (w < NEXP) {
        float acc = 0.f;
        for (int k = lane; k < HDIM; k += 32) acc = fmaf(hid[k], Wt2[k * NEXP + w], acc);
        #pragma unroll
        for (int off = 16; off; off >>= 1) acc += __shfl_down_sync(0xffffffffu, acc, off);
        if (lane == 0) strug[g * NEXP + w] = acc + bt2[w];
    }
}

__global__ void k_encode(const float* __restrict__ x, const float* __restrict__ W,
                         const float* __restrict__ b, float* __restrict__ h, int n) {
    int node = blockIdx.x;
    if (node >= n) return;
    __shared__ float xs[6];
    if (threadIdx.x < 6) xs[threadIdx.x] = x[node * 10 + 4 + threadIdx.x];
    __syncthreads();
    int j = threadIdx.x;
    float acc = b[j];
    #pragma unroll
    for (int k = 0; k < 6; k++) acc = fmaf(xs[k], W[k * HDIM + j], acc);
    h[(size_t)node * HDIM + j] = fmaxf(acc, 0.0f);
}

// ===========================================================================
// FFMA fp32 GEMM — router hidden layer only (top-2 selection needs exactness)
// ===========================================================================
#define BMR 128
#define BNR 64
#define BKR 16

__global__ __launch_bounds__(256) void k_gemm(
    const float* __restrict__ A, const float* __restrict__ W1,
    const float* __restrict__ bias, int n, float* __restrict__ C)
{
    __shared__ __align__(16) float As[BKR][BMR + 2];
    __shared__ __align__(16) float Ws[BKR][BNR];

    int m0 = blockIdx.x * BMR;
    int n0 = blockIdx.y * BNR;
    int tid = threadIdx.x;
    int tm = tid >> 4;
    int tn = tid & 15;

    ull acc2[4][4];
    #pragma unroll
    for (int i = 0; i < 4; i++)
        #pragma unroll
        for (int j = 0; j < 4; j++) acc2[i][j] = 0ull;

    for (int kc = 0; kc < HDIM; kc += BKR) {
        #pragma unroll
        for (int u = 0; u < 2; u++) {
            int idx = tid + u * 256;
            int row = idx >> 2;
            int kq  = idx & 3;
            float4 v = make_float4(0.f, 0.f, 0.f, 0.f);
            int gr = m0 + row;
            if (gr < n) v = *(const float4*)(A + (size_t)gr * HDIM + kc + kq * 4);
            As[kq * 4 + 0][row] = v.x;
            As[kq * 4 + 1][row] = v.y;
            As[kq * 4 + 2][row] = v.z;
            As[kq * 4 + 3][row] = v.w;
        }
        {
            int kk = tid >> 4, nq = tid & 15;
            float4 w = *(const float4*)(W1 + (size_t)(kc + kk) * HDIM + n0 + nq * 4);
            *(float4*)&Ws[kk][nq * 4] = w;
        }
        __syncthreads();
        #pragma unroll
        for (int kk = 0; kk < BKR; kk++) {
            ull a2[4];
            #pragma unroll
            for (int i2 = 0; i2 < 4; i2++)
                a2[i2] = *(const ull*)&As[kk][tm * 8 + i2 * 2];
            #pragma unroll
            for (int j = 0; j < 4; j++) {
                float bb = Ws[kk][tn * 4 + j];
                ull b2 = pack2(bb, bb);
                #pragma unroll
                for (int i2 = 0; i2 < 4; i2++) fma2acc(acc2[i2][j], a2[i2], b2);
            }
        }
        __syncthreads();
    }

    float4 bb4 = *(const float4*)&bias[n0 + tn * 4];
    #pragma unroll
    for (int i2 = 0; i2 < 4; i2++) {
        float4 vlo, vhi;
        unpack2(acc2[i2][0], vlo.x, vhi.x);
        unpack2(acc2[i2][1], vlo.y, vhi.y);
        unpack2(acc2[i2][2], vlo.z, vhi.z);
        unpack2(acc2[i2][3], vlo.w, vhi.w);
        #pragma unroll
        for (int rr = 0; rr < 2; rr++) {
            int row = m0 + tm * 8 + i2 * 2 + rr;
            if (row >= n) continue;
            float4 v = rr ? vhi : vlo;
            v.x = fmaxf(v.x + bb4.x, 0.f); v.y = fmaxf(v.y + bb4.y, 0.f);
            v.z = fmaxf(v.z + bb4.z, 0.f); v.w = fmaxf(v.w + bb4.w, 0.f);
            *(float4*)(C + (size_t)row * HDIM + n0 + tn * 4) = v;
        }
    }
}

// ===========================================================================
// Router logits + top-2 sparse gates
// ===========================================================================
__global__ void k_logits(const float* __restrict__ hs, const float* __restrict__ Ws2,
                         const float* __restrict__ bs2, const float* __restrict__ strug,
                         const int* __restrict__ batch, float* __restrict__ sparse, int n) {
    int warp = (blockIdx.x * blockDim.x + threadIdx.x) >> 5;
    int lane = threadIdx.x & 31;
    if (warp >= n) return;
    const float* row = hs + (size_t)warp * HDIM;
    float acc[NEXP];
    #pragma unroll
    for (int o = 0; o < NEXP; o++) acc[o] = 0.f;
    for (int k = lane; k < HDIM; k += 32) {
        float v = row[k];
        const float* w2 = Ws2 + k * NEXP;
        #pragma unroll
        for (int o = 0; o < NEXP; o++) acc[o] = fmaf(v, w2[o], acc[o]);
    }
    #pragma unroll
    for (int o = 0; o < NEXP; o++)
        #pragma unroll
        for (int off = 16; off; off >>= 1) acc[o] += __shfl_down_sync(0xffffffffu, acc[o], off);
    if (lane == 0) {
        int g = batch[warp];
        float lg[NEXP];
        #pragma unroll
        for (int o = 0; o < NEXP; o++)
            lg[o] = 0.5f * (acc[o] + bs2[o]) + 0.5f * strug[g * NEXP + o];
        float m1 = -3.4e38f; int i1 = 0;
        #pragma unroll
        for (int o = 0; o < NEXP; o++) if (lg[o] > m1) { m1 = lg[o]; i1 = o; }
        float m2 = -3.4e38f; int i2 = 0;
        #pragma unroll
        for (int o = 0; o < NEXP; o++) if (o != i1 && lg[o] > m2) { m2 = lg[o]; i2 = o; }
        float e2 = __expf(m2 - m1);
        float inv = 1.0f / (1.0f + e2);
        float* srow = sparse + (size_t)warp * NEXP;
        #pragma unroll
        for (int o = 0; o < NEXP; o++) srow[o] = 0.f;
        srow[i1] = inv;
        srow[i2] = e2 * inv;
    }
}

// ===========================================================================
// CSR build (counting sort by dst)
// ===========================================================================
__global__ void k_deg(const int* __restrict__ dst, int* __restrict__ deg, int e) {
    int i = blockIdx.x * blockDim.x + threadIdx.x;
    if (i < e) atomicAdd(&deg[dst[i]], 1);
}

__global__ void k_scan(const int* __restrict__ deg, int* __restrict__ rowptr,
                       int* __restrict__ cursor, int n) {
    __shared__ int sh[1024];
    __shared__ int carry;
    if (threadIdx.x == 0) { carry = 0; rowptr[0] = 0; }
    __syncthreads();
    for (int base = 0; base < n; base += 1024) {
        int i = base + (int)threadIdx.x;
        int v = (i < n) ? deg[i] : 0;
        sh[threadIdx.x] = v;
        __syncthreads();
        #pragma unroll
        for (int off = 1; off < 1024; off <<= 1) {
            int t = (threadIdx.x >= (unsigned)off) ? sh[threadIdx.x - off] : 0;
            __syncthreads();
            sh[threadIdx.x] += t;
            __syncthreads();
        }
        int inc = sh[threadIdx.x] + carry;
        if (i < n) { rowptr[i + 1] = inc; cursor[i] = inc - v; }
        __syncthreads();
        if (threadIdx.x == 1023) carry = inc;
        __syncthreads();
    }
}

__global__ void k_sortedges(const int* __restrict__ src, const int* __restrict__ dst,
                            int* __restrict__ cursor, int* __restrict__ colsrc, int e) {
    int i = blockIdx.x * blockDim.x + threadIdx.x;
    if (i < e) {
        int d = dst[i];
        int p = atomicAdd(&cursor[d], 1);
        colsrc[p] = src[i];
    }
}

// ===========================================================================
// CSR gather aggregation (no atomics)
// ===========================================================================
__global__ __launch_bounds__(256) void k_agg(const float* __restrict__ z,
                                             float* __restrict__ agg,
                                             const int* __restrict__ rowptr,
                                             const int* __restrict__ colsrc, int n) {
    int node = blockIdx.x;
    if (node >= n) return;
    int c = threadIdx.x;
    int s0 = rowptr[node], s1 = rowptr[node + 1];
    float a0 = 0.f, a1 = 0.f, a2 = 0.f, a3 = 0.f;
    int i = s0;
    for (; i + 3 < s1; i += 4) {
        int sA = colsrc[i], sB = colsrc[i + 1], sC = colsrc[i + 2], sD = colsrc[i + 3];
        a0 += z[(size_t)sA * HDIM + c];
        a1 += z[(size_t)sB * HDIM + c];
        a2 += z[(size_t)sC * HDIM + c];
        a3 += z[(size_t)sD * HDIM + c];
    }
    for (; i < s1; i++) a0 += z[(size_t)colsrc[i] * HDIM + c];
    agg[(size_t)node * HDIM + c] = (a0 + a1) + (a2 + a3);
}

// ===========================================================================
// Weight pack: wT[mat][n][k] = tf32( k<256 ? Wself[mat][k][n] : Wnei[mat][k-256][n] )
// ===========================================================================
__global__ void k_pack(const float* __restrict__ Wself, const float* __restrict__ Wnei,
                       uint32_t* __restrict__ wT) {
    int idx = blockIdx.x * 256 + threadIdx.x;
    int k = idx & 511;
    int rem = idx >> 9;
    int nrow = rem & 255;
    int mat = rem >> 8;
    const float* srcp = (k < 256) ? Wself : Wnei;
    int kk = k & 255;
    float v = srcp[((size_t)mat * 256 + kk) * 256 + nrow];
    wT[idx] = f2tf32(v);
}

// ===========================================================================
// mma.sync tf32 dual GEMM:  C[:,n0:n0+128] = op( [Az|Ag] @ WT^T + bias )
// BM=128, BN=128, BK=32 (16 chunks over virtual K=512), 256 thr = 8 warps,
// warp tile 32(m) x 64(n). Double-buffered SMEM + register staging.
// Epilogue: +bias, optional relu, optional sparse-gated accumulate into C.
// ===========================================================================
#define PAD 36
#define ABUF (128 * PAD)          // floats per A buffer
#define TM_SMEM (4 * ABUF * 4)    // bytes: A0,A1,B0,B1

__global__ __launch_bounds__(256, 1) void k_tmma(
    const float* __restrict__ Az, const float* __restrict__ Ag,
    const float* __restrict__ WT, const float* __restrict__ bias,
    int n, int relu, float* __restrict__ C,
    const float* __restrict__ sparse, int expert, int accum)
{
    extern __shared__ float smf[];
    float* As[2] = { smf,            smf + ABUF };
    float* Bs[2] = { smf + 2 * ABUF, smf + 3 * ABUF };

    int tid = threadIdx.x;
    int warp = tid >> 5, lane = tid & 31;
    int m0 = blockIdx.x * 128;
    int n0 = blockIdx.y * 128;
    int m_off = (warp >> 1) * 32;     // warp m tile
    int n_off = (warp & 1) * 64;      // warp n tile
    int g = lane >> 2, t = lane & 3;

    int lrow = tid >> 3;              // 0..31 (row stride 32 per i)
    int kq4  = (tid & 7) * 4;         // 0,4,...,28

    float acc[2][8][4];
    #pragma unroll
    for (int i = 0; i < 2; i++)
        #pragma unroll
        for (int j = 0; j < 8; j++)
            #pragma unroll
            for (int r = 0; r < 4; r++) acc[i][j][r] = 0.f;

    float4 ra[4], rb[4];

    // ---- chunk loader (to registers) ----
    auto load_chunk = [&](int c) {
        const float* Asrc = (c < 8) ? Az : Ag;
        int kb = (c & 7) * 32;
        #pragma unroll
        for (int i = 0; i < 4; i++) {
            int row = lrow + i * 32;
            int gr = m0 + row;
            ra[i] = (gr < n) ? *(const float4*)(Asrc + (size_t)gr * HDIM + kb + kq4)
                             : make_float4(0.f, 0.f, 0.f, 0.f);
            rb[i] = *(const float4*)(WT + (size_t)(n0 + row) * 512 + c * 32 + kq4);
        }
    };
    auto store_chunk = [&](int buf) {
        #pragma unroll
        for (int i = 0; i < 4; i++) {
            int row = lrow + i * 32;
            float* ad = As[buf] + row * PAD + kq4;
            ad[0] = __uint_as_float(f2tf32(ra[i].x));
            ad[1] = __uint_as_float(f2tf32(ra[i].y));
            ad[2] = __uint_as_float(f2tf32(ra[i].z));
            ad[3] = __uint_as_float(f2tf32(ra[i].w));
            float* bd = Bs[buf] + row * PAD + kq4;
            bd[0] = rb[i].x; bd[1] = rb[i].y; bd[2] = rb[i].z; bd[3] = rb[i].w;
        }
    };

    load_chunk(0);
    store_chunk(0);
    __syncthreads();

    for (int c = 0; c < 16; c++) {
        int buf = c & 1;
        if (c < 15) load_chunk(c + 1);

        const float* abase = As[buf] + m_off * PAD;
        const float* bbase = Bs[buf] + n_off * PAD;
        #pragma unroll
        for (int ks = 0; ks < 4; ks++) {
            int k0 = ks * 8;
            uint32_t af[2][4], bf[8][2];
            #pragma unroll
            for (int i = 0; i < 2; i++) {
                const float* ap = abase + (i * 16 + g) * PAD + k0 + t;
                af[i][0] = __float_as_uint(ap[0]);
                af[i][1] = __float_as_uint(ap[8 * PAD]);
                af[i][2] = __float_as_uint(ap[4]);
                af[i][3] = __float_as_uint(ap[8 * PAD + 4]);
            }
            #pragma unroll
            for (int j = 0; j < 8; j++) {
                const float* bp = bbase + (j * 8 + g) * PAD + k0 + t;
                bf[j][0] = __float_as_uint(bp[0]);
                bf[j][1] = __float_as_uint(bp[4]);
            }
            #pragma unroll
            for (int i = 0; i < 2; i++)
                #pragma unroll
                for (int j = 0; j < 8; j++)
                    mma_tf32(acc[i][j], af[i], bf[j]);
        }

        if (c < 15) store_chunk(buf ^ 1);
        __syncthreads();
    }

    // ---- epilogue ----
    #pragma unroll
    for (int i = 0; i < 2; i++) {
        int r0 = m0 + m_off + i * 16 + g;
        int r1 = r0 + 8;
        float s0 = 0.f, s1 = 0.f;
        if (sparse != nullptr) {
            if (r0 < n) s0 = sparse[(size_t)r0 * NEXP + expert];
            if (r1 < n) s1 = sparse[(size_t)r1 * NEXP + expert];
        }
        #pragma unroll
        for (int j = 0; j < 8; j++) {
            int col = n0 + n_off + j * 8 + 2 * t;
            float2 bb = *(const float2*)(bias + col);
            float2 v0, v1;
            v0.x = acc[i][j][0] + bb.x; v0.y = acc[i][j][1] + bb.y;
            v1.x = acc[i][j][2] + bb.x; v1.y = acc[i][j][3] + bb.y;
            if (relu) {
                v0.x = fmaxf(v0.x, 0.f); v0.y = fmaxf(v0.y, 0.f);
                v1.x = fmaxf(v1.x, 0.f); v1.y = fmaxf(v1.y, 0.f);
            }
            if (sparse != nullptr) {
                if (r0 < n) {
                    float2* op = (float2*)(C + (size_t)r0 * HDIM + col);
                    float2 o = accum ? *op : make_float2(0.f, 0.f);
                    o.x = fmaf(s0, v0.x, o.x); o.y = fmaf(s0, v0.y, o.y);
                    *op = o;
                }
                if (r1 < n) {
                    float2* op = (float2*)(C + (size_t)r1 * HDIM + col);
                    float2 o = accum ? *op : make_float2(0.f, 0.f);
                    o.x = fmaf(s1, v1.x, o.x); o.y = fmaf(s1, v1.y, o.y);
                    *op = o;
                }
            } else {
                if (r0 < n) *(float2*)(C + (size_t)r0 * HDIM + col) = v0;
                if (r1 < n) *(float2*)(C + (size_t)r1 * HDIM + col) = v1;
            }
        }
    }
}

// ===========================================================================
// host launch
// ===========================================================================
extern "C" void kernel_launch(void* const* d_in, const int* in_sizes, int n_in,
                              void* d_out, int out_size) {
    const float* x      = (const float*)d_in[0];
    const int*   ei     = (const int*)  d_in[1];
    const int*   batch  = (const int*)  d_in[2];
    const float* W_enc  = (const float*)d_in[3];
    const float* b_enc  = (const float*)d_in[4];
    const float* Ws1    = (const float*)d_in[5];
    const float* bs1    = (const float*)d_in[6];
    const float* Ws2    = (const float*)d_in[7];
    const float* bs2    = (const float*)d_in[8];
    const float* Wt1    = (const float*)d_in[9];
    const float* bt1    = (const float*)d_in[10];
    const float* Wt2    = (const float*)d_in[11];
    const float* bt2    = (const float*)d_in[12];
    const float* W_self = (const float*)d_in[13];
    const float* W_nei  = (const float*)d_in[14];
    const float* b_exp  = (const float*)d_in[15];

    int N = in_sizes[0] / 10;
    int E = in_sizes[1] / 2;
    const int* src = ei;
    const int* dst = ei + E;
    float* out = (float*)d_out;

    float *h, *z1, *z2, *agg0, *aggT, *sparse, *strug, *wT;
    int *deg, *rowptr, *cursor, *colsrc, *ng, *eg;
    cudaGetSymbolAddress((void**)&h,      g_h);
    cudaGetSymbolAddress((void**)&z1,     g_z1);
    cudaGetSymbolAddress((void**)&z2,     g_z2);
    cudaGetSymbolAddress((void**)&agg0,   g_agg0);
    cudaGetSymbolAddress((void**)&aggT,   g_aggT);
    cudaGetSymbolAddress((void**)&sparse, g_sparse);
    cudaGetSymbolAddress((void**)&strug,  g_strug);
    cudaGetSymbolAddress((void**)&wT,     g_wT);
    cudaGetSymbolAddress((void**)&deg,    g_deg);
    cudaGetSymbolAddress((void**)&rowptr, g_rowptr);
    cudaGetSymbolAddress((void**)&cursor, g_cursor);
    cudaGetSymbolAddress((void**)&colsrc, g_colsrc);
    cudaGetSymbolAddress((void**)&ng,     g_ng);
    cudaGetSymbolAddress((void**)&eg,     g_eg);

    cudaFuncSetAttribute(k_tmma, cudaFuncAttributeMaxDynamicSharedMemorySize, TM_SMEM);

    cudaMemsetAsync(ng,  0, NGRAPH * sizeof(int), 0);
    cudaMemsetAsync(eg,  0, NGRAPH * sizeof(int), 0);
    cudaMemsetAsync(deg, 0, (size_t)N * sizeof(int), 0);

    // weight pack (tf32 transpose) — independent of everything else
    k_pack<<<24 * 256 * 512 / 256, 256>>>(W_self, W_nei, (uint32_t*)wT);

    // routers' structural branch + encoder
    k_hist_nodes<<<128, 256>>>(batch, ng, N);
    k_hist_edges<<<256, 256>>>(batch, src, eg, E);
    k_stru<<<NGRAPH, 256>>>(ng, eg, Wt1, bt1, Wt2, bt2, strug);
    k_encode<<<N, 256>>>(x, W_enc, b_enc, h, N);

    // semantic router (fp32 exact): hs = relu(h @ Ws1 + bs1) -> z1, then gates
    dim3 rgrid((N + BMR - 1) / BMR, HDIM / BNR);
    k_gemm<<<rgrid, 256>>>(h, Ws1, bs1, N, z1);
    k_logits<<<(N + 7) / 8, 256>>>(z1, Ws2, bs2, strug, batch, sparse, N);

    // CSR build
    k_deg<<<(E + 255) / 256, 256>>>(dst, deg, E);
    k_scan<<<1, 1024>>>(deg, rowptr, cursor, N);
    k_sortedges<<<(E + 255) / 256, 256>>>(src, dst, cursor, colsrc, E);

    // layer-0 aggregation shared by all experts (z == h)
    k_agg<<<N, 256>>>(h, agg0, rowptr, colsrc, N);

    dim3 mgrid((N + 127) / 128, 2);
    for (int e = 0; e < NEXP; e++) {
        const float* wt0 = wT + (size_t)(e * 3 + 0) * 256 * 512;
        const float* wt1 = wT + (size_t)(e * 3 + 1) * 256 * 512;
        const float* wt2 = wT + (size_t)(e * 3 + 2) * 256 * 512;
        const float* b_l0 = b_exp + (size_t)(e * 3 + 0) * HDIM;
        const float* b_l1 = b_exp + (size_t)(e * 3 + 1) * HDIM;
        const float* b_l2 = b_exp + (size_t)(e * 3 + 2) * HDIM;

        k_tmma<<<mgrid, 256, TM_SMEM>>>(h,  agg0, wt0, b_l0, N, 1, z1, nullptr, 0, 0);
        k_agg<<<N, 256>>>(z1, aggT, rowptr, colsrc, N);
        k_tmma<<<mgrid, 256, TM_SMEM>>>(z1, aggT, wt1, b_l1, N, 1, z2, nullptr, 0, 0);
        k_agg<<<N, 256>>>(z2, aggT, rowptr, colsrc, N);
        k_tmma<<<mgrid, 256, TM_SMEM>>>(z2, aggT, wt2, b_l2, N, 0, out, sparse, e, (e > 0) ? 1 : 0);
    }
}

// round 5
// speedup vs baseline: 2.0859x; 1.1241x over previous
#include <cuda_runtime.h>
#include <cstdint>
#include <cstddef>

// ---------------------------------------------------------------------------
// GraphMoEDualRouter — GB300 sm_103a.
// Round 4: 4-way stream parallelism across expert chains (GEMM/agg overlap),
// router path overlapped with CSR build. Kernels unchanged from round 3.
// ---------------------------------------------------------------------------

#define HDIM 256
#define NEXP 8
#define NGRAPH 64
#define MAXN 50176
#define MAXE 1600000
#define NSTREAM 4

typedef unsigned long long ull;

// ---- scratch (static device memory; allocation is forbidden) ----
__device__ float g_h   [MAXN * HDIM];
__device__ float g_hs  [MAXN * HDIM];          // router hidden
__device__ float g_agg0[MAXN * HDIM];
__device__ float g_zA  [NSTREAM][MAXN * HDIM];
__device__ float g_zB  [NSTREAM][MAXN * HDIM];
__device__ float g_agT [NSTREAM][MAXN * HDIM];
__device__ float g_part[NSTREAM][MAXN * HDIM];
__device__ float g_sparse[MAXN * NEXP];
__device__ int   g_deg   [MAXN];
__device__ int   g_rowptr[MAXN + 1];
__device__ int   g_cursor[MAXN];
__device__ int   g_colsrc[MAXE];
__device__ int   g_ng[NGRAPH];
__device__ int   g_eg[NGRAPH];
__device__ float g_strug[NGRAPH * NEXP];
// packed transposed weights, tf32-converted bit patterns: [24 mats][256 n][512 k]
__device__ float g_wT[24 * 256 * 512];

// ---- host-side streams/events (created once, pre-main; host resources only)
struct StreamPool {
    cudaStream_t s[NSTREAM + 1];   // [0..3] expert chains, [4] router path
    cudaEvent_t evA, evB, fork, join[NSTREAM];
    StreamPool() {
        for (int i = 0; i <= NSTREAM; i++)
            cudaStreamCreateWithFlags(&s[i], cudaStreamNonBlocking);
        cudaEventCreateWithFlags(&evA,  cudaEventDisableTiming);
        cudaEventCreateWithFlags(&evB,  cudaEventDisableTiming);
        cudaEventCreateWithFlags(&fork, cudaEventDisableTiming);
        for (int i = 0; i < NSTREAM; i++)
            cudaEventCreateWithFlags(&join[i], cudaEventDisableTiming);
    }
};
static StreamPool g_sp;

// ---- helpers ----
__device__ __forceinline__ uint32_t f2tf32(float f) {
    uint32_t u; asm("cvt.rna.tf32.f32 %0, %1;" : "=r"(u) : "f"(f)); return u;
}
__device__ __forceinline__ ull pack2(float lo, float hi) {
    ull r; asm("mov.b64 %0, {%1, %2};" : "=l"(r) : "f"(lo), "f"(hi)); return r;
}
__device__ __forceinline__ void fma2acc(ull& d, ull a, ull b) {
    asm("fma.rn.f32x2 %0, %1, %2, %0;" : "+l"(d) : "l"(a), "l"(b));
}
__device__ __forceinline__ void unpack2(ull v, float& lo, float& hi) {
    asm("mov.b64 {%0, %1}, %2;" : "=f"(lo), "=f"(hi) : "l"(v));
}
__device__ __forceinline__ void mma_tf32(float* d, const uint32_t* a, const uint32_t* b) {
    asm volatile(
        "mma.sync.aligned.m16n8k8.row.col.f32.tf32.tf32.f32 "
        "{%0,%1,%2,%3}, {%4,%5,%6,%7}, {%8,%9}, {%0,%1,%2,%3};"
        : "+f"(d[0]), "+f"(d[1]), "+f"(d[2]), "+f"(d[3])
        : "r"(a[0]), "r"(a[1]), "r"(a[2]), "r"(a[3]), "r"(b[0]), "r"(b[1]));
}

// ===========================================================================
// Small kernels
// ===========================================================================
__global__ void k_hist_nodes(const int* __restrict__ batch, int* __restrict__ ng, int n) {
    __shared__ int sh[NGRAPH];
    if (threadIdx.x < NGRAPH) sh[threadIdx.x] = 0;
    __syncthreads();
    for (int i = blockIdx.x * blockDim.x + threadIdx.x; i < n; i += gridDim.x * blockDim.x)
        atomicAdd(&sh[batch[i]], 1);
    __syncthreads();
    if (threadIdx.x < NGRAPH) atomicAdd(&ng[threadIdx.x], sh[threadIdx.x]);
}

__global__ void k_hist_edges(const int* __restrict__ batch, const int* __restrict__ src,
                             int* __restrict__ eg, int e) {
    __shared__ int sh[NGRAPH];
    if (threadIdx.x < NGRAPH) sh[threadIdx.x] = 0;
    __syncthreads();
    for (int i = blockIdx.x * blockDim.x + threadIdx.x; i < e; i += gridDim.x * blockDim.x)
        atomicAdd(&sh[batch[src[i]]], 1);
    __syncthreads();
    if (threadIdx.x < NGRAPH) atomicAdd(&eg[threadIdx.x], sh[threadIdx.x]);
}

__global__ void k_stru(const int* __restrict__ ng, const int* __restrict__ eg,
                       const float* __restrict__ Wt1, const float* __restrict__ bt1,
                       const float* __restrict__ Wt2, const float* __restrict__ bt2,
                       float* __restrict__ strug) {
    int g = blockIdx.x;
    float fn = log1pf((float)ng[g]);
    float fe = log1pf((float)eg[g]);
    __shared__ float hid[HDIM];
    int j = threadIdx.x;
    hid[j] = fmaxf(fmaf(fn, Wt1[j], fmaf(fe, Wt1[HDIM + j], bt1[j])), 0.0f);
    __syncthreads();
    int w = threadIdx.x >> 5, lane = threadIdx.x & 31;
    if (w < NEXP) {
        float acc = 0.f;
        for (int k = lane; k < HDIM; k += 32) acc = fmaf(hid[k], Wt2[k * NEXP + w], acc);
        #pragma unroll
        for (int off = 16; off; off >>= 1) acc += __shfl_down_sync(0xffffffffu, acc, off);
        if (lane == 0) strug[g * NEXP + w] = acc + bt2[w];
    }
}

__global__ void k_encode(const float* __restrict__ x, const float* __restrict__ W,
                         const float* __restrict__ b, float* __restrict__ h, int n) {
    int node = blockIdx.x;
    if (node >= n) return;
    __shared__ float xs[6];
    if (threadIdx.x < 6) xs[threadIdx.x] = x[node * 10 + 4 + threadIdx.x];
    __syncthreads();
    int j = threadIdx.x;
    float acc = b[j];
    #pragma unroll
    for (int k = 0; k < 6; k++) acc = fmaf(xs[k], W[k * HDIM + j], acc);
    h[(size_t)node * HDIM + j] = fmaxf(acc, 0.0f);
}

// ===========================================================================
// FFMA fp32 GEMM — router hidden layer only (top-2 selection needs exactness)
// ===========================================================================
#define BMR 128
#define BNR 64
#define BKR 16

__global__ __launch_bounds__(256) void k_gemm(
    const float* __restrict__ A, const float* __restrict__ W1,
    const float* __restrict__ bias, int n, float* __restrict__ C)
{
    __shared__ __align__(16) float As[BKR][BMR + 2];
    __shared__ __align__(16) float Ws[BKR][BNR];

    int m0 = blockIdx.x * BMR;
    int n0 = blockIdx.y * BNR;
    int tid = threadIdx.x;
    int tm = tid >> 4;
    int tn = tid & 15;

    ull acc2[4][4];
    #pragma unroll
    for (int i = 0; i < 4; i++)
        #pragma unroll
        for (int j = 0; j < 4; j++) acc2[i][j] = 0ull;

    for (int kc = 0; kc < HDIM; kc += BKR) {
        #pragma unroll
        for (int u = 0; u < 2; u++) {
            int idx = tid + u * 256;
            int row = idx >> 2;
            int kq  = idx & 3;
            float4 v = make_float4(0.f, 0.f, 0.f, 0.f);
            int gr = m0 + row;
            if (gr < n) v = *(const float4*)(A + (size_t)gr * HDIM + kc + kq * 4);
            As[kq * 4 + 0][row] = v.x;
            As[kq * 4 + 1][row] = v.y;
            As[kq * 4 + 2][row] = v.z;
            As[kq * 4 + 3][row] = v.w;
        }
        {
            int kk = tid >> 4, nq = tid & 15;
            float4 w = *(const float4*)(W1 + (size_t)(kc + kk) * HDIM + n0 + nq * 4);
            *(float4*)&Ws[kk][nq * 4] = w;
        }
        __syncthreads();
        #pragma unroll
        for (int kk = 0; kk < BKR; kk++) {
            ull a2[4];
            #pragma unroll
            for (int i2 = 0; i2 < 4; i2++)
                a2[i2] = *(const ull*)&As[kk][tm * 8 + i2 * 2];
            #pragma unroll
            for (int j = 0; j < 4; j++) {
                float bb = Ws[kk][tn * 4 + j];
                ull b2 = pack2(bb, bb);
                #pragma unroll
                for (int i2 = 0; i2 < 4; i2++) fma2acc(acc2[i2][j], a2[i2], b2);
            }
        }
        __syncthreads();
    }

    float4 bb4 = *(const float4*)&bias[n0 + tn * 4];
    #pragma unroll
    for (int i2 = 0; i2 < 4; i2++) {
        float4 vlo, vhi;
        unpack2(acc2[i2][0], vlo.x, vhi.x);
        unpack2(acc2[i2][1], vlo.y, vhi.y);
        unpack2(acc2[i2][2], vlo.z, vhi.z);
        unpack2(acc2[i2][3], vlo.w, vhi.w);
        #pragma unroll
        for (int rr = 0; rr < 2; rr++) {
            int row = m0 + tm * 8 + i2 * 2 + rr;
            if (row >= n) continue;
            float4 v = rr ? vhi : vlo;
            v.x = fmaxf(v.x + bb4.x, 0.f); v.y = fmaxf(v.y + bb4.y, 0.f);
            v.z = fmaxf(v.z + bb4.z, 0.f); v.w = fmaxf(v.w + bb4.w, 0.f);
            *(float4*)(C + (size_t)row * HDIM + n0 + tn * 4) = v;
        }
    }
}

// ===========================================================================
// Router logits + top-2 sparse gates
// ===========================================================================
__global__ void k_logits(const float* __restrict__ hs, const float* __restrict__ Ws2,
                         const float* __restrict__ bs2, const float* __restrict__ strug,
                         const int* __restrict__ batch, float* __restrict__ sparse, int n) {
    int warp = (blockIdx.x * blockDim.x + threadIdx.x) >> 5;
    int lane = threadIdx.x & 31;
    if (warp >= n) return;
    const float* row = hs + (size_t)warp * HDIM;
    float acc[NEXP];
    #pragma unroll
    for (int o = 0; o < NEXP; o++) acc[o] = 0.f;
    for (int k = lane; k < HDIM; k += 32) {
        float v = row[k];
        const float* w2 = Ws2 + k * NEXP;
        #pragma unroll
        for (int o = 0; o < NEXP; o++) acc[o] = fmaf(v, w2[o], acc[o]);
    }
    #pragma unroll
    for (int o = 0; o < NEXP; o++)
        #pragma unroll
        for (int off = 16; off; off >>= 1) acc[o] += __shfl_down_sync(0xffffffffu, acc[o], off);
    if (lane == 0) {
        int g = batch[warp];
        float lg[NEXP];
        #pragma unroll
        for (int o = 0; o < NEXP; o++)
            lg[o] = 0.5f * (acc[o] + bs2[o]) + 0.5f * strug[g * NEXP + o];
        float m1 = -3.4e38f; int i1 = 0;
        #pragma unroll
        for (int o = 0; o < NEXP; o++) if (lg[o] > m1) { m1 = lg[o]; i1 = o; }
        float m2 = -3.4e38f; int i2 = 0;
        #pragma unroll
        for (int o = 0; o < NEXP; o++) if (o != i1 && lg[o] > m2) { m2 = lg[o]; i2 = o; }
        float e2 = __expf(m2 - m1);
        float inv = 1.0f / (1.0f + e2);
        float* srow = sparse + (size_t)warp * NEXP;
        #pragma unroll
        for (int o = 0; o < NEXP; o++) srow[o] = 0.f;
        srow[i1] = inv;
        srow[i2] = e2 * inv;
    }
}

// ===========================================================================
// CSR build (counting sort by dst)
// ===========================================================================
__global__ void k_deg(const int* __restrict__ dst, int* __restrict__ deg, int e) {
    int i = blockIdx.x * blockDim.x + threadIdx.x;
    if (i < e) atomicAdd(&deg[dst[i]], 1);
}

__global__ void k_scan(const int* __restrict__ deg, int* __restrict__ rowptr,
                       int* __restrict__ cursor, int n) {
    __shared__ int sh[1024];
    __shared__ int carry;
    if (threadIdx.x == 0) { carry = 0; rowptr[0] = 0; }
    __syncthreads();
    for (int base = 0; base < n; base += 1024) {
        int i = base + (int)threadIdx.x;
        int v = (i < n) ? deg[i] : 0;
        sh[threadIdx.x] = v;
        __syncthreads();
        #pragma unroll
        for (int off = 1; off < 1024; off <<= 1) {
            int t = (threadIdx.x >= (unsigned)off) ? sh[threadIdx.x - off] : 0;
            __syncthreads();
            sh[threadIdx.x] += t;
            __syncthreads();
        }
        int inc = sh[threadIdx.x] + carry;
        if (i < n) { rowptr[i + 1] = inc; cursor[i] = inc - v; }
        __syncthreads();
        if (threadIdx.x == 1023) carry = inc;
        __syncthreads();
    }
}

__global__ void k_sortedges(const int* __restrict__ src, const int* __restrict__ dst,
                            int* __restrict__ cursor, int* __restrict__ colsrc, int e) {
    int i = blockIdx.x * blockDim.x + threadIdx.x;
    if (i < e) {
        int d = dst[i];
        int p = atomicAdd(&cursor[d], 1);
        colsrc[p] = src[i];
    }
}

// ===========================================================================
// CSR gather aggregation (no atomics)
// ===========================================================================
__global__ __launch_bounds__(256) void k_agg(const float* __restrict__ z,
                                             float* __restrict__ agg,
                                             const int* __restrict__ rowptr,
                                             const int* __restrict__ colsrc, int n) {
    int node = blockIdx.x;
    if (node >= n) return;
    int c = threadIdx.x;
    int s0 = rowptr[node], s1 = rowptr[node + 1];
    float a0 = 0.f, a1 = 0.f, a2 = 0.f, a3 = 0.f;
    int i = s0;
    for (; i + 3 < s1; i += 4) {
        int sA = colsrc[i], sB = colsrc[i + 1], sC = colsrc[i + 2], sD = colsrc[i + 3];
        a0 += z[(size_t)sA * HDIM + c];
        a1 += z[(size_t)sB * HDIM + c];
        a2 += z[(size_t)sC * HDIM + c];
        a3 += z[(size_t)sD * HDIM + c];
    }
    for (; i < s1; i++) a0 += z[(size_t)colsrc[i] * HDIM + c];
    agg[(size_t)node * HDIM + c] = (a0 + a1) + (a2 + a3);
}

// ===========================================================================
// Weight pack: wT[mat][n][k] = tf32( k<256 ? Wself[mat][k][n] : Wnei[mat][k-256][n] )
// ===========================================================================
__global__ void k_pack(const float* __restrict__ Wself, const float* __restrict__ Wnei,
                       uint32_t* __restrict__ wT) {
    int idx = blockIdx.x * 256 + threadIdx.x;
    int k = idx & 511;
    int rem = idx >> 9;
    int nrow = rem & 255;
    int mat = rem >> 8;
    const float* srcp = (k < 256) ? Wself : Wnei;
    int kk = k & 255;
    float v = srcp[((size_t)mat * 256 + kk) * 256 + nrow];
    wT[idx] = f2tf32(v);
}

// ===========================================================================
// Final combine: out = p0 + p1 + p2 + p3 (float4 vectorized)
// ===========================================================================
__global__ void k_combine(const float* __restrict__ p0, const float* __restrict__ p1,
                          const float* __restrict__ p2, const float* __restrict__ p3,
                          float* __restrict__ out, int n4) {
    int i = blockIdx.x * blockDim.x + threadIdx.x;
    if (i >= n4) return;
    float4 a = ((const float4*)p0)[i];
    float4 b = ((const float4*)p1)[i];
    float4 c = ((const float4*)p2)[i];
    float4 d = ((const float4*)p3)[i];
    float4 o;
    o.x = (a.x + b.x) + (c.x + d.x);
    o.y = (a.y + b.y) + (c.y + d.y);
    o.z = (a.z + b.z) + (c.z + d.z);
    o.w = (a.w + b.w) + (c.w + d.w);
    ((float4*)out)[i] = o;
}

// ===========================================================================
// mma.sync tf32 dual GEMM (unchanged from round 3)
// ===========================================================================
#define PAD 36
#define ABUF (128 * PAD)
#define TM_SMEM (4 * ABUF * 4)

__global__ __launch_bounds__(256, 1) void k_tmma(
    const float* __restrict__ Az, const float* __restrict__ Ag,
    const float* __restrict__ WT, const float* __restrict__ bias,
    int n, int relu, float* __restrict__ C,
    const float* __restrict__ sparse, int expert, int accum)
{
    extern __shared__ float smf[];
    float* As[2] = { smf,            smf + ABUF };
    float* Bs[2] = { smf + 2 * ABUF, smf + 3 * ABUF };

    int tid = threadIdx.x;
    int warp = tid >> 5, lane = tid & 31;
    int m0 = blockIdx.x * 128;
    int n0 = blockIdx.y * 128;
    int m_off = (warp >> 1) * 32;
    int n_off = (warp & 1) * 64;
    int g = lane >> 2, t = lane & 3;

    int lrow = tid >> 3;
    int kq4  = (tid & 7) * 4;

    float acc[2][8][4];
    #pragma unroll
    for (int i = 0; i < 2; i++)
        #pragma unroll
        for (int j = 0; j < 8; j++)
            #pragma unroll
            for (int r = 0; r < 4; r++) acc[i][j][r] = 0.f;

    float4 ra[4], rb[4];

    auto load_chunk = [&](int c) {
        const float* Asrc = (c < 8) ? Az : Ag;
        int kb = (c & 7) * 32;
        #pragma unroll
        for (int i = 0; i < 4; i++) {
            int row = lrow + i * 32;
            int gr = m0 + row;
            ra[i] = (gr < n) ? *(const float4*)(Asrc + (size_t)gr * HDIM + kb + kq4)
                             : make_float4(0.f, 0.f, 0.f, 0.f);
            rb[i] = *(const float4*)(WT + (size_t)(n0 + row) * 512 + c * 32 + kq4);
        }
    };
    auto store_chunk = [&](int buf) {
        #pragma unroll
        for (int i = 0; i < 4; i++) {
            int row = lrow + i * 32;
            float* ad = As[buf] + row * PAD + kq4;
            ad[0] = __uint_as_float(f2tf32(ra[i].x));
            ad[1] = __uint_as_float(f2tf32(ra[i].y));
            ad[2] = __uint_as_float(f2tf32(ra[i].z));
            ad[3] = __uint_as_float(f2tf32(ra[i].w));
            float* bd = Bs[buf] + row * PAD + kq4;
            bd[0] = rb[i].x; bd[1] = rb[i].y; bd[2] = rb[i].z; bd[3] = rb[i].w;
        }
    };

    load_chunk(0);
    store_chunk(0);
    __syncthreads();

    for (int c = 0; c < 16; c++) {
        int buf = c & 1;
        if (c < 15) load_chunk(c + 1);

        const float* abase = As[buf] + m_off * PAD;
        const float* bbase = Bs[buf] + n_off * PAD;
        #pragma unroll
        for (int ks = 0; ks < 4; ks++) {
            int k0 = ks * 8;
            uint32_t af[2][4], bf[8][2];
            #pragma unroll
            for (int i = 0; i < 2; i++) {
                const float* ap = abase + (i * 16 + g) * PAD + k0 + t;
                af[i][0] = __float_as_uint(ap[0]);
                af[i][1] = __float_as_uint(ap[8 * PAD]);
                af[i][2] = __float_as_uint(ap[4]);
                af[i][3] = __float_as_uint(ap[8 * PAD + 4]);
            }
            #pragma unroll
            for (int j = 0; j < 8; j++) {
                const float* bp = bbase + (j * 8 + g) * PAD + k0 + t;
                bf[j][0] = __float_as_uint(bp[0]);
                bf[j][1] = __float_as_uint(bp[4]);
            }
            #pragma unroll
            for (int i = 0; i < 2; i++)
                #pragma unroll
                for (int j = 0; j < 8; j++)
                    mma_tf32(acc[i][j], af[i], bf[j]);
        }

        if (c < 15) store_chunk(buf ^ 1);
        __syncthreads();
    }

    #pragma unroll
    for (int i = 0; i < 2; i++) {
        int r0 = m0 + m_off + i * 16 + g;
        int r1 = r0 + 8;
        float s0 = 0.f, s1 = 0.f;
        if (sparse != nullptr) {
            if (r0 < n) s0 = sparse[(size_t)r0 * NEXP + expert];
            if (r1 < n) s1 = sparse[(size_t)r1 * NEXP + expert];
        }
        #pragma unroll
        for (int j = 0; j < 8; j++) {
            int col = n0 + n_off + j * 8 + 2 * t;
            float2 bb = *(const float2*)(bias + col);
            float2 v0, v1;
            v0.x = acc[i][j][0] + bb.x; v0.y = acc[i][j][1] + bb.y;
            v1.x = acc[i][j][2] + bb.x; v1.y = acc[i][j][3] + bb.y;
            if (relu) {
                v0.x = fmaxf(v0.x, 0.f); v0.y = fmaxf(v0.y, 0.f);
                v1.x = fmaxf(v1.x, 0.f); v1.y = fmaxf(v1.y, 0.f);
            }
            if (sparse != nullptr) {
                if (r0 < n) {
                    float2* op = (float2*)(C + (size_t)r0 * HDIM + col);
                    float2 o = accum ? *op : make_float2(0.f, 0.f);
                    o.x = fmaf(s0, v0.x, o.x); o.y = fmaf(s0, v0.y, o.y);
                    *op = o;
                }
                if (r1 < n) {
                    float2* op = (float2*)(C + (size_t)r1 * HDIM + col);
                    float2 o = accum ? *op : make_float2(0.f, 0.f);
                    o.x = fmaf(s1, v1.x, o.x); o.y = fmaf(s1, v1.y, o.y);
                    *op = o;
                }
            } else {
                if (r0 < n) *(float2*)(C + (size_t)r0 * HDIM + col) = v0;
                if (r1 < n) *(float2*)(C + (size_t)r1 * HDIM + col) = v1;
            }
        }
    }
}

// ===========================================================================
// host launch
// ===========================================================================
extern "C" void kernel_launch(void* const* d_in, const int* in_sizes, int n_in,
                              void* d_out, int out_size) {
    const float* x      = (const float*)d_in[0];
    const int*   ei     = (const int*)  d_in[1];
    const int*   batch  = (const int*)  d_in[2];
    const float* W_enc  = (const float*)d_in[3];
    const float* b_enc  = (const float*)d_in[4];
    const float* Ws1    = (const float*)d_in[5];
    const float* bs1    = (const float*)d_in[6];
    const float* Ws2    = (const float*)d_in[7];
    const float* bs2    = (const float*)d_in[8];
    const float* Wt1    = (const float*)d_in[9];
    const float* bt1    = (const float*)d_in[10];
    const float* Wt2    = (const float*)d_in[11];
    const float* bt2    = (const float*)d_in[12];
    const float* W_self = (const float*)d_in[13];
    const float* W_nei  = (const float*)d_in[14];
    const float* b_exp  = (const float*)d_in[15];

    int N = in_sizes[0] / 10;
    int E = in_sizes[1] / 2;
    const int* src = ei;
    const int* dst = ei + E;
    float* out = (float*)d_out;

    float *h, *hs, *agg0, *zA, *zB, *agT, *part, *sparse, *strug, *wT;
    int *deg, *rowptr, *cursor, *colsrc, *ng, *eg;
    cudaGetSymbolAddress((void**)&h,      g_h);
    cudaGetSymbolAddress((void**)&hs,     g_hs);
    cudaGetSymbolAddress((void**)&agg0,   g_agg0);
    cudaGetSymbolAddress((void**)&zA,     g_zA);
    cudaGetSymbolAddress((void**)&zB,     g_zB);
    cudaGetSymbolAddress((void**)&agT,    g_agT);
    cudaGetSymbolAddress((void**)&part,   g_part);
    cudaGetSymbolAddress((void**)&sparse, g_sparse);
    cudaGetSymbolAddress((void**)&strug,  g_strug);
    cudaGetSymbolAddress((void**)&wT,     g_wT);
    cudaGetSymbolAddress((void**)&deg,    g_deg);
    cudaGetSymbolAddress((void**)&rowptr, g_rowptr);
    cudaGetSymbolAddress((void**)&cursor, g_cursor);
    cudaGetSymbolAddress((void**)&colsrc, g_colsrc);
    cudaGetSymbolAddress((void**)&ng,     g_ng);
    cudaGetSymbolAddress((void**)&eg,     g_eg);

    cudaFuncSetAttribute(k_tmma, cudaFuncAttributeMaxDynamicSharedMemorySize, TM_SMEM);

    const size_t ZSZ = (size_t)MAXN * HDIM;

    // ---- prologue on capture stream (0): inputs for everything downstream
    cudaMemsetAsync(ng,  0, NGRAPH * sizeof(int), 0);
    cudaMemsetAsync(eg,  0, NGRAPH * sizeof(int), 0);
    cudaMemsetAsync(deg, 0, (size_t)N * sizeof(int), 0);

    k_pack<<<24 * 256 * 512 / 256, 256>>>(W_self, W_nei, (uint32_t*)wT);
    k_hist_nodes<<<128, 256>>>(batch, ng, N);
    k_hist_edges<<<256, 256>>>(batch, src, eg, E);
    k_stru<<<NGRAPH, 256>>>(ng, eg, Wt1, bt1, Wt2, bt2, strug);
    k_encode<<<N, 256>>>(x, W_enc, b_enc, h, N);

    // fork router path onto s[4]: hs = relu(h @ Ws1 + bs1); sparse gates
    cudaEventRecord(g_sp.evA, 0);
    cudaStreamWaitEvent(g_sp.s[NSTREAM], g_sp.evA, 0);
    {
        dim3 rgrid((N + BMR - 1) / BMR, HDIM / BNR);
        k_gemm<<<rgrid, 256, 0, g_sp.s[NSTREAM]>>>(h, Ws1, bs1, N, hs);
        k_logits<<<(N + 7) / 8, 256, 0, g_sp.s[NSTREAM]>>>(hs, Ws2, bs2, strug, batch, sparse, N);
        cudaEventRecord(g_sp.evB, g_sp.s[NSTREAM]);
    }

    // meanwhile on stream 0: CSR build + shared layer-0 aggregation
    k_deg<<<(E + 255) / 256, 256>>>(dst, deg, E);
    k_scan<<<1, 1024>>>(deg, rowptr, cursor, N);
    k_sortedges<<<(E + 255) / 256, 256>>>(src, dst, cursor, colsrc, E);
    k_agg<<<N, 256>>>(h, agg0, rowptr, colsrc, N);

    cudaEventRecord(g_sp.fork, 0);

    // ---- 4 parallel expert chains, 2 experts each
    dim3 mgrid((N + 127) / 128, 2);
    for (int i = 0; i < NSTREAM; i++) {
        cudaStream_t st = g_sp.s[i];
        cudaStreamWaitEvent(st, g_sp.fork, 0);
        cudaStreamWaitEvent(st, g_sp.evB, 0);
        float* zAi = zA + (size_t)i * ZSZ;
        float* zBi = zB + (size_t)i * ZSZ;
        float* agi = agT + (size_t)i * ZSZ;
        float* pti = part + (size_t)i * ZSZ;
        for (int j = 0; j < 2; j++) {
            int e = i * 2 + j;
            const float* wt0 = wT + (size_t)(e * 3 + 0) * 256 * 512;
            const float* wt1 = wT + (size_t)(e * 3 + 1) * 256 * 512;
            const float* wt2 = wT + (size_t)(e * 3 + 2) * 256 * 512;
            const float* b_l0 = b_exp + (size_t)(e * 3 + 0) * HDIM;
            const float* b_l1 = b_exp + (size_t)(e * 3 + 1) * HDIM;
            const float* b_l2 = b_exp + (size_t)(e * 3 + 2) * HDIM;

            k_tmma<<<mgrid, 256, TM_SMEM, st>>>(h,  agg0, wt0, b_l0, N, 1, zAi, nullptr, 0, 0);
            k_agg<<<N, 256, 0, st>>>(zAi, agi, rowptr, colsrc, N);
            k_tmma<<<mgrid, 256, TM_SMEM, st>>>(zAi, agi, wt1, b_l1, N, 1, zBi, nullptr, 0, 0);
            k_agg<<<N, 256, 0, st>>>(zBi, agi, rowptr, colsrc, N);
            k_tmma<<<mgrid, 256, TM_SMEM, st>>>(zBi, agi, wt2, b_l2, N, 0, pti, sparse, e, (j > 0) ? 1 : 0);
        }
        cudaEventRecord(g_sp.join[i], st);
    }

    // ---- join + combine
    for (int i = 0; i < NSTREAM; i++) cudaStreamWaitEvent(0, g_sp.join[i], 0);
    int n4 = N * HDIM / 4;
    k_combine<<<(n4 + 255) / 256, 256>>>(part, part + ZSZ, part + 2 * ZSZ, part + 3 * ZSZ, out, n4);
}

// round 6
// speedup vs baseline: 3.0737x; 1.4736x over previous
#include <cuda_runtime.h>
#include <cstdint>
#include <cstddef>

// ---------------------------------------------------------------------------
// GraphMoEDualRouter — GB300 sm_103a.
// Round 5: k_tmma v2 — cp.async global->smem (no staging regs), 2 CTAs/SM,
// in-fragment tf32 conversion (math bit-identical to round 3/4).
// Stream-parallel expert chains retained from round 4.
// ---------------------------------------------------------------------------

#define HDIM 256
#define NEXP 8
#define NGRAPH 64
#define MAXN 50176
#define MAXE 1600000
#define NSTREAM 4

typedef unsigned long long ull;

// ---- scratch (static device memory; allocation is forbidden) ----
__device__ float g_h   [MAXN * HDIM];
__device__ float g_hs  [MAXN * HDIM];          // router hidden
__device__ float g_agg0[MAXN * HDIM];
__device__ float g_zA  [NSTREAM][MAXN * HDIM];
__device__ float g_zB  [NSTREAM][MAXN * HDIM];
__device__ float g_agT [NSTREAM][MAXN * HDIM];
__device__ float g_part[NSTREAM][MAXN * HDIM];
__device__ float g_sparse[MAXN * NEXP];
__device__ int   g_deg   [MAXN];
__device__ int   g_rowptr[MAXN + 1];
__device__ int   g_cursor[MAXN];
__device__ int   g_colsrc[MAXE];
__device__ int   g_ng[NGRAPH];
__device__ int   g_eg[NGRAPH];
__device__ float g_strug[NGRAPH * NEXP];
// packed transposed weights, tf32-converted bit patterns: [24 mats][256 n][512 k]
__device__ float g_wT[24 * 256 * 512];

// ---- host-side streams/events (created once, pre-main; host resources only)
struct StreamPool {
    cudaStream_t s[NSTREAM + 1];
    cudaEvent_t evA, evB, fork, join[NSTREAM];
    StreamPool() {
        for (int i = 0; i <= NSTREAM; i++)
            cudaStreamCreateWithFlags(&s[i], cudaStreamNonBlocking);
        cudaEventCreateWithFlags(&evA,  cudaEventDisableTiming);
        cudaEventCreateWithFlags(&evB,  cudaEventDisableTiming);
        cudaEventCreateWithFlags(&fork, cudaEventDisableTiming);
        for (int i = 0; i < NSTREAM; i++)
            cudaEventCreateWithFlags(&join[i], cudaEventDisableTiming);
    }
};
static StreamPool g_sp;

// ---- helpers ----
__device__ __forceinline__ uint32_t f2tf32(float f) {
    uint32_t u; asm("cvt.rna.tf32.f32 %0, %1;" : "=r"(u) : "f"(f)); return u;
}
__device__ __forceinline__ ull pack2(float lo, float hi) {
    ull r; asm("mov.b64 %0, {%1, %2};" : "=l"(r) : "f"(lo), "f"(hi)); return r;
}
__device__ __forceinline__ void fma2acc(ull& d, ull a, ull b) {
    asm("fma.rn.f32x2 %0, %1, %2, %0;" : "+l"(d) : "l"(a), "l"(b));
}
__device__ __forceinline__ void unpack2(ull v, float& lo, float& hi) {
    asm("mov.b64 {%0, %1}, %2;" : "=f"(lo), "=f"(hi) : "l"(v));
}
__device__ __forceinline__ void mma_tf32(float* d, const uint32_t* a, const uint32_t* b) {
    asm volatile(
        "mma.sync.aligned.m16n8k8.row.col.f32.tf32.tf32.f32 "
        "{%0,%1,%2,%3}, {%4,%5,%6,%7}, {%8,%9}, {%0,%1,%2,%3};"
        : "+f"(d[0]), "+f"(d[1]), "+f"(d[2]), "+f"(d[3])
        : "r"(a[0]), "r"(a[1]), "r"(a[2]), "r"(a[3]), "r"(b[0]), "r"(b[1]));
}
__device__ __forceinline__ uint32_t smem_u32(const void* p) {
    uint32_t a;
    asm("{ .reg .u64 t; cvta.to.shared.u64 t, %1; cvt.u32.u64 %0, t; }" : "=r"(a) : "l"(p));
    return a;
}
__device__ __forceinline__ void cp16(uint32_t dst, const void* src, int sz) {
    asm volatile("cp.async.cg.shared.global [%0], [%1], 16, %2;"
                 :: "r"(dst), "l"(src), "r"(sz) : "memory");
}
__device__ __forceinline__ void cp16u(uint32_t dst, const void* src) {
    asm volatile("cp.async.cg.shared.global [%0], [%1], 16;"
                 :: "r"(dst), "l"(src) : "memory");
}

// ===========================================================================
// Small kernels
// ===========================================================================
__global__ void k_hist_nodes(const int* __restrict__ batch, int* __restrict__ ng, int n) {
    __shared__ int sh[NGRAPH];
    if (threadIdx.x < NGRAPH) sh[threadIdx.x] = 0;
    __syncthreads();
    for (int i = blockIdx.x * blockDim.x + threadIdx.x; i < n; i += gridDim.x * blockDim.x)
        atomicAdd(&sh[batch[i]], 1);
    __syncthreads();
    if (threadIdx.x < NGRAPH) atomicAdd(&ng[threadIdx.x], sh[threadIdx.x]);
}

__global__ void k_hist_edges(const int* __restrict__ batch, const int* __restrict__ src,
                             int* __restrict__ eg, int e) {
    __shared__ int sh[NGRAPH];
    if (threadIdx.x < NGRAPH) sh[threadIdx.x] = 0;
    __syncthreads();
    for (int i = blockIdx.x * blockDim.x + threadIdx.x; i < e; i += gridDim.x * blockDim.x)
        atomicAdd(&sh[batch[src[i]]], 1);
    __syncthreads();
    if (threadIdx.x < NGRAPH) atomicAdd(&eg[threadIdx.x], sh[threadIdx.x]);
}

__global__ void k_stru(const int* __restrict__ ng, const int* __restrict__ eg,
                       const float* __restrict__ Wt1, const float* __restrict__ bt1,
                       const float* __restrict__ Wt2, const float* __restrict__ bt2,
                       float* __restrict__ strug) {
    int g = blockIdx.x;
    float fn = log1pf((float)ng[g]);
    float fe = log1pf((float)eg[g]);
    __shared__ float hid[HDIM];
    int j = threadIdx.x;
    hid[j] = fmaxf(fmaf(fn, Wt1[j], fmaf(fe, Wt1[HDIM + j], bt1[j])), 0.0f);
    __syncthreads();
    int w = threadIdx.x >> 5, lane = threadIdx.x & 31;
    if (w < NEXP) {
        float acc = 0.f;
        for (int k = lane; k < HDIM; k += 32) acc = fmaf(hid[k], Wt2[k * NEXP + w], acc);
        #pragma unroll
        for (int off = 16; off; off >>= 1) acc += __shfl_down_sync(0xffffffffu, acc, off);
        if (lane == 0) strug[g * NEXP + w] = acc + bt2[w];
    }
}

__global__ void k_encode(const float* __restrict__ x, const float* __restrict__ W,
                         const float* __restrict__ b, float* __restrict__ h, int n) {
    int node = blockIdx.x;
    if (node >= n) return;
    __shared__ float xs[6];
    if (threadIdx.x < 6) xs[threadIdx.x] = x[node * 10 + 4 + threadIdx.x];
    __syncthreads();
    int j = threadIdx.x;
    float acc = b[j];
    #pragma unroll
    for (int k = 0; k < 6; k++) acc = fmaf(xs[k], W[k * HDIM + j], acc);
    h[(size_t)node * HDIM + j] = fmaxf(acc, 0.0f);
}

// ===========================================================================
// FFMA fp32 GEMM — router hidden layer only (top-2 selection needs exactness)
// ===========================================================================
#define BMR 128
#define BNR 64
#define BKR 16

__global__ __launch_bounds__(256) void k_gemm(
    const float* __restrict__ A, const float* __restrict__ W1,
    const float* __restrict__ bias, int n, float* __restrict__ C)
{
    __shared__ __align__(16) float As[BKR][BMR + 2];
    __shared__ __align__(16) float Ws[BKR][BNR];

    int m0 = blockIdx.x * BMR;
    int n0 = blockIdx.y * BNR;
    int tid = threadIdx.x;
    int tm = tid >> 4;
    int tn = tid & 15;

    ull acc2[4][4];
    #pragma unroll
    for (int i = 0; i < 4; i++)
        #pragma unroll
        for (int j = 0; j < 4; j++) acc2[i][j] = 0ull;

    for (int kc = 0; kc < HDIM; kc += BKR) {
        #pragma unroll
        for (int u = 0; u < 2; u++) {
            int idx = tid + u * 256;
            int row = idx >> 2;
            int kq  = idx & 3;
            float4 v = make_float4(0.f, 0.f, 0.f, 0.f);
            int gr = m0 + row;
            if (gr < n) v = *(const float4*)(A + (size_t)gr * HDIM + kc + kq * 4);
            As[kq * 4 + 0][row] = v.x;
            As[kq * 4 + 1][row] = v.y;
            As[kq * 4 + 2][row] = v.z;
            As[kq * 4 + 3][row] = v.w;
        }
        {
            int kk = tid >> 4, nq = tid & 15;
            float4 w = *(const float4*)(W1 + (size_t)(kc + kk) * HDIM + n0 + nq * 4);
            *(float4*)&Ws[kk][nq * 4] = w;
        }
        __syncthreads();
        #pragma unroll
        for (int kk = 0; kk < BKR; kk++) {
            ull a2[4];
            #pragma unroll
            for (int i2 = 0; i2 < 4; i2++)
                a2[i2] = *(const ull*)&As[kk][tm * 8 + i2 * 2];
            #pragma unroll
            for (int j = 0; j < 4; j++) {
                float bb = Ws[kk][tn * 4 + j];
                ull b2 = pack2(bb, bb);
                #pragma unroll
                for (int i2 = 0; i2 < 4; i2++) fma2acc(acc2[i2][j], a2[i2], b2);
            }
        }
        __syncthreads();
    }

    float4 bb4 = *(const float4*)&bias[n0 + tn * 4];
    #pragma unroll
    for (int i2 = 0; i2 < 4; i2++) {
        float4 vlo, vhi;
        unpack2(acc2[i2][0], vlo.x, vhi.x);
        unpack2(acc2[i2][1], vlo.y, vhi.y);
        unpack2(acc2[i2][2], vlo.z, vhi.z);
        unpack2(acc2[i2][3], vlo.w, vhi.w);
        #pragma unroll
        for (int rr = 0; rr < 2; rr++) {
            int row = m0 + tm * 8 + i2 * 2 + rr;
            if (row >= n) continue;
            float4 v = rr ? vhi : vlo;
            v.x = fmaxf(v.x + bb4.x, 0.f); v.y = fmaxf(v.y + bb4.y, 0.f);
            v.z = fmaxf(v.z + bb4.z, 0.f); v.w = fmaxf(v.w + bb4.w, 0.f);
            *(float4*)(C + (size_t)row * HDIM + n0 + tn * 4) = v;
        }
    }
}

// ===========================================================================
// Router logits + top-2 sparse gates
// ===========================================================================
__global__ void k_logits(const float* __restrict__ hs, const float* __restrict__ Ws2,
                         const float* __restrict__ bs2, const float* __restrict__ strug,
                         const int* __restrict__ batch, float* __restrict__ sparse, int n) {
    int warp = (blockIdx.x * blockDim.x + threadIdx.x) >> 5;
    int lane = threadIdx.x & 31;
    if (warp >= n) return;
    const float* row = hs + (size_t)warp * HDIM;
    float acc[NEXP];
    #pragma unroll
    for (int o = 0; o < NEXP; o++) acc[o] = 0.f;
    for (int k = lane; k < HDIM; k += 32) {
        float v = row[k];
        const float* w2 = Ws2 + k * NEXP;
        #pragma unroll
        for (int o = 0; o < NEXP; o++) acc[o] = fmaf(v, w2[o], acc[o]);
    }
    #pragma unroll
    for (int o = 0; o < NEXP; o++)
        #pragma unroll
        for (int off = 16; off; off >>= 1) acc[o] += __shfl_down_sync(0xffffffffu, acc[o], off);
    if (lane == 0) {
        int g = batch[warp];
        float lg[NEXP];
        #pragma unroll
        for (int o = 0; o < NEXP; o++)
            lg[o] = 0.5f * (acc[o] + bs2[o]) + 0.5f * strug[g * NEXP + o];
        float m1 = -3.4e38f; int i1 = 0;
        #pragma unroll
        for (int o = 0; o < NEXP; o++) if (lg[o] > m1) { m1 = lg[o]; i1 = o; }
        float m2 = -3.4e38f; int i2 = 0;
        #pragma unroll
        for (int o = 0; o < NEXP; o++) if (o != i1 && lg[o] > m2) { m2 = lg[o]; i2 = o; }
        float e2 = __expf(m2 - m1);
        float inv = 1.0f / (1.0f + e2);
        float* srow = sparse + (size_t)warp * NEXP;
        #pragma unroll
        for (int o = 0; o < NEXP; o++) srow[o] = 0.f;
        srow[i1] = inv;
        srow[i2] = e2 * inv;
    }
}

// ===========================================================================
// CSR build (counting sort by dst)
// ===========================================================================
__global__ void k_deg(const int* __restrict__ dst, int* __restrict__ deg, int e) {
    int i = blockIdx.x * blockDim.x + threadIdx.x;
    if (i < e) atomicAdd(&deg[dst[i]], 1);
}

__global__ void k_scan(const int* __restrict__ deg, int* __restrict__ rowptr,
                       int* __restrict__ cursor, int n) {
    __shared__ int sh[1024];
    __shared__ int carry;
    if (threadIdx.x == 0) { carry = 0; rowptr[0] = 0; }
    __syncthreads();
    for (int base = 0; base < n; base += 1024) {
        int i = base + (int)threadIdx.x;
        int v = (i < n) ? deg[i] : 0;
        sh[threadIdx.x] = v;
        __syncthreads();
        #pragma unroll
        for (int off = 1; off < 1024; off <<= 1) {
            int t = (threadIdx.x >= (unsigned)off) ? sh[threadIdx.x - off] : 0;
            __syncthreads();
            sh[threadIdx.x] += t;
            __syncthreads();
        }
        int inc = sh[threadIdx.x] + carry;
        if (i < n) { rowptr[i + 1] = inc; cursor[i] = inc - v; }
        __syncthreads();
        if (threadIdx.x == 1023) carry = inc;
        __syncthreads();
    }
}

__global__ void k_sortedges(const int* __restrict__ src, const int* __restrict__ dst,
                            int* __restrict__ cursor, int* __restrict__ colsrc, int e) {
    int i = blockIdx.x * blockDim.x + threadIdx.x;
    if (i < e) {
        int d = dst[i];
        int p = atomicAdd(&cursor[d], 1);
        colsrc[p] = src[i];
    }
}

// ===========================================================================
// CSR gather aggregation (no atomics)
// ===========================================================================
__global__ __launch_bounds__(256) void k_agg(const float* __restrict__ z,
                                             float* __restrict__ agg,
                                             const int* __restrict__ rowptr,
                                             const int* __restrict__ colsrc, int n) {
    int node = blockIdx.x;
    if (node >= n) return;
    int c = threadIdx.x;
    int s0 = rowptr[node], s1 = rowptr[node + 1];
    float a0 = 0.f, a1 = 0.f, a2 = 0.f, a3 = 0.f;
    int i = s0;
    for (; i + 3 < s1; i += 4) {
        int sA = colsrc[i], sB = colsrc[i + 1], sC = colsrc[i + 2], sD = colsrc[i + 3];
        a0 += z[(size_t)sA * HDIM + c];
        a1 += z[(size_t)sB * HDIM + c];
        a2 += z[(size_t)sC * HDIM + c];
        a3 += z[(size_t)sD * HDIM + c];
    }
    for (; i < s1; i++) a0 += z[(size_t)colsrc[i] * HDIM + c];
    agg[(size_t)node * HDIM + c] = (a0 + a1) + (a2 + a3);
}

// ===========================================================================
// Weight pack: wT[mat][n][k] = tf32( k<256 ? Wself[mat][k][n] : Wnei[mat][k-256][n] )
// ===========================================================================
__global__ void k_pack(const float* __restrict__ Wself, const float* __restrict__ Wnei,
                       uint32_t* __restrict__ wT) {
    int idx = blockIdx.x * 256 + threadIdx.x;
    int k = idx & 511;
    int rem = idx >> 9;
    int nrow = rem & 255;
    int mat = rem >> 8;
    const float* srcp = (k < 256) ? Wself : Wnei;
    int kk = k & 255;
    float v = srcp[((size_t)mat * 256 + kk) * 256 + nrow];
    wT[idx] = f2tf32(v);
}

// ===========================================================================
// Final combine: out = p0 + p1 + p2 + p3
// ===========================================================================
__global__ void k_combine(const float* __restrict__ p0, const float* __restrict__ p1,
                          const float* __restrict__ p2, const float* __restrict__ p3,
                          float* __restrict__ out, int n4) {
    int i = blockIdx.x * blockDim.x + threadIdx.x;
    if (i >= n4) return;
    float4 a = ((const float4*)p0)[i];
    float4 b = ((const float4*)p1)[i];
    float4 c = ((const float4*)p2)[i];
    float4 d = ((const float4*)p3)[i];
    float4 o;
    o.x = (a.x + b.x) + (c.x + d.x);
    o.y = (a.y + b.y) + (c.y + d.y);
    o.z = (a.z + b.z) + (c.z + d.z);
    o.w = (a.w + b.w) + (c.w + d.w);
    ((float4*)out)[i] = o;
}

// ===========================================================================
// mma.sync tf32 dual GEMM v2:  C = op( [Az|Ag] @ WT^T + bias )
// cp.async double-buffered, 2 CTAs/SM, tf32 conversion in fragment load.
// ===========================================================================
#define PAD 36
#define ABUF (128 * PAD)          // floats per buffer
#define TM_SMEM (4 * ABUF * 4)    // A0,A1,B0,B1 = 73728 bytes

__global__ __launch_bounds__(256, 2) void k_tmma(
    const float* __restrict__ Az, const float* __restrict__ Ag,
    const float* __restrict__ WT, const float* __restrict__ bias,
    int n, int relu, float* __restrict__ C,
    const float* __restrict__ sparse, int expert, int accum)
{
    extern __shared__ float smf[];
    uint32_t sbase = smem_u32(smf);

    int tid = threadIdx.x;
    int warp = tid >> 5, lane = tid & 31;
    int m0 = blockIdx.x * 128;
    int n0 = blockIdx.y * 128;
    int m_off = (warp >> 1) * 32;
    int n_off = (warp & 1) * 64;
    int g = lane >> 2, t = lane & 3;

    float acc[2][8][4];
    #pragma unroll
    for (int i = 0; i < 2; i++)
        #pragma unroll
        for (int j = 0; j < 8; j++)
            #pragma unroll
            for (int r = 0; r < 4; r++) acc[i][j][r] = 0.f;

    // cp.async chunk issue: A tile 128x32 + B tile 128x32, 4+4 ops/thread
    int crow = tid >> 3;          // 0..31, +32 per i
    int ckq  = (tid & 7) * 4;     // 0,4,...,28
    auto issue_chunk = [&](int c, int buf) {
        const float* Asrc = (c < 8) ? Az : Ag;
        int kb = (c & 7) * 32;
        uint32_t abase = sbase + (uint32_t)buf * (ABUF * 4);
        uint32_t bbase = sbase + (uint32_t)(2 + buf) * (ABUF * 4);
        #pragma unroll
        for (int i = 0; i < 4; i++) {
            int row = crow + i * 32;
            int gr = m0 + row;
            int grc = (gr < n) ? gr : 0;
            cp16(abase + (uint32_t)(row * PAD + ckq) * 4,
                 Asrc + (size_t)grc * HDIM + kb + ckq,
                 (gr < n) ? 16 : 0);
            cp16u(bbase + (uint32_t)(row * PAD + ckq) * 4,
                  WT + (size_t)(n0 + row) * 512 + c * 32 + ckq);
        }
        asm volatile("cp.async.commit_group;" ::: "memory");
    };

    issue_chunk(0, 0);

    for (int c = 0; c < 16; c++) {
        int buf = c & 1;
        if (c < 15) {
            issue_chunk(c + 1, buf ^ 1);
            asm volatile("cp.async.wait_group 1;" ::: "memory");
        } else {
            asm volatile("cp.async.wait_group 0;" ::: "memory");
        }
        __syncthreads();

        const float* abase = smf + (size_t)buf * ABUF + m_off * PAD;
        const float* bbase = smf + (size_t)(2 + buf) * ABUF + n_off * PAD;
        #pragma unroll
        for (int ks = 0; ks < 4; ks++) {
            int k0 = ks * 8;
            uint32_t af[2][4], bf[8][2];
            #pragma unroll
            for (int i = 0; i < 2; i++) {
                const float* ap = abase + (i * 16 + g) * PAD + k0 + t;
                af[i][0] = f2tf32(ap[0]);
                af[i][1] = f2tf32(ap[8 * PAD]);
                af[i][2] = f2tf32(ap[4]);
                af[i][3] = f2tf32(ap[8 * PAD + 4]);
            }
            #pragma unroll
            for (int j = 0; j < 8; j++) {
                const float* bp = bbase + (j * 8 + g) * PAD + k0 + t;
                bf[j][0] = __float_as_uint(bp[0]);
                bf[j][1] = __float_as_uint(bp[4]);
            }
            #pragma unroll
            for (int i = 0; i < 2; i++)
                #pragma unroll
                for (int j = 0; j < 8; j++)
                    mma_tf32(acc[i][j], af[i], bf[j]);
        }
        __syncthreads();
    }

    // ---- epilogue ----
    #pragma unroll
    for (int i = 0; i < 2; i++) {
        int r0 = m0 + m_off + i * 16 + g;
        int r1 = r0 + 8;
        float s0 = 0.f, s1 = 0.f;
        if (sparse != nullptr) {
            if (r0 < n) s0 = sparse[(size_t)r0 * NEXP + expert];
            if (r1 < n) s1 = sparse[(size_t)r1 * NEXP + expert];
        }
        #pragma unroll
        for (int j = 0; j < 8; j++) {
            int col = n0 + n_off + j * 8 + 2 * t;
            float2 bb = *(const float2*)(bias + col);
            float2 v0, v1;
            v0.x = acc[i][j][0] + bb.x; v0.y = acc[i][j][1] + bb.y;
            v1.x = acc[i][j][2] + bb.x; v1.y = acc[i][j][3] + bb.y;
            if (relu) {
                v0.x = fmaxf(v0.x, 0.f); v0.y = fmaxf(v0.y, 0.f);
                v1.x = fmaxf(v1.x, 0.f); v1.y = fmaxf(v1.y, 0.f);
            }
            if (sparse != nullptr) {
                if (r0 < n) {
                    float2* op = (float2*)(C + (size_t)r0 * HDIM + col);
                    float2 o = accum ? *op : make_float2(0.f, 0.f);
                    o.x = fmaf(s0, v0.x, o.x); o.y = fmaf(s0, v0.y, o.y);
                    *op = o;
                }
                if (r1 < n) {
                    float2* op = (float2*)(C + (size_t)r1 * HDIM + col);
                    float2 o = accum ? *op : make_float2(0.f, 0.f);
                    o.x = fmaf(s1, v1.x, o.x); o.y = fmaf(s1, v1.y, o.y);
                    *op = o;
                }
            } else {
                if (r0 < n) *(float2*)(C + (size_t)r0 * HDIM + col) = v0;
                if (r1 < n) *(float2*)(C + (size_t)r1 * HDIM + col) = v1;
            }
        }
    }
}

// ===========================================================================
// host launch
// ===========================================================================
extern "C" void kernel_launch(void* const* d_in, const int* in_sizes, int n_in,
                              void* d_out, int out_size) {
    const float* x      = (const float*)d_in[0];
    const int*   ei     = (const int*)  d_in[1];
    const int*   batch  = (const int*)  d_in[2];
    const float* W_enc  = (const float*)d_in[3];
    const float* b_enc  = (const float*)d_in[4];
    const float* Ws1    = (const float*)d_in[5];
    const float* bs1    = (const float*)d_in[6];
    const float* Ws2    = (const float*)d_in[7];
    const float* bs2    = (const float*)d_in[8];
    const float* Wt1    = (const float*)d_in[9];
    const float* bt1    = (const float*)d_in[10];
    const float* Wt2    = (const float*)d_in[11];
    const float* bt2    = (const float*)d_in[12];
    const float* W_self = (const float*)d_in[13];
    const float* W_nei  = (const float*)d_in[14];
    const float* b_exp  = (const float*)d_in[15];

    int N = in_sizes[0] / 10;
    int E = in_sizes[1] / 2;
    const int* src = ei;
    const int* dst = ei + E;
    float* out = (float*)d_out;

    float *h, *hs, *agg0, *zA, *zB, *agT, *part, *sparse, *strug, *wT;
    int *deg, *rowptr, *cursor, *colsrc, *ng, *eg;
    cudaGetSymbolAddress((void**)&h,      g_h);
    cudaGetSymbolAddress((void**)&hs,     g_hs);
    cudaGetSymbolAddress((void**)&agg0,   g_agg0);
    cudaGetSymbolAddress((void**)&zA,     g_zA);
    cudaGetSymbolAddress((void**)&zB,     g_zB);
    cudaGetSymbolAddress((void**)&agT,    g_agT);
    cudaGetSymbolAddress((void**)&part,   g_part);
    cudaGetSymbolAddress((void**)&sparse, g_sparse);
    cudaGetSymbolAddress((void**)&strug,  g_strug);
    cudaGetSymbolAddress((void**)&wT,     g_wT);
    cudaGetSymbolAddress((void**)&deg,    g_deg);
    cudaGetSymbolAddress((void**)&rowptr, g_rowptr);
    cudaGetSymbolAddress((void**)&cursor, g_cursor);
    cudaGetSymbolAddress((void**)&colsrc, g_colsrc);
    cudaGetSymbolAddress((void**)&ng,     g_ng);
    cudaGetSymbolAddress((void**)&eg,     g_eg);

    cudaFuncSetAttribute(k_tmma, cudaFuncAttributeMaxDynamicSharedMemorySize, TM_SMEM);

    const size_t ZSZ = (size_t)MAXN * HDIM;

    // ---- prologue on capture stream (0)
    cudaMemsetAsync(ng,  0, NGRAPH * sizeof(int), 0);
    cudaMemsetAsync(eg,  0, NGRAPH * sizeof(int), 0);
    cudaMemsetAsync(deg, 0, (size_t)N * sizeof(int), 0);

    k_pack<<<24 * 256 * 512 / 256, 256>>>(W_self, W_nei, (uint32_t*)wT);
    k_hist_nodes<<<128, 256>>>(batch, ng, N);
    k_hist_edges<<<256, 256>>>(batch, src, eg, E);
    k_stru<<<NGRAPH, 256>>>(ng, eg, Wt1, bt1, Wt2, bt2, strug);
    k_encode<<<N, 256>>>(x, W_enc, b_enc, h, N);

    // fork router path onto s[4]
    cudaEventRecord(g_sp.evA, 0);
    cudaStreamWaitEvent(g_sp.s[NSTREAM], g_sp.evA, 0);
    {
        dim3 rgrid((N + BMR - 1) / BMR, HDIM / BNR);
        k_gemm<<<rgrid, 256, 0, g_sp.s[NSTREAM]>>>(h, Ws1, bs1, N, hs);
        k_logits<<<(N + 7) / 8, 256, 0, g_sp.s[NSTREAM]>>>(hs, Ws2, bs2, strug, batch, sparse, N);
        cudaEventRecord(g_sp.evB, g_sp.s[NSTREAM]);
    }

    // meanwhile on stream 0: CSR build + shared layer-0 aggregation
    k_deg<<<(E + 255) / 256, 256>>>(dst, deg, E);
    k_scan<<<1, 1024>>>(deg, rowptr, cursor, N);
    k_sortedges<<<(E + 255) / 256, 256>>>(src, dst, cursor, colsrc, E);
    k_agg<<<N, 256>>>(h, agg0, rowptr, colsrc, N);

    cudaEventRecord(g_sp.fork, 0);

    // ---- 4 parallel expert chains, 2 experts each
    dim3 mgrid((N + 127) / 128, 2);
    for (int i = 0; i < NSTREAM; i++) {
        cudaStream_t st = g_sp.s[i];
        cudaStreamWaitEvent(st, g_sp.fork, 0);
        cudaStreamWaitEvent(st, g_sp.evB, 0);
        float* zAi = zA + (size_t)i * ZSZ;
        float* zBi = zB + (size_t)i * ZSZ;
        float* agi = agT + (size_t)i * ZSZ;
        float* pti = part + (size_t)i * ZSZ;
        for (int j = 0; j < 2; j++) {
            int e = i * 2 + j;
            const float* wt0 = wT + (size_t)(e * 3 + 0) * 256 * 512;
            const float* wt1 = wT + (size_t)(e * 3 + 1) * 256 * 512;
            const float* wt2 = wT + (size_t)(e * 3 + 2) * 256 * 512;
            const float* b_l0 = b_exp + (size_t)(e * 3 + 0) * HDIM;
            const float* b_l1 = b_exp + (size_t)(e * 3 + 1) * HDIM;
            const float* b_l2 = b_exp + (size_t)(e * 3 + 2) * HDIM;

            k_tmma<<<mgrid, 256, TM_SMEM, st>>>(h,  agg0, wt0, b_l0, N, 1, zAi, nullptr, 0, 0);
            k_agg<<<N, 256, 0, st>>>(zAi, agi, rowptr, colsrc, N);
            k_tmma<<<mgrid, 256, TM_SMEM, st>>>(zAi, agi, wt1, b_l1, N, 1, zBi, nullptr, 0, 0);
            k_agg<<<N, 256, 0, st>>>(zBi, agi, rowptr, colsrc, N);
            k_tmma<<<mgrid, 256, TM_SMEM, st>>>(zBi, agi, wt2, b_l2, N, 0, pti, sparse, e, (j > 0) ? 1 : 0);
        }
        cudaEventRecord(g_sp.join[i], st);
    }

    // ---- join + combine
    for (int i = 0; i < NSTREAM; i++) cudaStreamWaitEvent(0, g_sp.join[i], 0);
    int n4 = N * HDIM / 4;
    k_combine<<<(n4 + 255) / 256, 256>>>(part, part + ZSZ, part + 2 * ZSZ, part + 3 * ZSZ, out, n4);
}

// round 7
// speedup vs baseline: 4.9440x; 1.6085x over previous
#include <cuda_runtime.h>
#include <cuda_fp16.h>
#include <cstdint>
#include <cstddef>

// ---------------------------------------------------------------------------
// GraphMoEDualRouter — GB300 sm_103a.
// Round 6: full fp16 expert pipeline (storage + m16n8k16 HMMA, fp32 accum).
// fp16 mantissa == tf32 mantissa (11 bits) -> same rounding as before, but
// products are exact and all traffic halves. Router path stays fp32-exact.
// ---------------------------------------------------------------------------

#define HDIM 256
#define NEXP 8
#define NGRAPH 64
#define MAXN 50176
#define MAXE 1600000
#define NSTREAM 4

typedef unsigned long long ull;

// ---- scratch (static device memory; allocation is forbidden) ----
__device__ float  g_h    [MAXN * HDIM];                 // fp32 h (router)
__device__ __half g_h16  [MAXN * HDIM];                 // fp16 h (experts)
__device__ float  g_hs   [MAXN * HDIM];                 // router hidden
__device__ __half g_agg0 [MAXN * HDIM];
__device__ __half g_zA   [NSTREAM][MAXN * HDIM];
__device__ __half g_zB   [NSTREAM][MAXN * HDIM];
__device__ __half g_agT  [NSTREAM][MAXN * HDIM];
__device__ float  g_part [NSTREAM][MAXN * HDIM];
__device__ float  g_sparse[MAXN * NEXP];
__device__ int    g_deg   [MAXN];
__device__ int    g_rowptr[MAXN + 1];
__device__ int    g_cursor[MAXN];
__device__ int    g_colsrc[MAXE];
__device__ int    g_ng[NGRAPH];
__device__ int    g_eg[NGRAPH];
__device__ float  g_strug[NGRAPH * NEXP];
// packed transposed fp16 weights: [24 mats][256 nrows][512 k]
__device__ __half g_wTh[24 * 256 * 512];

// ---- host-side streams/events (created once, pre-main; host resources only)
struct StreamPool {
    cudaStream_t s[NSTREAM + 1];
    cudaEvent_t evA, evB, fork, join[NSTREAM];
    StreamPool() {
        for (int i = 0; i <= NSTREAM; i++)
            cudaStreamCreateWithFlags(&s[i], cudaStreamNonBlocking);
        cudaEventCreateWithFlags(&evA,  cudaEventDisableTiming);
        cudaEventCreateWithFlags(&evB,  cudaEventDisableTiming);
        cudaEventCreateWithFlags(&fork, cudaEventDisableTiming);
        for (int i = 0; i < NSTREAM; i++)
            cudaEventCreateWithFlags(&join[i], cudaEventDisableTiming);
    }
};
static StreamPool g_sp;

// ---- helpers ----
__device__ __forceinline__ ull pack2(float lo, float hi) {
    ull r; asm("mov.b64 %0, {%1, %2};" : "=l"(r) : "f"(lo), "f"(hi)); return r;
}
__device__ __forceinline__ void fma2acc(ull& d, ull a, ull b) {
    asm("fma.rn.f32x2 %0, %1, %2, %0;" : "+l"(d) : "l"(a), "l"(b));
}
__device__ __forceinline__ void unpack2(ull v, float& lo, float& hi) {
    asm("mov.b64 {%0, %1}, %2;" : "=f"(lo), "=f"(hi) : "l"(v));
}
__device__ __forceinline__ void mma_f16(float* d, const uint32_t* a, const uint32_t* b) {
    asm volatile(
        "mma.sync.aligned.m16n8k16.row.col.f32.f16.f16.f32 "
        "{%0,%1,%2,%3}, {%4,%5,%6,%7}, {%8,%9}, {%0,%1,%2,%3};"
        : "+f"(d[0]), "+f"(d[1]), "+f"(d[2]), "+f"(d[3])
        : "r"(a[0]), "r"(a[1]), "r"(a[2]), "r"(a[3]), "r"(b[0]), "r"(b[1]));
}
__device__ __forceinline__ uint32_t smem_u32(const void* p) {
    uint32_t a;
    asm("{ .reg .u64 t; cvta.to.shared.u64 t, %1; cvt.u32.u64 %0, t; }" : "=r"(a) : "l"(p));
    return a;
}
__device__ __forceinline__ void cp16(uint32_t dst, const void* src, int sz) {
    asm volatile("cp.async.cg.shared.global [%0], [%1], 16, %2;"
                 :: "r"(dst), "l"(src), "r"(sz) : "memory");
}
__device__ __forceinline__ void cp16u(uint32_t dst, const void* src) {
    asm volatile("cp.async.cg.shared.global [%0], [%1], 16;"
                 :: "r"(dst), "l"(src) : "memory");
}

// ===========================================================================
// Small kernels
// ===========================================================================
__global__ void k_hist_nodes(const int* __restrict__ batch, int* __restrict__ ng, int n) {
    __shared__ int sh[NGRAPH];
    if (threadIdx.x < NGRAPH) sh[threadIdx.x] = 0;
    __syncthreads();
    for (int i = blockIdx.x * blockDim.x + threadIdx.x; i < n; i += gridDim.x * blockDim.x)
        atomicAdd(&sh[batch[i]], 1);
    __syncthreads();
    if (threadIdx.x < NGRAPH) atomicAdd(&ng[threadIdx.x], sh[threadIdx.x]);
}

__global__ void k_hist_edges(const int* __restrict__ batch, const int* __restrict__ src,
                             int* __restrict__ eg, int e) {
    __shared__ int sh[NGRAPH];
    if (threadIdx.x < NGRAPH) sh[threadIdx.x] = 0;
    __syncthreads();
    for (int i = blockIdx.x * blockDim.x + threadIdx.x; i < e; i += gridDim.x * blockDim.x)
        atomicAdd(&sh[batch[src[i]]], 1);
    __syncthreads();
    if (threadIdx.x < NGRAPH) atomicAdd(&eg[threadIdx.x], sh[threadIdx.x]);
}

__global__ void k_stru(const int* __restrict__ ng, const int* __restrict__ eg,
                       const float* __restrict__ Wt1, const float* __restrict__ bt1,
                       const float* __restrict__ Wt2, const float* __restrict__ bt2,
                       float* __restrict__ strug) {
    int g = blockIdx.x;
    float fn = log1pf((float)ng[g]);
    float fe = log1pf((float)eg[g]);
    __shared__ float hid[HDIM];
    int j = threadIdx.x;
    hid[j] = fmaxf(fmaf(fn, Wt1[j], fmaf(fe, Wt1[HDIM + j], bt1[j])), 0.0f);
    __syncthreads();
    int w = threadIdx.x >> 5, lane = threadIdx.x & 31;
    if (w < NEXP) {
        float acc = 0.f;
        for (int k = lane; k < HDIM; k += 32) acc = fmaf(hid[k], Wt2[k * NEXP + w], acc);
        #pragma unroll
        for (int off = 16; off; off >>= 1) acc += __shfl_down_sync(0xffffffffu, acc, off);
        if (lane == 0) strug[g * NEXP + w] = acc + bt2[w];
    }
}

__global__ void k_encode(const float* __restrict__ x, const float* __restrict__ W,
                         const float* __restrict__ b, float* __restrict__ h,
                         __half* __restrict__ h16, int n) {
    int node = blockIdx.x;
    if (node >= n) return;
    __shared__ float xs[6];
    if (threadIdx.x < 6) xs[threadIdx.x] = x[node * 10 + 4 + threadIdx.x];
    __syncthreads();
    int j = threadIdx.x;
    float acc = b[j];
    #pragma unroll
    for (int k = 0; k < 6; k++) acc = fmaf(xs[k], W[k * HDIM + j], acc);
    float v = fmaxf(acc, 0.0f);
    h[(size_t)node * HDIM + j] = v;
    h16[(size_t)node * HDIM + j] = __float2half_rn(v);
}

// ===========================================================================
// FFMA fp32 GEMM — router hidden layer only (top-2 selection needs exactness)
// ===========================================================================
#define BMR 128
#define BNR 64
#define BKR 16

__global__ __launch_bounds__(256) void k_gemm(
    const float* __restrict__ A, const float* __restrict__ W1,
    const float* __restrict__ bias, int n, float* __restrict__ C)
{
    __shared__ __align__(16) float As[BKR][BMR + 2];
    __shared__ __align__(16) float Ws[BKR][BNR];

    int m0 = blockIdx.x * BMR;
    int n0 = blockIdx.y * BNR;
    int tid = threadIdx.x;
    int tm = tid >> 4;
    int tn = tid & 15;

    ull acc2[4][4];
    #pragma unroll
    for (int i = 0; i < 4; i++)
        #pragma unroll
        for (int j = 0; j < 4; j++) acc2[i][j] = 0ull;

    for (int kc = 0; kc < HDIM; kc += BKR) {
        #pragma unroll
        for (int u = 0; u < 2; u++) {
            int idx = tid + u * 256;
            int row = idx >> 2;
            int kq  = idx & 3;
            float4 v = make_float4(0.f, 0.f, 0.f, 0.f);
            int gr = m0 + row;
            if (gr < n) v = *(const float4*)(A + (size_t)gr * HDIM + kc + kq * 4);
            As[kq * 4 + 0][row] = v.x;
            As[kq * 4 + 1][row] = v.y;
            As[kq * 4 + 2][row] = v.z;
            As[kq * 4 + 3][row] = v.w;
        }
        {
            int kk = tid >> 4, nq = tid & 15;
            float4 w = *(const float4*)(W1 + (size_t)(kc + kk) * HDIM + n0 + nq * 4);
            *(float4*)&Ws[kk][nq * 4] = w;
        }
        __syncthreads();
        #pragma unroll
        for (int kk = 0; kk < BKR; kk++) {
            ull a2[4];
            #pragma unroll
            for (int i2 = 0; i2 < 4; i2++)
                a2[i2] = *(const ull*)&As[kk][tm * 8 + i2 * 2];
            #pragma unroll
            for (int j = 0; j < 4; j++) {
                float bb = Ws[kk][tn * 4 + j];
                ull b2 = pack2(bb, bb);
                #pragma unroll
                for (int i2 = 0; i2 < 4; i2++) fma2acc(acc2[i2][j], a2[i2], b2);
            }
        }
        __syncthreads();
    }

    float4 bb4 = *(const float4*)&bias[n0 + tn * 4];
    #pragma unroll
    for (int i2 = 0; i2 < 4; i2++) {
        float4 vlo, vhi;
        unpack2(acc2[i2][0], vlo.x, vhi.x);
        unpack2(acc2[i2][1], vlo.y, vhi.y);
        unpack2(acc2[i2][2], vlo.z, vhi.z);
        unpack2(acc2[i2][3], vlo.w, vhi.w);
        #pragma unroll
        for (int rr = 0; rr < 2; rr++) {
            int row = m0 + tm * 8 + i2 * 2 + rr;
            if (row >= n) continue;
            float4 v = rr ? vhi : vlo;
            v.x = fmaxf(v.x + bb4.x, 0.f); v.y = fmaxf(v.y + bb4.y, 0.f);
            v.z = fmaxf(v.z + bb4.z, 0.f); v.w = fmaxf(v.w + bb4.w, 0.f);
            *(float4*)(C + (size_t)row * HDIM + n0 + tn * 4) = v;
        }
    }
}

// ===========================================================================
// Router logits + top-2 sparse gates
// ===========================================================================
__global__ void k_logits(const float* __restrict__ hs, const float* __restrict__ Ws2,
                         const float* __restrict__ bs2, const float* __restrict__ strug,
                         const int* __restrict__ batch, float* __restrict__ sparse, int n) {
    int warp = (blockIdx.x * blockDim.x + threadIdx.x) >> 5;
    int lane = threadIdx.x & 31;
    if (warp >= n) return;
    const float* row = hs + (size_t)warp * HDIM;
    float acc[NEXP];
    #pragma unroll
    for (int o = 0; o < NEXP; o++) acc[o] = 0.f;
    for (int k = lane; k < HDIM; k += 32) {
        float v = row[k];
        const float* w2 = Ws2 + k * NEXP;
        #pragma unroll
        for (int o = 0; o < NEXP; o++) acc[o] = fmaf(v, w2[o], acc[o]);
    }
    #pragma unroll
    for (int o = 0; o < NEXP; o++)
        #pragma unroll
        for (int off = 16; off; off >>= 1) acc[o] += __shfl_down_sync(0xffffffffu, acc[o], off);
    if (lane == 0) {
        int g = batch[warp];
        float lg[NEXP];
        #pragma unroll
        for (int o = 0; o < NEXP; o++)
            lg[o] = 0.5f * (acc[o] + bs2[o]) + 0.5f * strug[g * NEXP + o];
        float m1 = -3.4e38f; int i1 = 0;
        #pragma unroll
        for (int o = 0; o < NEXP; o++) if (lg[o] > m1) { m1 = lg[o]; i1 = o; }
        float m2 = -3.4e38f; int i2 = 0;
        #pragma unroll
        for (int o = 0; o < NEXP; o++) if (o != i1 && lg[o] > m2) { m2 = lg[o]; i2 = o; }
        float e2 = __expf(m2 - m1);
        float inv = 1.0f / (1.0f + e2);
        float* srow = sparse + (size_t)warp * NEXP;
        #pragma unroll
        for (int o = 0; o < NEXP; o++) srow[o] = 0.f;
        srow[i1] = inv;
        srow[i2] = e2 * inv;
    }
}

// ===========================================================================
// CSR build (counting sort by dst)
// ===========================================================================
__global__ void k_deg(const int* __restrict__ dst, int* __restrict__ deg, int e) {
    int i = blockIdx.x * blockDim.x + threadIdx.x;
    if (i < e) atomicAdd(&deg[dst[i]], 1);
}

__global__ void k_scan(const int* __restrict__ deg, int* __restrict__ rowptr,
                       int* __restrict__ cursor, int n) {
    __shared__ int sh[1024];
    __shared__ int carry;
    if (threadIdx.x == 0) { carry = 0; rowptr[0] = 0; }
    __syncthreads();
    for (int base = 0; base < n; base += 1024) {
        int i = base + (int)threadIdx.x;
        int v = (i < n) ? deg[i] : 0;
        sh[threadIdx.x] = v;
        __syncthreads();
        #pragma unroll
        for (int off = 1; off < 1024; off <<= 1) {
            int t = (threadIdx.x >= (unsigned)off) ? sh[threadIdx.x - off] : 0;
            __syncthreads();
            sh[threadIdx.x] += t;
            __syncthreads();
        }
        int inc = sh[threadIdx.x] + carry;
        if (i < n) { rowptr[i + 1] = inc; cursor[i] = inc - v; }
        __syncthreads();
        if (threadIdx.x == 1023) carry = inc;
        __syncthreads();
    }
}

__global__ void k_sortedges(const int* __restrict__ src, const int* __restrict__ dst,
                            int* __restrict__ cursor, int* __restrict__ colsrc, int e) {
    int i = blockIdx.x * blockDim.x + threadIdx.x;
    if (i < e) {
        int d = dst[i];
        int p = atomicAdd(&cursor[d], 1);
        colsrc[p] = src[i];
    }
}

// ===========================================================================
// fp16 CSR gather aggregation: agg[n] = sum_{in-edges} z[src]  (fp32 accum)
// One block (128 threads = 128 half2 cols) per node.
// ===========================================================================
__global__ __launch_bounds__(128) void k_agg(const __half2* __restrict__ z,
                                             __half2* __restrict__ agg,
                                             const int* __restrict__ rowptr,
                                             const int* __restrict__ colsrc, int n) {
    int node = blockIdx.x;
    if (node >= n) return;
    int c = threadIdx.x;                 // 0..127 half2 columns
    int s0 = rowptr[node], s1 = rowptr[node + 1];
    float2 a0 = make_float2(0.f, 0.f), a1 = make_float2(0.f, 0.f);
    float2 a2 = make_float2(0.f, 0.f), a3 = make_float2(0.f, 0.f);
    int i = s0;
    for (; i + 3 < s1; i += 4) {
        int sA = colsrc[i], sB = colsrc[i + 1], sC = colsrc[i + 2], sD = colsrc[i + 3];
        float2 vA = __half22float2(z[(size_t)sA * 128 + c]);
        float2 vB = __half22float2(z[(size_t)sB * 128 + c]);
        float2 vC = __half22float2(z[(size_t)sC * 128 + c]);
        float2 vD = __half22float2(z[(size_t)sD * 128 + c]);
        a0.x += vA.x; a0.y += vA.y;
        a1.x += vB.x; a1.y += vB.y;
        a2.x += vC.x; a2.y += vC.y;
        a3.x += vD.x; a3.y += vD.y;
    }
    for (; i < s1; i++) {
        float2 v = __half22float2(z[(size_t)colsrc[i] * 128 + c]);
        a0.x += v.x; a0.y += v.y;
    }
    float rx = (a0.x + a1.x) + (a2.x + a3.x);
    float ry = (a0.y + a1.y) + (a2.y + a3.y);
    agg[(size_t)node * 128 + c] = __floats2half2_rn(rx, ry);
}

// ===========================================================================
// Weight pack: wTh[mat][n][k] = fp16( k<256 ? Wself[mat][k][n] : Wnei[...][n] )
// ===========================================================================
__global__ void k_pack(const float* __restrict__ Wself, const float* __restrict__ Wnei,
                       __half* __restrict__ wTh) {
    int idx = blockIdx.x * 256 + threadIdx.x;
    int k = idx & 511;
    int rem = idx >> 9;
    int nrow = rem & 255;
    int mat = rem >> 8;
    const float* srcp = (k < 256) ? Wself : Wnei;
    int kk = k & 255;
    wTh[idx] = __float2half_rn(srcp[((size_t)mat * 256 + kk) * 256 + nrow]);
}

// ===========================================================================
// Final combine: out = p0 + p1 + p2 + p3
// ===========================================================================
__global__ void k_combine(const float* __restrict__ p0, const float* __restrict__ p1,
                          const float* __restrict__ p2, const float* __restrict__ p3,
                          float* __restrict__ out, int n4) {
    int i = blockIdx.x * blockDim.x + threadIdx.x;
    if (i >= n4) return;
    float4 a = ((const float4*)p0)[i];
    float4 b = ((const float4*)p1)[i];
    float4 c = ((const float4*)p2)[i];
    float4 d = ((const float4*)p3)[i];
    float4 o;
    o.x = (a.x + b.x) + (c.x + d.x);
    o.y = (a.y + b.y) + (c.y + d.y);
    o.z = (a.z + b.z) + (c.z + d.z);
    o.w = (a.w + b.w) + (c.w + d.w);
    ((float4*)out)[i] = o;
}

// ===========================================================================
// fp16 mma.sync dual GEMM:  C = op( [Az|Ag] @ WTh^T + bias )
// BM=128, BN=128, BK=64 (8 chunks over virtual K=512), m16n8k16, fp32 accum.
// cp.async double-buffered, 2 CTAs/SM. PADH=72 halves -> conflict-free frags.
// Ch != null: intermediate fp16 output (relu). Cf != null: final gated fp32.
// ===========================================================================
#define PADH 72
#define HBUF (128 * PADH)                 // halves per buffer (18432 B)
#define TM_SMEM (4 * HBUF * 2)            // 73728 bytes

__global__ __launch_bounds__(256, 2) void k_tmma(
    const __half* __restrict__ Az, const __half* __restrict__ Ag,
    const __half* __restrict__ WTh, const float* __restrict__ bias,
    int n, int relu, __half* __restrict__ Ch, float* __restrict__ Cf,
    const float* __restrict__ sparse, int expert, int accum)
{
    extern __shared__ __half smh[];
    uint32_t sbase = smem_u32(smh);

    int tid = threadIdx.x;
    int warp = tid >> 5, lane = tid & 31;
    int m0 = blockIdx.x * 128;
    int n0 = blockIdx.y * 128;
    int m_off = (warp >> 1) * 32;
    int n_off = (warp & 1) * 64;
    int g = lane >> 2, t = lane & 3;

    float acc[2][8][4];
    #pragma unroll
    for (int i = 0; i < 2; i++)
        #pragma unroll
        for (int j = 0; j < 8; j++)
            #pragma unroll
            for (int r = 0; r < 4; r++) acc[i][j][r] = 0.f;

    // cp.async: A tile 128x64 halves (16KB) + B tile same; 4+4 cp16 per thread
    auto issue_chunk = [&](int c, int buf) {
        const __half* Asrc = (c < 4) ? Az : Ag;
        int kb = (c & 3) * 64;
        uint32_t abase = sbase + (uint32_t)buf * (HBUF * 2);
        uint32_t bbase = sbase + (uint32_t)(2 + buf) * (HBUF * 2);
        #pragma unroll
        for (int i = 0; i < 4; i++) {
            int idx = tid + i * 256;
            int row = idx >> 3, q = idx & 7;
            int gr = m0 + row;
            int grc = (gr < n) ? gr : 0;
            cp16(abase + (uint32_t)(row * (PADH * 2) + q * 16),
                 Asrc + (size_t)grc * HDIM + kb + q * 8,
                 (gr < n) ? 16 : 0);
            cp16u(bbase + (uint32_t)(row * (PADH * 2) + q * 16),
                  WTh + (size_t)(n0 + row) * 512 + c * 64 + q * 8);
        }
        asm volatile("cp.async.commit_group;" ::: "memory");
    };

    issue_chunk(0, 0);

    for (int c = 0; c < 8; c++) {
        int buf = c & 1;
        if (c < 7) {
            issue_chunk(c + 1, buf ^ 1);
            asm volatile("cp.async.wait_group 1;" ::: "memory");
        } else {
            asm volatile("cp.async.wait_group 0;" ::: "memory");
        }
        __syncthreads();

        const __half* ab = smh + (size_t)buf * HBUF + m_off * PADH;
        const __half* bb = smh + (size_t)(2 + buf) * HBUF + n_off * PADH;
        #pragma unroll
        for (int ks = 0; ks < 4; ks++) {
            int k0 = ks * 16;
            uint32_t af[2][4], bf[8][2];
            #pragma unroll
            for (int i = 0; i < 2; i++) {
                const __half* ap = ab + (i * 16 + g) * PADH + k0 + 2 * t;
                af[i][0] = *(const uint32_t*)(ap);
                af[i][1] = *(const uint32_t*)(ap + 8 * PADH);
                af[i][2] = *(const uint32_t*)(ap + 8);
                af[i][3] = *(const uint32_t*)(ap + 8 * PADH + 8);
            }
            #pragma unroll
            for (int j = 0; j < 8; j++) {
                const __half* bp = bb + (j * 8 + g) * PADH + k0 + 2 * t;
                bf[j][0] = *(const uint32_t*)(bp);
                bf[j][1] = *(const uint32_t*)(bp + 8);
            }
            #pragma unroll
            for (int i = 0; i < 2; i++)
                #pragma unroll
                for (int j = 0; j < 8; j++)
                    mma_f16(acc[i][j], af[i], bf[j]);
        }
        __syncthreads();
    }

    // ---- epilogue ----
    #pragma unroll
    for (int i = 0; i < 2; i++) {
        int r0 = m0 + m_off + i * 16 + g;
        int r1 = r0 + 8;
        float s0 = 0.f, s1 = 0.f;
        if (Cf != nullptr) {
            if (r0 < n) s0 = sparse[(size_t)r0 * NEXP + expert];
            if (r1 < n) s1 = sparse[(size_t)r1 * NEXP + expert];
        }
        #pragma unroll
        for (int j = 0; j < 8; j++) {
            int col = n0 + n_off + j * 8 + 2 * t;
            float2 bb2 = *(const float2*)(bias + col);
            float2 v0, v1;
            v0.x = acc[i][j][0] + bb2.x; v0.y = acc[i][j][1] + bb2.y;
            v1.x = acc[i][j][2] + bb2.x; v1.y = acc[i][j][3] + bb2.y;
            if (relu) {
                v0.x = fmaxf(v0.x, 0.f); v0.y = fmaxf(v0.y, 0.f);
                v1.x = fmaxf(v1.x, 0.f); v1.y = fmaxf(v1.y, 0.f);
            }
            if (Cf != nullptr) {
                if (r0 < n) {
                    float2* op = (float2*)(Cf + (size_t)r0 * HDIM + col);
                    float2 o = accum ? *op : make_float2(0.f, 0.f);
                    o.x = fmaf(s0, v0.x, o.x); o.y = fmaf(s0, v0.y, o.y);
                    *op = o;
                }
                if (r1 < n) {
                    float2* op = (float2*)(Cf + (size_t)r1 * HDIM + col);
                    float2 o = accum ? *op : make_float2(0.f, 0.f);
                    o.x = fmaf(s1, v1.x, o.x); o.y = fmaf(s1, v1.y, o.y);
                    *op = o;
                }
            } else {
                if (r0 < n) *(__half2*)(Ch + (size_t)r0 * HDIM + col) = __floats2half2_rn(v0.x, v0.y);
                if (r1 < n) *(__half2*)(Ch + (size_t)r1 * HDIM + col) = __floats2half2_rn(v1.x, v1.y);
            }
        }
    }
}

// ===========================================================================
// host launch
// ===========================================================================
extern "C" void kernel_launch(void* const* d_in, const int* in_sizes, int n_in,
                              void* d_out, int out_size) {
    const float* x      = (const float*)d_in[0];
    const int*   ei     = (const int*)  d_in[1];
    const int*   batch  = (const int*)  d_in[2];
    const float* W_enc  = (const float*)d_in[3];
    const float* b_enc  = (const float*)d_in[4];
    const float* Ws1    = (const float*)d_in[5];
    const float* bs1    = (const float*)d_in[6];
    const float* Ws2    = (const float*)d_in[7];
    const float* bs2    = (const float*)d_in[8];
    const float* Wt1    = (const float*)d_in[9];
    const float* bt1    = (const float*)d_in[10];
    const float* Wt2    = (const float*)d_in[11];
    const float* bt2    = (const float*)d_in[12];
    const float* W_self = (const float*)d_in[13];
    const float* W_nei  = (const float*)d_in[14];
    const float* b_exp  = (const float*)d_in[15];

    int N = in_sizes[0] / 10;
    int E = in_sizes[1] / 2;
    const int* src = ei;
    const int* dst = ei + E;
    float* out = (float*)d_out;

    float *h, *hs, *part, *sparse, *strug;
    __half *h16, *agg0, *zA, *zB, *agT, *wTh;
    int *deg, *rowptr, *cursor, *colsrc, *ng, *eg;
    cudaGetSymbolAddress((void**)&h,      g_h);
    cudaGetSymbolAddress((void**)&h16,    g_h16);
    cudaGetSymbolAddress((void**)&hs,     g_hs);
    cudaGetSymbolAddress((void**)&agg0,   g_agg0);
    cudaGetSymbolAddress((void**)&zA,     g_zA);
    cudaGetSymbolAddress((void**)&zB,     g_zB);
    cudaGetSymbolAddress((void**)&agT,    g_agT);
    cudaGetSymbolAddress((void**)&part,   g_part);
    cudaGetSymbolAddress((void**)&sparse, g_sparse);
    cudaGetSymbolAddress((void**)&strug,  g_strug);
    cudaGetSymbolAddress((void**)&wTh,    g_wTh);
    cudaGetSymbolAddress((void**)&deg,    g_deg);
    cudaGetSymbolAddress((void**)&rowptr, g_rowptr);
    cudaGetSymbolAddress((void**)&cursor, g_cursor);
    cudaGetSymbolAddress((void**)&colsrc, g_colsrc);
    cudaGetSymbolAddress((void**)&ng,     g_ng);
    cudaGetSymbolAddress((void**)&eg,     g_eg);

    cudaFuncSetAttribute(k_tmma, cudaFuncAttributeMaxDynamicSharedMemorySize, TM_SMEM);

    const size_t ZSZ = (size_t)MAXN * HDIM;

    // ---- prologue on capture stream (0)
    cudaMemsetAsync(ng,  0, NGRAPH * sizeof(int), 0);
    cudaMemsetAsync(eg,  0, NGRAPH * sizeof(int), 0);
    cudaMemsetAsync(deg, 0, (size_t)N * sizeof(int), 0);

    k_pack<<<24 * 256 * 512 / 256, 256>>>(W_self, W_nei, wTh);
    k_hist_nodes<<<128, 256>>>(batch, ng, N);
    k_hist_edges<<<256, 256>>>(batch, src, eg, E);
    k_stru<<<NGRAPH, 256>>>(ng, eg, Wt1, bt1, Wt2, bt2, strug);
    k_encode<<<N, 256>>>(x, W_enc, b_enc, h, h16, N);

    // fork router path onto s[4]
    cudaEventRecord(g_sp.evA, 0);
    cudaStreamWaitEvent(g_sp.s[NSTREAM], g_sp.evA, 0);
    {
        dim3 rgrid((N + BMR - 1) / BMR, HDIM / BNR);
        k_gemm<<<rgrid, 256, 0, g_sp.s[NSTREAM]>>>(h, Ws1, bs1, N, hs);
        k_logits<<<(N + 7) / 8, 256, 0, g_sp.s[NSTREAM]>>>(hs, Ws2, bs2, strug, batch, sparse, N);
        cudaEventRecord(g_sp.evB, g_sp.s[NSTREAM]);
    }

    // meanwhile on stream 0: CSR build + shared layer-0 aggregation (fp16)
    k_deg<<<(E + 255) / 256, 256>>>(dst, deg, E);
    k_scan<<<1, 1024>>>(deg, rowptr, cursor, N);
    k_sortedges<<<(E + 255) / 256, 256>>>(src, dst, cursor, colsrc, E);
    k_agg<<<N, 128>>>((const __half2*)h16, (__half2*)agg0, rowptr, colsrc, N);

    cudaEventRecord(g_sp.fork, 0);

    // ---- 4 parallel expert chains, 2 experts each
    dim3 mgrid((N + 127) / 128, 2);
    for (int i = 0; i < NSTREAM; i++) {
        cudaStream_t st = g_sp.s[i];
        cudaStreamWaitEvent(st, g_sp.fork, 0);
        cudaStreamWaitEvent(st, g_sp.evB, 0);
        __half* zAi = zA + (size_t)i * ZSZ;
        __half* zBi = zB + (size_t)i * ZSZ;
        __half* agi = agT + (size_t)i * ZSZ;
        float*  pti = part + (size_t)i * ZSZ;
        for (int j = 0; j < 2; j++) {
            int e = i * 2 + j;
            const __half* wt0 = wTh + (size_t)(e * 3 + 0) * 256 * 512;
            const __half* wt1 = wTh + (size_t)(e * 3 + 1) * 256 * 512;
            const __half* wt2 = wTh + (size_t)(e * 3 + 2) * 256 * 512;
            const float* b_l0 = b_exp + (size_t)(e * 3 + 0) * HDIM;
            const float* b_l1 = b_exp + (size_t)(e * 3 + 1) * HDIM;
            const float* b_l2 = b_exp + (size_t)(e * 3 + 2) * HDIM;

            k_tmma<<<mgrid, 256, TM_SMEM, st>>>(h16, agg0, wt0, b_l0, N, 1, zAi, nullptr, nullptr, 0, 0);
            k_agg<<<N, 128, 0, st>>>((const __half2*)zAi, (__half2*)agi, rowptr, colsrc, N);
            k_tmma<<<mgrid, 256, TM_SMEM, st>>>(zAi, agi, wt1, b_l1, N, 1, zBi, nullptr, nullptr, 0, 0);
            k_agg<<<N, 128, 0, st>>>((const __half2*)zBi, (__half2*)agi, rowptr, colsrc, N);
            k_tmma<<<mgrid, 256, TM_SMEM, st>>>(zBi, agi, wt2, b_l2, N, 0, nullptr, pti, sparse, e, (j > 0) ? 1 : 0);
        }
        cudaEventRecord(g_sp.join[i], st);
    }

    // ---- join + combine
    for (int i = 0; i < NSTREAM; i++) cudaStreamWaitEvent(0, g_sp.join[i], 0);
    int n4 = N * HDIM / 4;
    k_combine<<<(n4 + 255) / 256, 256>>>(part, part + ZSZ, part + 2 * ZSZ, part + 3 * ZSZ, out, n4);
}

// round 10
// speedup vs baseline: 5.0877x; 1.0291x over previous
#include <cuda_runtime.h>
#include <cuda_fp16.h>
#include <cstdint>
#include <cstddef>

// ---------------------------------------------------------------------------
// GraphMoEDualRouter — GB300 sm_103a.
// Round 8: round-7 pipeline with the k_scan2 width-64 shuffle bug fixed
// (shared-memory scan). Stagger + multi-block scan + fp16 pipeline retained.
// ---------------------------------------------------------------------------

#define HDIM 256
#define NEXP 8
#define NGRAPH 64
#define MAXN 50176
#define MAXE 1600000
#define NSTREAM 4

typedef unsigned long long ull;

// ---- scratch (static device memory; allocation is forbidden) ----
__device__ float  g_h    [MAXN * HDIM];                 // fp32 h (router)
__device__ __half g_h16  [MAXN * HDIM];                 // fp16 h (experts)
__device__ float  g_hs   [MAXN * HDIM];                 // router hidden
__device__ __half g_agg0 [MAXN * HDIM];
__device__ __half g_zA   [NSTREAM][MAXN * HDIM];
__device__ __half g_zB   [NSTREAM][MAXN * HDIM];
__device__ __half g_agT  [NSTREAM][MAXN * HDIM];
__device__ float  g_part [NSTREAM][MAXN * HDIM];
__device__ float  g_sparse[MAXN * NEXP];
__device__ int    g_deg   [MAXN];
__device__ int    g_rowptr[MAXN + 1];
__device__ int    g_cursor[MAXN];
__device__ int    g_colsrc[MAXE];
__device__ int    g_bsum  [64];
__device__ int    g_boff  [64];
__device__ int    g_ng[NGRAPH];
__device__ int    g_eg[NGRAPH];
__device__ float  g_strug[NGRAPH * NEXP];
// packed transposed fp16 weights: [24 mats][256 nrows][512 k]
__device__ __half g_wTh[24 * 256 * 512];

// ---- host-side streams/events (created once, pre-main; host resources only)
struct StreamPool {
    cudaStream_t s[NSTREAM + 1];
    cudaEvent_t evA, evB, fork, join[NSTREAM], stg[2];
    StreamPool() {
        for (int i = 0; i <= NSTREAM; i++)
            cudaStreamCreateWithFlags(&s[i], cudaStreamNonBlocking);
        cudaEventCreateWithFlags(&evA,  cudaEventDisableTiming);
        cudaEventCreateWithFlags(&evB,  cudaEventDisableTiming);
        cudaEventCreateWithFlags(&fork, cudaEventDisableTiming);
        for (int i = 0; i < NSTREAM; i++)
            cudaEventCreateWithFlags(&join[i], cudaEventDisableTiming);
        cudaEventCreateWithFlags(&stg[0], cudaEventDisableTiming);
        cudaEventCreateWithFlags(&stg[1], cudaEventDisableTiming);
    }
};
static StreamPool g_sp;

// ---- helpers ----
__device__ __forceinline__ ull pack2(float lo, float hi) {
    ull r; asm("mov.b64 %0, {%1, %2};" : "=l"(r) : "f"(lo), "f"(hi)); return r;
}
__device__ __forceinline__ void fma2acc(ull& d, ull a, ull b) {
    asm("fma.rn.f32x2 %0, %1, %2, %0;" : "+l"(d) : "l"(a), "l"(b));
}
__device__ __forceinline__ void unpack2(ull v, float& lo, float& hi) {
    asm("mov.b64 {%0, %1}, %2;" : "=f"(lo), "=f"(hi) : "l"(v));
}
__device__ __forceinline__ void mma_f16(float* d, const uint32_t* a, const uint32_t* b) {
    asm volatile(
        "mma.sync.aligned.m16n8k16.row.col.f32.f16.f16.f32 "
        "{%0,%1,%2,%3}, {%4,%5,%6,%7}, {%8,%9}, {%0,%1,%2,%3};"
        : "+f"(d[0]), "+f"(d[1]), "+f"(d[2]), "+f"(d[3])
        : "r"(a[0]), "r"(a[1]), "r"(a[2]), "r"(a[3]), "r"(b[0]), "r"(b[1]));
}
__device__ __forceinline__ uint32_t smem_u32(const void* p) {
    uint32_t a;
    asm("{ .reg .u64 t; cvta.to.shared.u64 t, %1; cvt.u32.u64 %0, t; }" : "=r"(a) : "l"(p));
    return a;
}
__device__ __forceinline__ void cp16(uint32_t dst, const void* src, int sz) {
    asm volatile("cp.async.cg.shared.global [%0], [%1], 16, %2;"
                 :: "r"(dst), "l"(src), "r"(sz) : "memory");
}
__device__ __forceinline__ void cp16u(uint32_t dst, const void* src) {
    asm volatile("cp.async.cg.shared.global [%0], [%1], 16;"
                 :: "r"(dst), "l"(src) : "memory");
}

// ===========================================================================
// Small kernels
// ===========================================================================
__global__ void k_hist_nodes(const int* __restrict__ batch, int* __restrict__ ng, int n) {
    __shared__ int sh[NGRAPH];
    if (threadIdx.x < NGRAPH) sh[threadIdx.x] = 0;
    __syncthreads();
    for (int i = blockIdx.x * blockDim.x + threadIdx.x; i < n; i += gridDim.x * blockDim.x)
        atomicAdd(&sh[batch[i]], 1);
    __syncthreads();
    if (threadIdx.x < NGRAPH) atomicAdd(&ng[threadIdx.x], sh[threadIdx.x]);
}

__global__ void k_hist_edges(const int* __restrict__ batch, const int* __restrict__ src,
                             int* __restrict__ eg, int e) {
    __shared__ int sh[NGRAPH];
    if (threadIdx.x < NGRAPH) sh[threadIdx.x] = 0;
    __syncthreads();
    for (int i = blockIdx.x * blockDim.x + threadIdx.x; i < e; i += gridDim.x * blockDim.x)
        atomicAdd(&sh[batch[src[i]]], 1);
    __syncthreads();
    if (threadIdx.x < NGRAPH) atomicAdd(&eg[threadIdx.x], sh[threadIdx.x]);
}

__global__ void k_stru(const int* __restrict__ ng, const int* __restrict__ eg,
                       const float* __restrict__ Wt1, const float* __restrict__ bt1,
                       const float* __restrict__ Wt2, const float* __restrict__ bt2,
                       float* __restrict__ strug) {
    int g = blockIdx.x;
    float fn = log1pf((float)ng[g]);
    float fe = log1pf((float)eg[g]);
    __shared__ float hid[HDIM];
    int j = threadIdx.x;
    hid[j] = fmaxf(fmaf(fn, Wt1[j], fmaf(fe, Wt1[HDIM + j], bt1[j])), 0.0f);
    __syncthreads();
    int w = threadIdx.x >> 5, lane = threadIdx.x & 31;
    if (w < NEXP) {
        float acc = 0.f;
        for (int k = lane; k < HDIM; k += 32) acc = fmaf(hid[k], Wt2[k * NEXP + w], acc);
        #pragma unroll
        for (int off = 16; off; off >>= 1) acc += __shfl_down_sync(0xffffffffu, acc, off);
        if (lane == 0) strug[g * NEXP + w] = acc + bt2[w];
    }
}

__global__ void k_encode(const float* __restrict__ x, const float* __restrict__ W,
                         const float* __restrict__ b, float* __restrict__ h,
                         __half* __restrict__ h16, int n) {
    int node = blockIdx.x;
    if (node >= n) return;
    __shared__ float xs[6];
    if (threadIdx.x < 6) xs[threadIdx.x] = x[node * 10 + 4 + threadIdx.x];
    __syncthreads();
    int j = threadIdx.x;
    float acc = b[j];
    #pragma unroll
    for (int k = 0; k < 6; k++) acc = fmaf(xs[k], W[k * HDIM + j], acc);
    float v = fmaxf(acc, 0.0f);
    h[(size_t)node * HDIM + j] = v;
    h16[(size_t)node * HDIM + j] = __float2half_rn(v);
}

// ===========================================================================
// FFMA fp32 GEMM — router hidden layer only (top-2 selection needs exactness)
// ===========================================================================
#define BMR 128
#define BNR 64
#define BKR 16

__global__ __launch_bounds__(256) void k_gemm(
    const float* __restrict__ A, const float* __restrict__ W1,
    const float* __restrict__ bias, int n, float* __restrict__ C)
{
    __shared__ __align__(16) float As[BKR][BMR + 2];
    __shared__ __align__(16) float Ws[BKR][BNR];

    int m0 = blockIdx.x * BMR;
    int n0 = blockIdx.y * BNR;
    int tid = threadIdx.x;
    int tm = tid >> 4;
    int tn = tid & 15;

    ull acc2[4][4];
    #pragma unroll
    for (int i = 0; i < 4; i++)
        #pragma unroll
        for (int j = 0; j < 4; j++) acc2[i][j] = 0ull;

    for (int kc = 0; kc < HDIM; kc += BKR) {
        #pragma unroll
        for (int u = 0; u < 2; u++) {
            int idx = tid + u * 256;
            int row = idx >> 2;
            int kq  = idx & 3;
            float4 v = make_float4(0.f, 0.f, 0.f, 0.f);
            int gr = m0 + row;
            if (gr < n) v = *(const float4*)(A + (size_t)gr * HDIM + kc + kq * 4);
            As[kq * 4 + 0][row] = v.x;
            As[kq * 4 + 1][row] = v.y;
            As[kq * 4 + 2][row] = v.z;
            As[kq * 4 + 3][row] = v.w;
        }
        {
            int kk = tid >> 4, nq = tid & 15;
            float4 w = *(const float4*)(W1 + (size_t)(kc + kk) * HDIM + n0 + nq * 4);
            *(float4*)&Ws[kk][nq * 4] = w;
        }
        __syncthreads();
        #pragma unroll
        for (int kk = 0; kk < BKR; kk++) {
            ull a2[4];
            #pragma unroll
            for (int i2 = 0; i2 < 4; i2++)
                a2[i2] = *(const ull*)&As[kk][tm * 8 + i2 * 2];
            #pragma unroll
            for (int j = 0; j < 4; j++) {
                float bb = Ws[kk][tn * 4 + j];
                ull b2 = pack2(bb, bb);
                #pragma unroll
                for (int i2 = 0; i2 < 4; i2++) fma2acc(acc2[i2][j], a2[i2], b2);
            }
        }
        __syncthreads();
    }

    float4 bb4 = *(const float4*)&bias[n0 + tn * 4];
    #pragma unroll
    for (int i2 = 0; i2 < 4; i2++) {
        float4 vlo, vhi;
        unpack2(acc2[i2][0], vlo.x, vhi.x);
        unpack2(acc2[i2][1], vlo.y, vhi.y);
        unpack2(acc2[i2][2], vlo.z, vhi.z);
        unpack2(acc2[i2][3], vlo.w, vhi.w);
        #pragma unroll
        for (int rr = 0; rr < 2; rr++) {
            int row = m0 + tm * 8 + i2 * 2 + rr;
            if (row >= n) continue;
            float4 v = rr ? vhi : vlo;
            v.x = fmaxf(v.x + bb4.x, 0.f); v.y = fmaxf(v.y + bb4.y, 0.f);
            v.z = fmaxf(v.z + bb4.z, 0.f); v.w = fmaxf(v.w + bb4.w, 0.f);
            *(float4*)(C + (size_t)row * HDIM + n0 + tn * 4) = v;
        }
    }
}

// ===========================================================================
// Router logits + top-2 sparse gates
// ===========================================================================
__global__ void k_logits(const float* __restrict__ hs, const float* __restrict__ Ws2,
                         const float* __restrict__ bs2, const float* __restrict__ strug,
                         const int* __restrict__ batch, float* __restrict__ sparse, int n) {
    int warp = (blockIdx.x * blockDim.x + threadIdx.x) >> 5;
    int lane = threadIdx.x & 31;
    if (warp >= n) return;
    const float* row = hs + (size_t)warp * HDIM;
    float acc[NEXP];
    #pragma unroll
    for (int o = 0; o < NEXP; o++) acc[o] = 0.f;
    for (int k = lane; k < HDIM; k += 32) {
        float v = row[k];
        const float* w2 = Ws2 + k * NEXP;
        #pragma unroll
        for (int o = 0; o < NEXP; o++) acc[o] = fmaf(v, w2[o], acc[o]);
    }
    #pragma unroll
    for (int o = 0; o < NEXP; o++)
        #pragma unroll
        for (int off = 16; off; off >>= 1) acc[o] += __shfl_down_sync(0xffffffffu, acc[o], off);
    if (lane == 0) {
        int g = batch[warp];
        float lg[NEXP];
        #pragma unroll
        for (int o = 0; o < NEXP; o++)
            lg[o] = 0.5f * (acc[o] + bs2[o]) + 0.5f * strug[g * NEXP + o];
        float m1 = -3.4e38f; int i1 = 0;
        #pragma unroll
        for (int o = 0; o < NEXP; o++) if (lg[o] > m1) { m1 = lg[o]; i1 = o; }
        float m2 = -3.4e38f; int i2 = 0;
        #pragma unroll
        for (int o = 0; o < NEXP; o++) if (o != i1 && lg[o] > m2) { m2 = lg[o]; i2 = o; }
        float e2 = __expf(m2 - m1);
        float inv = 1.0f / (1.0f + e2);
        float* srow = sparse + (size_t)warp * NEXP;
        #pragma unroll
        for (int o = 0; o < NEXP; o++) srow[o] = 0.f;
        srow[i1] = inv;
        srow[i2] = e2 * inv;
    }
}

// ===========================================================================
// CSR build: counting sort by dst with 3-phase multi-block scan
// ===========================================================================
__global__ void k_deg(const int* __restrict__ dst, int* __restrict__ deg, int e) {
    int i = blockIdx.x * blockDim.x + threadIdx.x;
    if (i < e) atomicAdd(&deg[dst[i]], 1);
}

// per-block inclusive scan of deg; writes partial scan + block total
__global__ void k_scan1(const int* __restrict__ deg, int* __restrict__ rowptr,
                        int* __restrict__ bsum, int n) {
    __shared__ int sh[1024];
    int i = blockIdx.x * 1024 + threadIdx.x;
    int v = (i < n) ? deg[i] : 0;
    sh[threadIdx.x] = v;
    __syncthreads();
    #pragma unroll
    for (int off = 1; off < 1024; off <<= 1) {
        int t = (threadIdx.x >= (unsigned)off) ? sh[threadIdx.x - off] : 0;
        __syncthreads();
        sh[threadIdx.x] += t;
        __syncthreads();
    }
    if (i < n) rowptr[i + 1] = sh[threadIdx.x];
    if (threadIdx.x == 1023) bsum[blockIdx.x] = sh[1023];
}

// exclusive scan of block sums (<=64 blocks) — shared-memory Hillis-Steele
// (round 7 used __shfl_up_sync width=64, which is illegal; this is the fix)
__global__ void k_scan2(const int* __restrict__ bsum, int* __restrict__ boff, int nb) {
    __shared__ int sh[64];
    int i = threadIdx.x;
    int orig = (i < nb) ? bsum[i] : 0;
    sh[i] = orig;
    __syncthreads();
    #pragma unroll
    for (int off = 1; off < 64; off <<= 1) {
        int t = (i >= off) ? sh[i - off] : 0;
        __syncthreads();
        sh[i] += t;
        __syncthreads();
    }
    if (i < nb) boff[i] = sh[i] - orig;     // exclusive prefix
}

// add block offsets; produce cursor & rowptr[0]
__global__ void k_scan3(const int* __restrict__ deg, int* __restrict__ rowptr,
                        const int* __restrict__ boff, int* __restrict__ cursor, int n) {
    int i = blockIdx.x * 1024 + threadIdx.x;
    if (i == 0) rowptr[0] = 0;
    if (i < n) {
        int inc = rowptr[i + 1] + boff[blockIdx.x];
        rowptr[i + 1] = inc;
        cursor[i] = inc - deg[i];
    }
}

__global__ void k_sortedges(const int* __restrict__ src, const int* __restrict__ dst,
                            int* __restrict__ cursor, int* __restrict__ colsrc, int e) {
    int i = blockIdx.x * blockDim.x + threadIdx.x;
    if (i < e) {
        int d = dst[i];
        int p = atomicAdd(&cursor[d], 1);
        colsrc[p] = src[i];
    }
}

// ===========================================================================
// fp16 CSR gather aggregation (fp32 accum)
// ===========================================================================
__global__ __launch_bounds__(128) void k_agg(const __half2* __restrict__ z,
                                             __half2* __restrict__ agg,
                                             const int* __restrict__ rowptr,
                                             const int* __restrict__ colsrc, int n) {
    int node = blockIdx.x;
    if (node >= n) return;
    int c = threadIdx.x;
    int s0 = rowptr[node], s1 = rowptr[node + 1];
    float2 a0 = make_float2(0.f, 0.f), a1 = make_float2(0.f, 0.f);
    float2 a2 = make_float2(0.f, 0.f), a3 = make_float2(0.f, 0.f);
    int i = s0;
    for (; i + 3 < s1; i += 4) {
        int sA = colsrc[i], sB = colsrc[i + 1], sC = colsrc[i + 2], sD = colsrc[i + 3];
        float2 vA = __half22float2(z[(size_t)sA * 128 + c]);
        float2 vB = __half22float2(z[(size_t)sB * 128 + c]);
        float2 vC = __half22float2(z[(size_t)sC * 128 + c]);
        float2 vD = __half22float2(z[(size_t)sD * 128 + c]);
        a0.x += vA.x; a0.y += vA.y;
        a1.x += vB.x; a1.y += vB.y;
        a2.x += vC.x; a2.y += vC.y;
        a3.x += vD.x; a3.y += vD.y;
    }
    for (; i < s1; i++) {
        float2 v = __half22float2(z[(size_t)colsrc[i] * 128 + c]);
        a0.x += v.x; a0.y += v.y;
    }
    float rx = (a0.x + a1.x) + (a2.x + a3.x);
    float ry = (a0.y + a1.y) + (a2.y + a3.y);
    agg[(size_t)node * 128 + c] = __floats2half2_rn(rx, ry);
}

// ===========================================================================
// Weight pack
// ===========================================================================
__global__ void k_pack(const float* __restrict__ Wself, const float* __restrict__ Wnei,
                       __half* __restrict__ wTh) {
    int idx = blockIdx.x * 256 + threadIdx.x;
    int k = idx & 511;
    int rem = idx >> 9;
    int nrow = rem & 255;
    int mat = rem >> 8;
    const float* srcp = (k < 256) ? Wself : Wnei;
    int kk = k & 255;
    wTh[idx] = __float2half_rn(srcp[((size_t)mat * 256 + kk) * 256 + nrow]);
}

// ===========================================================================
// Final combine
// ===========================================================================
__global__ void k_combine(const float* __restrict__ p0, const float* __restrict__ p1,
                          const float* __restrict__ p2, const float* __restrict__ p3,
                          float* __restrict__ out, int n4) {
    int i = blockIdx.x * blockDim.x + threadIdx.x;
    if (i >= n4) return;
    float4 a = ((const float4*)p0)[i];
    float4 b = ((const float4*)p1)[i];
    float4 c = ((const float4*)p2)[i];
    float4 d = ((const float4*)p3)[i];
    float4 o;
    o.x = (a.x + b.x) + (c.x + d.x);
    o.y = (a.y + b.y) + (c.y + d.y);
    o.z = (a.z + b.z) + (c.z + d.z);
    o.w = (a.w + b.w) + (c.w + d.w);
    ((float4*)out)[i] = o;
}

// ===========================================================================
// fp16 mma.sync dual GEMM (unchanged from round 6)
// ===========================================================================
#define PADH 72
#define HBUF (128 * PADH)
#define TM_SMEM (4 * HBUF * 2)

__global__ __launch_bounds__(256, 2) void k_tmma(
    const __half* __restrict__ Az, const __half* __restrict__ Ag,
    const __half* __restrict__ WTh, const float* __restrict__ bias,
    int n, int relu, __half* __restrict__ Ch, float* __restrict__ Cf,
    const float* __restrict__ sparse, int expert, int accum)
{
    extern __shared__ __half smh[];
    uint32_t sbase = smem_u32(smh);

    int tid = threadIdx.x;
    int warp = tid >> 5, lane = tid & 31;
    int m0 = blockIdx.x * 128;
    int n0 = blockIdx.y * 128;
    int m_off = (warp >> 1) * 32;
    int n_off = (warp & 1) * 64;
    int g = lane >> 2, t = lane & 3;

    float acc[2][8][4];
    #pragma unroll
    for (int i = 0; i < 2; i++)
        #pragma unroll
        for (int j = 0; j < 8; j++)
            #pragma unroll
            for (int r = 0; r < 4; r++) acc[i][j][r] = 0.f;

    auto issue_chunk = [&](int c, int buf) {
        const __half* Asrc = (c < 4) ? Az : Ag;
        int kb = (c & 3) * 64;
        uint32_t abase = sbase + (uint32_t)buf * (HBUF * 2);
        uint32_t bbase = sbase + (uint32_t)(2 + buf) * (HBUF * 2);
        #pragma unroll
        for (int i = 0; i < 4; i++) {
            int idx = tid + i * 256;
            int row = idx >> 3, q = idx & 7;
            int gr = m0 + row;
            int grc = (gr < n) ? gr : 0;
            cp16(abase + (uint32_t)(row * (PADH * 2) + q * 16),
                 Asrc + (size_t)grc * HDIM + kb + q * 8,
                 (gr < n) ? 16 : 0);
            cp16u(bbase + (uint32_t)(row * (PADH * 2) + q * 16),
                  WTh + (size_t)(n0 + row) * 512 + c * 64 + q * 8);
        }
        asm volatile("cp.async.commit_group;" ::: "memory");
    };

    issue_chunk(0, 0);

    for (int c = 0; c < 8; c++) {
        int buf = c & 1;
        if (c < 7) {
            issue_chunk(c + 1, buf ^ 1);
            asm volatile("cp.async.wait_group 1;" ::: "memory");
        } else {
            asm volatile("cp.async.wait_group 0;" ::: "memory");
        }
        __syncthreads();

        const __half* ab = smh + (size_t)buf * HBUF + m_off * PADH;
        const __half* bb = smh + (size_t)(2 + buf) * HBUF + n_off * PADH;
        #pragma unroll
        for (int ks = 0; ks < 4; ks++) {
            int k0 = ks * 16;
            uint32_t af[2][4], bf[8][2];
            #pragma unroll
            for (int i = 0; i < 2; i++) {
                const __half* ap = ab + (i * 16 + g) * PADH + k0 + 2 * t;
                af[i][0] = *(const uint32_t*)(ap);
                af[i][1] = *(const uint32_t*)(ap + 8 * PADH);
                af[i][2] = *(const uint32_t*)(ap + 8);
                af[i][3] = *(const uint32_t*)(ap + 8 * PADH + 8);
            }
            #pragma unroll
            for (int j = 0; j < 8; j++) {
                const __half* bp = bb + (j * 8 + g) * PADH + k0 + 2 * t;
                bf[j][0] = *(const uint32_t*)(bp);
                bf[j][1] = *(const uint32_t*)(bp + 8);
            }
            #pragma unroll
            for (int i = 0; i < 2; i++)
                #pragma unroll
                for (int j = 0; j < 8; j++)
                    mma_f16(acc[i][j], af[i], bf[j]);
        }
        __syncthreads();
    }

    // ---- epilogue ----
    #pragma unroll
    for (int i = 0; i < 2; i++) {
        int r0 = m0 + m_off + i * 16 + g;
        int r1 = r0 + 8;
        float s0 = 0.f, s1 = 0.f;
        if (Cf != nullptr) {
            if (r0 < n) s0 = sparse[(size_t)r0 * NEXP + expert];
            if (r1 < n) s1 = sparse[(size_t)r1 * NEXP + expert];
        }
        #pragma unroll
        for (int j = 0; j < 8; j++) {
            int col = n0 + n_off + j * 8 + 2 * t;
            float2 bb2 = *(const float2*)(bias + col);
            float2 v0, v1;
            v0.x = acc[i][j][0] + bb2.x; v0.y = acc[i][j][1] + bb2.y;
            v1.x = acc[i][j][2] + bb2.x; v1.y = acc[i][j][3] + bb2.y;
            if (relu) {
                v0.x = fmaxf(v0.x, 0.f); v0.y = fmaxf(v0.y, 0.f);
                v1.x = fmaxf(v1.x, 0.f); v1.y = fmaxf(v1.y, 0.f);
            }
            if (Cf != nullptr) {
                if (r0 < n) {
                    float2* op = (float2*)(Cf + (size_t)r0 * HDIM + col);
                    float2 o = accum ? *op : make_float2(0.f, 0.f);
                    o.x = fmaf(s0, v0.x, o.x); o.y = fmaf(s0, v0.y, o.y);
                    *op = o;
                }
                if (r1 < n) {
                    float2* op = (float2*)(Cf + (size_t)r1 * HDIM + col);
                    float2 o = accum ? *op : make_float2(0.f, 0.f);
                    o.x = fmaf(s1, v1.x, o.x); o.y = fmaf(s1, v1.y, o.y);
                    *op = o;
                }
            } else {
                if (r0 < n) *(__half2*)(Ch + (size_t)r0 * HDIM + col) = __floats2half2_rn(v0.x, v0.y);
                if (r1 < n) *(__half2*)(Ch + (size_t)r1 * HDIM + col) = __floats2half2_rn(v1.x, v1.y);
            }
        }
    }
}

// ===========================================================================
// host launch
// ===========================================================================
extern "C" void kernel_launch(void* const* d_in, const int* in_sizes, int n_in,
                              void* d_out, int out_size) {
    const float* x      = (const float*)d_in[0];
    const int*   ei     = (const int*)  d_in[1];
    const int*   batch  = (const int*)  d_in[2];
    const float* W_enc  = (const float*)d_in[3];
    const float* b_enc  = (const float*)d_in[4];
    const float* Ws1    = (const float*)d_in[5];
    const float* bs1    = (const float*)d_in[6];
    const float* Ws2    = (const float*)d_in[7];
    const float* bs2    = (const float*)d_in[8];
    const float* Wt1    = (const float*)d_in[9];
    const float* bt1    = (const float*)d_in[10];
    const float* Wt2    = (const float*)d_in[11];
    const float* bt2    = (const float*)d_in[12];
    const float* W_self = (const float*)d_in[13];
    const float* W_nei  = (const float*)d_in[14];
    const float* b_exp  = (const float*)d_in[15];

    int N = in_sizes[0] / 10;
    int E = in_sizes[1] / 2;
    const int* src = ei;
    const int* dst = ei + E;
    float* out = (float*)d_out;

    float *h, *hs, *part, *sparse, *strug;
    __half *h16, *agg0, *zA, *zB, *agT, *wTh;
    int *deg, *rowptr, *cursor, *colsrc, *ng, *eg, *bsum, *boff;
    cudaGetSymbolAddress((void**)&h,      g_h);
    cudaGetSymbolAddress((void**)&h16,    g_h16);
    cudaGetSymbolAddress((void**)&hs,     g_hs);
    cudaGetSymbolAddress((void**)&agg0,   g_agg0);
    cudaGetSymbolAddress((void**)&zA,     g_zA);
    cudaGetSymbolAddress((void**)&zB,     g_zB);
    cudaGetSymbolAddress((void**)&agT,    g_agT);
    cudaGetSymbolAddress((void**)&part,   g_part);
    cudaGetSymbolAddress((void**)&sparse, g_sparse);
    cudaGetSymbolAddress((void**)&strug,  g_strug);
    cudaGetSymbolAddress((void**)&wTh,    g_wTh);
    cudaGetSymbolAddress((void**)&deg,    g_deg);
    cudaGetSymbolAddress((void**)&rowptr, g_rowptr);
    cudaGetSymbolAddress((void**)&cursor, g_cursor);
    cudaGetSymbolAddress((void**)&colsrc, g_colsrc);
    cudaGetSymbolAddress((void**)&ng,     g_ng);
    cudaGetSymbolAddress((void**)&eg,     g_eg);
    cudaGetSymbolAddress((void**)&bsum,   g_bsum);
    cudaGetSymbolAddress((void**)&boff,   g_boff);

    cudaFuncSetAttribute(k_tmma, cudaFuncAttributeMaxDynamicSharedMemorySize, TM_SMEM);

    const size_t ZSZ = (size_t)MAXN * HDIM;
    int nsb = (N + 1023) / 1024;

    // ---- prologue on capture stream (0)
    cudaMemsetAsync(ng,  0, NGRAPH * sizeof(int), 0);
    cudaMemsetAsync(eg,  0, NGRAPH * sizeof(int), 0);
    cudaMemsetAsync(deg, 0, (size_t)N * sizeof(int), 0);

    k_pack<<<24 * 256 * 512 / 256, 256>>>(W_self, W_nei, wTh);
    k_hist_nodes<<<128, 256>>>(batch, ng, N);
    k_hist_edges<<<256, 256>>>(batch, src, eg, E);
    k_stru<<<NGRAPH, 256>>>(ng, eg, Wt1, bt1, Wt2, bt2, strug);
    k_encode<<<N, 256>>>(x, W_enc, b_enc, h, h16, N);

    // fork router path onto s[4]
    cudaEventRecord(g_sp.evA, 0);
    cudaStreamWaitEvent(g_sp.s[NSTREAM], g_sp.evA, 0);
    {
        dim3 rgrid((N + BMR - 1) / BMR, HDIM / BNR);
        k_gemm<<<rgrid, 256, 0, g_sp.s[NSTREAM]>>>(h, Ws1, bs1, N, hs);
        k_logits<<<(N + 7) / 8, 256, 0, g_sp.s[NSTREAM]>>>(hs, Ws2, bs2, strug, batch, sparse, N);
        cudaEventRecord(g_sp.evB, g_sp.s[NSTREAM]);
    }

    // meanwhile on stream 0: CSR build (multi-block scan) + layer-0 agg
    k_deg<<<(E + 255) / 256, 256>>>(dst, deg, E);
    k_scan1<<<nsb, 1024>>>(deg, rowptr, bsum, N);
    k_scan2<<<1, 64>>>(bsum, boff, nsb);
    k_scan3<<<nsb, 1024>>>(deg, rowptr, boff, cursor, N);
    k_sortedges<<<(E + 255) / 256, 256>>>(src, dst, cursor, colsrc, E);
    k_agg<<<N, 128>>>((const __half2*)h16, (__half2*)agg0, rowptr, colsrc, N);

    cudaEventRecord(g_sp.fork, 0);

    // ---- 4 parallel expert chains, 2 experts each; streams 2,3 staggered
    // one stage behind streams 0,1 so GEMM (compute) overlaps agg (LTS).
    dim3 mgrid((N + 127) / 128, 2);
    for (int i = 0; i < NSTREAM; i++) {
        cudaStream_t st = g_sp.s[i];
        cudaStreamWaitEvent(st, g_sp.fork, 0);
        cudaStreamWaitEvent(st, g_sp.evB, 0);
        if (i >= 2) cudaStreamWaitEvent(st, g_sp.stg[i - 2], 0);   // stagger
        __half* zAi = zA + (size_t)i * ZSZ;
        __half* zBi = zB + (size_t)i * ZSZ;
        __half* agi = agT + (size_t)i * ZSZ;
        float*  pti = part + (size_t)i * ZSZ;
        for (int j = 0; j < 2; j++) {
            int e = i * 2 + j;
            const __half* wt0 = wTh + (size_t)(e * 3 + 0) * 256 * 512;
            const __half* wt1 = wTh + (size_t)(e * 3 + 1) * 256 * 512;
            const __half* wt2 = wTh + (size_t)(e * 3 + 2) * 256 * 512;
            const float* b_l0 = b_exp + (size_t)(e * 3 + 0) * HDIM;
            const float* b_l1 = b_exp + (size_t)(e * 3 + 1) * HDIM;
            const float* b_l2 = b_exp + (size_t)(e * 3 + 2) * HDIM;

            k_tmma<<<mgrid, 256, TM_SMEM, st>>>(h16, agg0, wt0, b_l0, N, 1, zAi, nullptr, nullptr, 0, 0);
            if (j == 0 && i < 2) cudaEventRecord(g_sp.stg[i], st);  // after 1st GEMM
            k_agg<<<N, 128, 0, st>>>((const __half2*)zAi, (__half2*)agi, rowptr, colsrc, N);
            k_tmma<<<mgrid, 256, TM_SMEM, st>>>(zAi, agi, wt1, b_l1, N, 1, zBi, nullptr, nullptr, 0, 0);
            k_agg<<<N, 128, 0, st>>>((const __half2*)zBi, (__half2*)agi, rowptr, colsrc, N);
            k_tmma<<<mgrid, 256, TM_SMEM, st>>>(zBi, agi, wt2, b_l2, N, 0, nullptr, pti, sparse, e, (j > 0) ? 1 : 0);
        }
        cudaEventRecord(g_sp.join[i], st);
    }

    // ---- join + combine
    for (int i = 0; i < NSTREAM; i++) cudaStreamWaitEvent(0, g_sp.join[i], 0);
    int n4 = N * HDIM / 4;
    k_combine<<<(n4 + 255) / 256, 256>>>(part, part + ZSZ, part + 2 * ZSZ, part + 3 * ZSZ, out, n4);
}

// round 11
// speedup vs baseline: 6.4831x; 1.2743x over previous
#include <cuda_runtime.h>
#include <cuda_fp16.h>
#include <cstdint>
#include <cstddef>

// ---------------------------------------------------------------------------
// GraphMoEDualRouter — GB300 sm_103a.
// Round 10: top-2 sparsity exploited — final-layer GEMM and second agg per
// expert run only over that expert's gated nodes (~N/4), via compacted index
// lists with fixed grids (early-exit CTAs). fp16 pipeline otherwise unchanged.
// ---------------------------------------------------------------------------

#define HDIM 256
#define NEXP 8
#define NGRAPH 64
#define MAXN 50176
#define MAXE 1600000
#define NSTREAM 4

typedef unsigned long long ull;

// ---- scratch (static device memory; allocation is forbidden) ----
__device__ float  g_h    [MAXN * HDIM];                 // fp32 h (router)
__device__ __half g_h16  [MAXN * HDIM];                 // fp16 h (experts)
__device__ float  g_hs   [MAXN * HDIM];                 // router hidden
__device__ __half g_agg0 [MAXN * HDIM];
__device__ __half g_zA   [NSTREAM][MAXN * HDIM];
__device__ __half g_zB   [NSTREAM][MAXN * HDIM];
__device__ __half g_agT  [NSTREAM][MAXN * HDIM];
__device__ float  g_part [NSTREAM][MAXN * HDIM];
__device__ float  g_sparse[MAXN * NEXP];
__device__ int    g_xidx  [NEXP][MAXN];                 // per-expert gated nodes
__device__ int    g_xcnt  [NEXP];
__device__ int    g_deg   [MAXN];
__device__ int    g_rowptr[MAXN + 1];
__device__ int    g_cursor[MAXN];
__device__ int    g_colsrc[MAXE];
__device__ int    g_bsum  [64];
__device__ int    g_boff  [64];
__device__ int    g_ng[NGRAPH];
__device__ int    g_eg[NGRAPH];
__device__ float  g_strug[NGRAPH * NEXP];
// packed transposed fp16 weights: [24 mats][256 nrows][512 k]
__device__ __half g_wTh[24 * 256 * 512];

// ---- host-side streams/events (created once, pre-main; host resources only)
struct StreamPool {
    cudaStream_t s[NSTREAM + 1];
    cudaEvent_t evA, evB, fork, join[NSTREAM], stg[2];
    StreamPool() {
        for (int i = 0; i <= NSTREAM; i++)
            cudaStreamCreateWithFlags(&s[i], cudaStreamNonBlocking);
        cudaEventCreateWithFlags(&evA,  cudaEventDisableTiming);
        cudaEventCreateWithFlags(&evB,  cudaEventDisableTiming);
        cudaEventCreateWithFlags(&fork, cudaEventDisableTiming);
        for (int i = 0; i < NSTREAM; i++)
            cudaEventCreateWithFlags(&join[i], cudaEventDisableTiming);
        cudaEventCreateWithFlags(&stg[0], cudaEventDisableTiming);
        cudaEventCreateWithFlags(&stg[1], cudaEventDisableTiming);
    }
};
static StreamPool g_sp;

// ---- helpers ----
__device__ __forceinline__ ull pack2(float lo, float hi) {
    ull r; asm("mov.b64 %0, {%1, %2};" : "=l"(r) : "f"(lo), "f"(hi)); return r;
}
__device__ __forceinline__ void fma2acc(ull& d, ull a, ull b) {
    asm("fma.rn.f32x2 %0, %1, %2, %0;" : "+l"(d) : "l"(a), "l"(b));
}
__device__ __forceinline__ void unpack2(ull v, float& lo, float& hi) {
    asm("mov.b64 {%0, %1}, %2;" : "=f"(lo), "=f"(hi) : "l"(v));
}
__device__ __forceinline__ void mma_f16(float* d, const uint32_t* a, const uint32_t* b) {
    asm volatile(
        "mma.sync.aligned.m16n8k16.row.col.f32.f16.f16.f32 "
        "{%0,%1,%2,%3}, {%4,%5,%6,%7}, {%8,%9}, {%0,%1,%2,%3};"
        : "+f"(d[0]), "+f"(d[1]), "+f"(d[2]), "+f"(d[3])
        : "r"(a[0]), "r"(a[1]), "r"(a[2]), "r"(a[3]), "r"(b[0]), "r"(b[1]));
}
__device__ __forceinline__ uint32_t smem_u32(const void* p) {
    uint32_t a;
    asm("{ .reg .u64 t; cvta.to.shared.u64 t, %1; cvt.u32.u64 %0, t; }" : "=r"(a) : "l"(p));
    return a;
}
__device__ __forceinline__ void cp16(uint32_t dst, const void* src, int sz) {
    asm volatile("cp.async.cg.shared.global [%0], [%1], 16, %2;"
                 :: "r"(dst), "l"(src), "r"(sz) : "memory");
}
__device__ __forceinline__ void cp16u(uint32_t dst, const void* src) {
    asm volatile("cp.async.cg.shared.global [%0], [%1], 16;"
                 :: "r"(dst), "l"(src) : "memory");
}

// ===========================================================================
// Small kernels
// ===========================================================================
__global__ void k_hist_nodes(const int* __restrict__ batch, int* __restrict__ ng, int n) {
    __shared__ int sh[NGRAPH];
    if (threadIdx.x < NGRAPH) sh[threadIdx.x] = 0;
    __syncthreads();
    for (int i = blockIdx.x * blockDim.x + threadIdx.x; i < n; i += gridDim.x * blockDim.x)
        atomicAdd(&sh[batch[i]], 1);
    __syncthreads();
    if (threadIdx.x < NGRAPH) atomicAdd(&ng[threadIdx.x], sh[threadIdx.x]);
}

__global__ void k_hist_edges(const int* __restrict__ batch, const int* __restrict__ src,
                             int* __restrict__ eg, int e) {
    __shared__ int sh[NGRAPH];
    if (threadIdx.x < NGRAPH) sh[threadIdx.x] = 0;
    __syncthreads();
    for (int i = blockIdx.x * blockDim.x + threadIdx.x; i < e; i += gridDim.x * blockDim.x)
        atomicAdd(&sh[batch[src[i]]], 1);
    __syncthreads();
    if (threadIdx.x < NGRAPH) atomicAdd(&eg[threadIdx.x], sh[threadIdx.x]);
}

__global__ void k_stru(const int* __restrict__ ng, const int* __restrict__ eg,
                       const float* __restrict__ Wt1, const float* __restrict__ bt1,
                       const float* __restrict__ Wt2, const float* __restrict__ bt2,
                       float* __restrict__ strug) {
    int g = blockIdx.x;
    float fn = log1pf((float)ng[g]);
    float fe = log1pf((float)eg[g]);
    __shared__ float hid[HDIM];
    int j = threadIdx.x;
    hid[j] = fmaxf(fmaf(fn, Wt1[j], fmaf(fe, Wt1[HDIM + j], bt1[j])), 0.0f);
    __syncthreads();
    int w = threadIdx.x >> 5, lane = threadIdx.x & 31;
    if (w < NEXP) {
        float acc = 0.f;
        for (int k = lane; k < HDIM; k += 32) acc = fmaf(hid[k], Wt2[k * NEXP + w], acc);
        #pragma unroll
        for (int off = 16; off; off >>= 1) acc += __shfl_down_sync(0xffffffffu, acc, off);
        if (lane == 0) strug[g * NEXP + w] = acc + bt2[w];
    }
}

__global__ void k_encode(const float* __restrict__ x, const float* __restrict__ W,
                         const float* __restrict__ b, float* __restrict__ h,
                         __half* __restrict__ h16, int n) {
    int node = blockIdx.x;
    if (node >= n) return;
    __shared__ float xs[6];
    if (threadIdx.x < 6) xs[threadIdx.x] = x[node * 10 + 4 + threadIdx.x];
    __syncthreads();
    int j = threadIdx.x;
    float acc = b[j];
    #pragma unroll
    for (int k = 0; k < 6; k++) acc = fmaf(xs[k], W[k * HDIM + j], acc);
    float v = fmaxf(acc, 0.0f);
    h[(size_t)node * HDIM + j] = v;
    h16[(size_t)node * HDIM + j] = __float2half_rn(v);
}

// ===========================================================================
// FFMA fp32 GEMM — router hidden layer only (top-2 selection needs exactness)
// ===========================================================================
#define BMR 128
#define BNR 64
#define BKR 16

__global__ __launch_bounds__(256) void k_gemm(
    const float* __restrict__ A, const float* __restrict__ W1,
    const float* __restrict__ bias, int n, float* __restrict__ C)
{
    __shared__ __align__(16) float As[BKR][BMR + 2];
    __shared__ __align__(16) float Ws[BKR][BNR];

    int m0 = blockIdx.x * BMR;
    int n0 = blockIdx.y * BNR;
    int tid = threadIdx.x;
    int tm = tid >> 4;
    int tn = tid & 15;

    ull acc2[4][4];
    #pragma unroll
    for (int i = 0; i < 4; i++)
        #pragma unroll
        for (int j = 0; j < 4; j++) acc2[i][j] = 0ull;

    for (int kc = 0; kc < HDIM; kc += BKR) {
        #pragma unroll
        for (int u = 0; u < 2; u++) {
            int idx = tid + u * 256;
            int row = idx >> 2;
            int kq  = idx & 3;
            float4 v = make_float4(0.f, 0.f, 0.f, 0.f);
            int gr = m0 + row;
            if (gr < n) v = *(const float4*)(A + (size_t)gr * HDIM + kc + kq * 4);
            As[kq * 4 + 0][row] = v.x;
            As[kq * 4 + 1][row] = v.y;
            As[kq * 4 + 2][row] = v.z;
            As[kq * 4 + 3][row] = v.w;
        }
        {
            int kk = tid >> 4, nq = tid & 15;
            float4 w = *(const float4*)(W1 + (size_t)(kc + kk) * HDIM + n0 + nq * 4);
            *(float4*)&Ws[kk][nq * 4] = w;
        }
        __syncthreads();
        #pragma unroll
        for (int kk = 0; kk < BKR; kk++) {
            ull a2[4];
            #pragma unroll
            for (int i2 = 0; i2 < 4; i2++)
                a2[i2] = *(const ull*)&As[kk][tm * 8 + i2 * 2];
            #pragma unroll
            for (int j = 0; j < 4; j++) {
                float bb = Ws[kk][tn * 4 + j];
                ull b2 = pack2(bb, bb);
                #pragma unroll
                for (int i2 = 0; i2 < 4; i2++) fma2acc(acc2[i2][j], a2[i2], b2);
            }
        }
        __syncthreads();
    }

    float4 bb4 = *(const float4*)&bias[n0 + tn * 4];
    #pragma unroll
    for (int i2 = 0; i2 < 4; i2++) {
        float4 vlo, vhi;
        unpack2(acc2[i2][0], vlo.x, vhi.x);
        unpack2(acc2[i2][1], vlo.y, vhi.y);
        unpack2(acc2[i2][2], vlo.z, vhi.z);
        unpack2(acc2[i2][3], vlo.w, vhi.w);
        #pragma unroll
        for (int rr = 0; rr < 2; rr++) {
            int row = m0 + tm * 8 + i2 * 2 + rr;
            if (row >= n) continue;
            float4 v = rr ? vhi : vlo;
            v.x = fmaxf(v.x + bb4.x, 0.f); v.y = fmaxf(v.y + bb4.y, 0.f);
            v.z = fmaxf(v.z + bb4.z, 0.f); v.w = fmaxf(v.w + bb4.w, 0.f);
            *(float4*)(C + (size_t)row * HDIM + n0 + tn * 4) = v;
        }
    }
}

// ===========================================================================
// Router logits + top-2 sparse gates + per-expert compacted node lists
// ===========================================================================
__global__ void k_logits(const float* __restrict__ hs, const float* __restrict__ Ws2,
                         const float* __restrict__ bs2, const float* __restrict__ strug,
                         const int* __restrict__ batch, float* __restrict__ sparse,
                         int* __restrict__ xidx, int* __restrict__ xcnt, int n) {
    int warp = (blockIdx.x * blockDim.x + threadIdx.x) >> 5;
    int lane = threadIdx.x & 31;
    if (warp >= n) return;
    const float* row = hs + (size_t)warp * HDIM;
    float acc[NEXP];
    #pragma unroll
    for (int o = 0; o < NEXP; o++) acc[o] = 0.f;
    for (int k = lane; k < HDIM; k += 32) {
        float v = row[k];
        const float* w2 = Ws2 + k * NEXP;
        #pragma unroll
        for (int o = 0; o < NEXP; o++) acc[o] = fmaf(v, w2[o], acc[o]);
    }
    #pragma unroll
    for (int o = 0; o < NEXP; o++)
        #pragma unroll
        for (int off = 16; off; off >>= 1) acc[o] += __shfl_down_sync(0xffffffffu, acc[o], off);
    if (lane == 0) {
        int g = batch[warp];
        float lg[NEXP];
        #pragma unroll
        for (int o = 0; o < NEXP; o++)
            lg[o] = 0.5f * (acc[o] + bs2[o]) + 0.5f * strug[g * NEXP + o];
        float m1 = -3.4e38f; int i1 = 0;
        #pragma unroll
        for (int o = 0; o < NEXP; o++) if (lg[o] > m1) { m1 = lg[o]; i1 = o; }
        float m2 = -3.4e38f; int i2 = 0;
        #pragma unroll
        for (int o = 0; o < NEXP; o++) if (o != i1 && lg[o] > m2) { m2 = lg[o]; i2 = o; }
        float e2 = __expf(m2 - m1);
        float inv = 1.0f / (1.0f + e2);
        float* srow = sparse + (size_t)warp * NEXP;
        #pragma unroll
        for (int o = 0; o < NEXP; o++) srow[o] = 0.f;
        srow[i1] = inv;
        srow[i2] = e2 * inv;
        int p1 = atomicAdd(&xcnt[i1], 1);
        xidx[i1 * MAXN + p1] = warp;
        int p2 = atomicAdd(&xcnt[i2], 1);
        xidx[i2 * MAXN + p2] = warp;
    }
}

// ===========================================================================
// CSR build: counting sort by dst with 3-phase multi-block scan
// ===========================================================================
__global__ void k_deg(const int* __restrict__ dst, int* __restrict__ deg, int e) {
    int i = blockIdx.x * blockDim.x + threadIdx.x;
    if (i < e) atomicAdd(&deg[dst[i]], 1);
}

__global__ void k_scan1(const int* __restrict__ deg, int* __restrict__ rowptr,
                        int* __restrict__ bsum, int n) {
    __shared__ int sh[1024];
    int i = blockIdx.x * 1024 + threadIdx.x;
    int v = (i < n) ? deg[i] : 0;
    sh[threadIdx.x] = v;
    __syncthreads();
    #pragma unroll
    for (int off = 1; off < 1024; off <<= 1) {
        int t = (threadIdx.x >= (unsigned)off) ? sh[threadIdx.x - off] : 0;
        __syncthreads();
        sh[threadIdx.x] += t;
        __syncthreads();
    }
    if (i < n) rowptr[i + 1] = sh[threadIdx.x];
    if (threadIdx.x == 1023) bsum[blockIdx.x] = sh[1023];
}

__global__ void k_scan2(const int* __restrict__ bsum, int* __restrict__ boff, int nb) {
    __shared__ int sh[64];
    int i = threadIdx.x;
    int orig = (i < nb) ? bsum[i] : 0;
    sh[i] = orig;
    __syncthreads();
    #pragma unroll
    for (int off = 1; off < 64; off <<= 1) {
        int t = (i >= off) ? sh[i - off] : 0;
        __syncthreads();
        sh[i] += t;
        __syncthreads();
    }
    if (i < nb) boff[i] = sh[i] - orig;
}

__global__ void k_scan3(const int* __restrict__ deg, int* __restrict__ rowptr,
                        const int* __restrict__ boff, int* __restrict__ cursor, int n) {
    int i = blockIdx.x * 1024 + threadIdx.x;
    if (i == 0) rowptr[0] = 0;
    if (i < n) {
        int inc = rowptr[i + 1] + boff[blockIdx.x];
        rowptr[i + 1] = inc;
        cursor[i] = inc - deg[i];
    }
}

__global__ void k_sortedges(const int* __restrict__ src, const int* __restrict__ dst,
                            int* __restrict__ cursor, int* __restrict__ colsrc, int e) {
    int i = blockIdx.x * blockDim.x + threadIdx.x;
    if (i < e) {
        int d = dst[i];
        int p = atomicAdd(&cursor[d], 1);
        colsrc[p] = src[i];
    }
}

// ===========================================================================
// fp16 CSR gather aggregation (fp32 accum); optional compacted node list
// ===========================================================================
__global__ __launch_bounds__(128) void k_agg(const __half2* __restrict__ z,
                                             __half2* __restrict__ agg,
                                             const int* __restrict__ rowptr,
                                             const int* __restrict__ colsrc, int n,
                                             const int* __restrict__ ridx,
                                             const int* __restrict__ cntp) {
    int b = blockIdx.x;
    int node;
    if (ridx != nullptr) {
        if (b >= *cntp) return;
        node = ridx[b];
    } else {
        if (b >= n) return;
        node = b;
    }
    int c = threadIdx.x;
    int s0 = rowptr[node], s1 = rowptr[node + 1];
    float2 a0 = make_float2(0.f, 0.f), a1 = make_float2(0.f, 0.f);
    float2 a2 = make_float2(0.f, 0.f), a3 = make_float2(0.f, 0.f);
    int i = s0;
    for (; i + 3 < s1; i += 4) {
        int sA = colsrc[i], sB = colsrc[i + 1], sC = colsrc[i + 2], sD = colsrc[i + 3];
        float2 vA = __half22float2(z[(size_t)sA * 128 + c]);
        float2 vB = __half22float2(z[(size_t)sB * 128 + c]);
        float2 vC = __half22float2(z[(size_t)sC * 128 + c]);
        float2 vD = __half22float2(z[(size_t)sD * 128 + c]);
        a0.x += vA.x; a0.y += vA.y;
        a1.x += vB.x; a1.y += vB.y;
        a2.x += vC.x; a2.y += vC.y;
        a3.x += vD.x; a3.y += vD.y;
    }
    for (; i < s1; i++) {
        float2 v = __half22float2(z[(size_t)colsrc[i] * 128 + c]);
        a0.x += v.x; a0.y += v.y;
    }
    float rx = (a0.x + a1.x) + (a2.x + a3.x);
    float ry = (a0.y + a1.y) + (a2.y + a3.y);
    agg[(size_t)node * 128 + c] = __floats2half2_rn(rx, ry);
}

// ===========================================================================
// Weight pack
// ===========================================================================
__global__ void k_pack(const float* __restrict__ Wself, const float* __restrict__ Wnei,
                       __half* __restrict__ wTh) {
    int idx = blockIdx.x * 256 + threadIdx.x;
    int k = idx & 511;
    int rem = idx >> 9;
    int nrow = rem & 255;
    int mat = rem >> 8;
    const float* srcp = (k < 256) ? Wself : Wnei;
    int kk = k & 255;
    wTh[idx] = __float2half_rn(srcp[((size_t)mat * 256 + kk) * 256 + nrow]);
}

// ===========================================================================
// Final combine
// ===========================================================================
__global__ void k_combine(const float* __restrict__ p0, const float* __restrict__ p1,
                          const float* __restrict__ p2, const float* __restrict__ p3,
                          float* __restrict__ out, int n4) {
    int i = blockIdx.x * blockDim.x + threadIdx.x;
    if (i >= n4) return;
    float4 a = ((const float4*)p0)[i];
    float4 b = ((const float4*)p1)[i];
    float4 c = ((const float4*)p2)[i];
    float4 d = ((const float4*)p3)[i];
    float4 o;
    o.x = (a.x + b.x) + (c.x + d.x);
    o.y = (a.y + b.y) + (c.y + d.y);
    o.z = (a.z + b.z) + (c.z + d.z);
    o.w = (a.w + b.w) + (c.w + d.w);
    ((float4*)out)[i] = o;
}

// ===========================================================================
// fp16 mma.sync dual GEMM; optional compacted row list (ridx/cntp)
// ===========================================================================
#define PADH 72
#define HBUF (128 * PADH)
#define TM_SMEM (4 * HBUF * 2)

__global__ __launch_bounds__(256, 2) void k_tmma(
    const __half* __restrict__ Az, const __half* __restrict__ Ag,
    const __half* __restrict__ WTh, const float* __restrict__ bias,
    int n, int relu, __half* __restrict__ Ch, float* __restrict__ Cf,
    const float* __restrict__ sparse, int expert, int accum,
    const int* __restrict__ ridx, const int* __restrict__ cntp)
{
    extern __shared__ __half smh[];
    __shared__ int rid_s[128];
    uint32_t sbase = smem_u32(smh);

    int tid = threadIdx.x;
    int warp = tid >> 5, lane = tid & 31;
    int m0 = blockIdx.x * 128;
    int n0 = blockIdx.y * 128;
    int m_off = (warp >> 1) * 32;
    int n_off = (warp & 1) * 64;
    int g = lane >> 2, t = lane & 3;

    int mrows = (cntp != nullptr) ? *cntp : n;
    if (m0 >= mrows) return;

    // stage row->node map for this tile
    if (tid < 128) {
        int gr = m0 + tid;
        rid_s[tid] = (gr < mrows) ? ((ridx != nullptr) ? ridx[gr] : gr) : 0;
    }
    __syncthreads();

    float acc[2][8][4];
    #pragma unroll
    for (int i = 0; i < 2; i++)
        #pragma unroll
        for (int j = 0; j < 8; j++)
            #pragma unroll
            for (int r = 0; r < 4; r++) acc[i][j][r] = 0.f;

    auto issue_chunk = [&](int c, int buf) {
        const __half* Asrc = (c < 4) ? Az : Ag;
        int kb = (c & 3) * 64;
        uint32_t abase = sbase + (uint32_t)buf * (HBUF * 2);
        uint32_t bbase = sbase + (uint32_t)(2 + buf) * (HBUF * 2);
        #pragma unroll
        for (int i = 0; i < 4; i++) {
            int idx = tid + i * 256;
            int row = idx >> 3, q = idx & 7;
            int gr = m0 + row;
            int node = rid_s[row];
            cp16(abase + (uint32_t)(row * (PADH * 2) + q * 16),
                 Asrc + (size_t)node * HDIM + kb + q * 8,
                 (gr < mrows) ? 16 : 0);
            cp16u(bbase + (uint32_t)(row * (PADH * 2) + q * 16),
                  WTh + (size_t)(n0 + row) * 512 + c * 64 + q * 8);
        }
        asm volatile("cp.async.commit_group;" ::: "memory");
    };

    issue_chunk(0, 0);

    for (int c = 0; c < 8; c++) {
        int buf = c & 1;
        if (c < 7) {
            issue_chunk(c + 1, buf ^ 1);
            asm volatile("cp.async.wait_group 1;" ::: "memory");
        } else {
            asm volatile("cp.async.wait_group 0;" ::: "memory");
        }
        __syncthreads();

        const __half* ab = smh + (size_t)buf * HBUF + m_off * PADH;
        const __half* bb = smh + (size_t)(2 + buf) * HBUF + n_off * PADH;
        #pragma unroll
        for (int ks = 0; ks < 4; ks++) {
            int k0 = ks * 16;
            uint32_t af[2][4], bf[8][2];
            #pragma unroll
            for (int i = 0; i < 2; i++) {
                const __half* ap = ab + (i * 16 + g) * PADH + k0 + 2 * t;
                af[i][0] = *(const uint32_t*)(ap);
                af[i][1] = *(const uint32_t*)(ap + 8 * PADH);
                af[i][2] = *(const uint32_t*)(ap + 8);
                af[i][3] = *(const uint32_t*)(ap + 8 * PADH + 8);
            }
            #pragma unroll
            for (int j = 0; j < 8; j++) {
                const __half* bp = bb + (j * 8 + g) * PADH + k0 + 2 * t;
                bf[j][0] = *(const uint32_t*)(bp);
                bf[j][1] = *(const uint32_t*)(bp + 8);
            }
            #pragma unroll
            for (int i = 0; i < 2; i++)
                #pragma unroll
                for (int j = 0; j < 8; j++)
                    mma_f16(acc[i][j], af[i], bf[j]);
        }
        __syncthreads();
    }

    // ---- epilogue ----
    #pragma unroll
    for (int i = 0; i < 2; i++) {
        int l0 = m_off + i * 16 + g;          // logical row in tile
        int l1 = l0 + 8;
        bool v0r = (m0 + l0) < mrows;
        bool v1r = (m0 + l1) < mrows;
        int node0 = rid_s[l0];
        int node1 = rid_s[l1];
        float s0 = 0.f, s1 = 0.f;
        if (Cf != nullptr) {
            if (v0r) s0 = sparse[(size_t)node0 * NEXP + expert];
            if (v1r) s1 = sparse[(size_t)node1 * NEXP + expert];
        }
        #pragma unroll
        for (int j = 0; j < 8; j++) {
            int col = n0 + n_off + j * 8 + 2 * t;
            float2 bb2 = *(const float2*)(bias + col);
            float2 v0, v1;
            v0.x = acc[i][j][0] + bb2.x; v0.y = acc[i][j][1] + bb2.y;
            v1.x = acc[i][j][2] + bb2.x; v1.y = acc[i][j][3] + bb2.y;
            if (relu) {
                v0.x = fmaxf(v0.x, 0.f); v0.y = fmaxf(v0.y, 0.f);
                v1.x = fmaxf(v1.x, 0.f); v1.y = fmaxf(v1.y, 0.f);
            }
            if (Cf != nullptr) {
                if (v0r) {
                    float2* op = (float2*)(Cf + (size_t)node0 * HDIM + col);
                    float2 o = accum ? *op : make_float2(0.f, 0.f);
                    o.x = fmaf(s0, v0.x, o.x); o.y = fmaf(s0, v0.y, o.y);
                    *op = o;
                }
                if (v1r) {
                    float2* op = (float2*)(Cf + (size_t)node1 * HDIM + col);
                    float2 o = accum ? *op : make_float2(0.f, 0.f);
                    o.x = fmaf(s1, v1.x, o.x); o.y = fmaf(s1, v1.y, o.y);
                    *op = o;
                }
            } else {
                if (v0r) *(__half2*)(Ch + (size_t)node0 * HDIM + col) = __floats2half2_rn(v0.x, v0.y);
                if (v1r) *(__half2*)(Ch + (size_t)node1 * HDIM + col) = __floats2half2_rn(v1.x, v1.y);
            }
        }
    }
}

// ===========================================================================
// host launch
// ===========================================================================
extern "C" void kernel_launch(void* const* d_in, const int* in_sizes, int n_in,
                              void* d_out, int out_size) {
    const float* x      = (const float*)d_in[0];
    const int*   ei     = (const int*)  d_in[1];
    const int*   batch  = (const int*)  d_in[2];
    const float* W_enc  = (const float*)d_in[3];
    const float* b_enc  = (const float*)d_in[4];
    const float* Ws1    = (const float*)d_in[5];
    const float* bs1    = (const float*)d_in[6];
    const float* Ws2    = (const float*)d_in[7];
    const float* bs2    = (const float*)d_in[8];
    const float* Wt1    = (const float*)d_in[9];
    const float* bt1    = (const float*)d_in[10];
    const float* Wt2    = (const float*)d_in[11];
    const float* bt2    = (const float*)d_in[12];
    const float* W_self = (const float*)d_in[13];
    const float* W_nei  = (const float*)d_in[14];
    const float* b_exp  = (const float*)d_in[15];

    int N = in_sizes[0] / 10;
    int E = in_sizes[1] / 2;
    const int* src = ei;
    const int* dst = ei + E;
    float* out = (float*)d_out;

    float *h, *hs, *part, *sparse, *strug;
    __half *h16, *agg0, *zA, *zB, *agT, *wTh;
    int *deg, *rowptr, *cursor, *colsrc, *ng, *eg, *bsum, *boff, *xidx, *xcnt;
    cudaGetSymbolAddress((void**)&h,      g_h);
    cudaGetSymbolAddress((void**)&h16,    g_h16);
    cudaGetSymbolAddress((void**)&hs,     g_hs);
    cudaGetSymbolAddress((void**)&agg0,   g_agg0);
    cudaGetSymbolAddress((void**)&zA,     g_zA);
    cudaGetSymbolAddress((void**)&zB,     g_zB);
    cudaGetSymbolAddress((void**)&agT,    g_agT);
    cudaGetSymbolAddress((void**)&part,   g_part);
    cudaGetSymbolAddress((void**)&sparse, g_sparse);
    cudaGetSymbolAddress((void**)&strug,  g_strug);
    cudaGetSymbolAddress((void**)&wTh,    g_wTh);
    cudaGetSymbolAddress((void**)&deg,    g_deg);
    cudaGetSymbolAddress((void**)&rowptr, g_rowptr);
    cudaGetSymbolAddress((void**)&cursor, g_cursor);
    cudaGetSymbolAddress((void**)&colsrc, g_colsrc);
    cudaGetSymbolAddress((void**)&ng,     g_ng);
    cudaGetSymbolAddress((void**)&eg,     g_eg);
    cudaGetSymbolAddress((void**)&bsum,   g_bsum);
    cudaGetSymbolAddress((void**)&boff,   g_boff);
    cudaGetSymbolAddress((void**)&xidx,   g_xidx);
    cudaGetSymbolAddress((void**)&xcnt,   g_xcnt);

    cudaFuncSetAttribute(k_tmma, cudaFuncAttributeMaxDynamicSharedMemorySize, TM_SMEM);

    const size_t ZSZ = (size_t)MAXN * HDIM;
    int nsb = (N + 1023) / 1024;

    // ---- prologue on capture stream (0)
    cudaMemsetAsync(ng,   0, NGRAPH * sizeof(int), 0);
    cudaMemsetAsync(eg,   0, NGRAPH * sizeof(int), 0);
    cudaMemsetAsync(deg,  0, (size_t)N * sizeof(int), 0);
    cudaMemsetAsync(xcnt, 0, NEXP * sizeof(int), 0);

    k_pack<<<24 * 256 * 512 / 256, 256>>>(W_self, W_nei, wTh);
    k_hist_nodes<<<128, 256>>>(batch, ng, N);
    k_hist_edges<<<256, 256>>>(batch, src, eg, E);
    k_stru<<<NGRAPH, 256>>>(ng, eg, Wt1, bt1, Wt2, bt2, strug);
    k_encode<<<N, 256>>>(x, W_enc, b_enc, h, h16, N);

    // fork router path onto s[4]
    cudaEventRecord(g_sp.evA, 0);
    cudaStreamWaitEvent(g_sp.s[NSTREAM], g_sp.evA, 0);
    {
        dim3 rgrid((N + BMR - 1) / BMR, HDIM / BNR);
        k_gemm<<<rgrid, 256, 0, g_sp.s[NSTREAM]>>>(h, Ws1, bs1, N, hs);
        k_logits<<<(N + 7) / 8, 256, 0, g_sp.s[NSTREAM]>>>(hs, Ws2, bs2, strug, batch,
                                                           sparse, xidx, xcnt, N);
        cudaEventRecord(g_sp.evB, g_sp.s[NSTREAM]);
    }

    // meanwhile on stream 0: CSR build + layer-0 agg
    k_deg<<<(E + 255) / 256, 256>>>(dst, deg, E);
    k_scan1<<<nsb, 1024>>>(deg, rowptr, bsum, N);
    k_scan2<<<1, 64>>>(bsum, boff, nsb);
    k_scan3<<<nsb, 1024>>>(deg, rowptr, boff, cursor, N);
    k_sortedges<<<(E + 255) / 256, 256>>>(src, dst, cursor, colsrc, E);
    k_agg<<<N, 128>>>((const __half2*)h16, (__half2*)agg0, rowptr, colsrc, N, nullptr, nullptr);

    cudaEventRecord(g_sp.fork, 0);

    // ---- 4 parallel expert chains, 2 experts each; streams 2,3 staggered
    dim3 mgrid((N + 127) / 128, 2);
    for (int i = 0; i < NSTREAM; i++) {
        cudaStream_t st = g_sp.s[i];
        cudaStreamWaitEvent(st, g_sp.fork, 0);
        cudaStreamWaitEvent(st, g_sp.evB, 0);
        if (i >= 2) cudaStreamWaitEvent(st, g_sp.stg[i - 2], 0);
        __half* zAi = zA + (size_t)i * ZSZ;
        __half* zBi = zB + (size_t)i * ZSZ;
        __half* agi = agT + (size_t)i * ZSZ;
        float*  pti = part + (size_t)i * ZSZ;
        cudaMemsetAsync(pti, 0, ZSZ * sizeof(float), st);   // gated accumulation base
        for (int j = 0; j < 2; j++) {
            int e = i * 2 + j;
            const __half* wt0 = wTh + (size_t)(e * 3 + 0) * 256 * 512;
            const __half* wt1 = wTh + (size_t)(e * 3 + 1) * 256 * 512;
            const __half* wt2 = wTh + (size_t)(e * 3 + 2) * 256 * 512;
            const float* b_l0 = b_exp + (size_t)(e * 3 + 0) * HDIM;
            const float* b_l1 = b_exp + (size_t)(e * 3 + 1) * HDIM;
            const float* b_l2 = b_exp + (size_t)(e * 3 + 2) * HDIM;
            const int* ri = xidx + (size_t)e * MAXN;
            const int* ct = xcnt + e;

            // dense layers 0,1 (all nodes — needed by graph aggregation)
            k_tmma<<<mgrid, 256, TM_SMEM, st>>>(h16, agg0, wt0, b_l0, N, 1, zAi, nullptr,
                                                nullptr, 0, 0, nullptr, nullptr);
            if (j == 0 && i < 2) cudaEventRecord(g_sp.stg[i], st);
            k_agg<<<N, 128, 0, st>>>((const __half2*)zAi, (__half2*)agi, rowptr, colsrc, N,
                                     nullptr, nullptr);
            k_tmma<<<mgrid, 256, TM_SMEM, st>>>(zAi, agi, wt1, b_l1, N, 1, zBi, nullptr,
                                                nullptr, 0, 0, nullptr, nullptr);
            // sparse: second agg + final gated GEMM only over gated nodes
            k_agg<<<N, 128, 0, st>>>((const __half2*)zBi, (__half2*)agi, rowptr, colsrc, N,
                                     ri, ct);
            k_tmma<<<mgrid, 256, TM_SMEM, st>>>(zBi, agi, wt2, b_l2, N, 0, nullptr, pti,
                                                sparse, e, 1, ri, ct);
        }
        cudaEventRecord(g_sp.join[i], st);
    }

    // ---- join + combine
    for (int i = 0; i < NSTREAM; i++) cudaStreamWaitEvent(0, g_sp.join[i], 0);
    int n4 = N * HDIM / 4;
    k_combine<<<(n4 + 255) / 256, 256>>>(part, part + ZSZ, part + 2 * ZSZ, part + 3 * ZSZ, out, n4);
}

// round 12
// speedup vs baseline: 6.7414x; 1.0398x over previous
#include <cuda_runtime.h>
#include <cuda_fp16.h>
#include <cstdint>
#include <cstddef>

// ---------------------------------------------------------------------------
// GraphMoEDualRouter — GB300 sm_103a.
// Round 11: k_tmma fragment loads via ldmatrix.x4 (4x fewer shared-load
// instrs, bit-identical fragments); k_pack moved off the critical prologue.
// Sparse final layer + fp16 pipeline from round 10 unchanged.
// ---------------------------------------------------------------------------

#define HDIM 256
#define NEXP 8
#define NGRAPH 64
#define MAXN 50176
#define MAXE 1600000
#define NSTREAM 4

typedef unsigned long long ull;

// ---- scratch (static device memory; allocation is forbidden) ----
__device__ float  g_h    [MAXN * HDIM];                 // fp32 h (router)
__device__ __half g_h16  [MAXN * HDIM];                 // fp16 h (experts)
__device__ float  g_hs   [MAXN * HDIM];                 // router hidden
__device__ __half g_agg0 [MAXN * HDIM];
__device__ __half g_zA   [NSTREAM][MAXN * HDIM];
__device__ __half g_zB   [NSTREAM][MAXN * HDIM];
__device__ __half g_agT  [NSTREAM][MAXN * HDIM];
__device__ float  g_part [NSTREAM][MAXN * HDIM];
__device__ float  g_sparse[MAXN * NEXP];
__device__ int    g_xidx  [NEXP][MAXN];                 // per-expert gated nodes
__device__ int    g_xcnt  [NEXP];
__device__ int    g_deg   [MAXN];
__device__ int    g_rowptr[MAXN + 1];
__device__ int    g_cursor[MAXN];
__device__ int    g_colsrc[MAXE];
__device__ int    g_bsum  [64];
__device__ int    g_boff  [64];
__device__ int    g_ng[NGRAPH];
__device__ int    g_eg[NGRAPH];
__device__ float  g_strug[NGRAPH * NEXP];
// packed transposed fp16 weights: [24 mats][256 nrows][512 k]
__device__ __half g_wTh[24 * 256 * 512];

// ---- host-side streams/events (created once, pre-main; host resources only)
struct StreamPool {
    cudaStream_t s[NSTREAM + 1];
    cudaEvent_t evA, evB, fork, join[NSTREAM], stg[2];
    StreamPool() {
        for (int i = 0; i <= NSTREAM; i++)
            cudaStreamCreateWithFlags(&s[i], cudaStreamNonBlocking);
        cudaEventCreateWithFlags(&evA,  cudaEventDisableTiming);
        cudaEventCreateWithFlags(&evB,  cudaEventDisableTiming);
        cudaEventCreateWithFlags(&fork, cudaEventDisableTiming);
        for (int i = 0; i < NSTREAM; i++)
            cudaEventCreateWithFlags(&join[i], cudaEventDisableTiming);
        cudaEventCreateWithFlags(&stg[0], cudaEventDisableTiming);
        cudaEventCreateWithFlags(&stg[1], cudaEventDisableTiming);
    }
};
static StreamPool g_sp;

// ---- helpers ----
__device__ __forceinline__ ull pack2(float lo, float hi) {
    ull r; asm("mov.b64 %0, {%1, %2};" : "=l"(r) : "f"(lo), "f"(hi)); return r;
}
__device__ __forceinline__ void fma2acc(ull& d, ull a, ull b) {
    asm("fma.rn.f32x2 %0, %1, %2, %0;" : "+l"(d) : "l"(a), "l"(b));
}
__device__ __forceinline__ void unpack2(ull v, float& lo, float& hi) {
    asm("mov.b64 {%0, %1}, %2;" : "=f"(lo), "=f"(hi) : "l"(v));
}
__device__ __forceinline__ void mma_f16(float* d, const uint32_t* a, const uint32_t* b) {
    asm volatile(
        "mma.sync.aligned.m16n8k16.row.col.f32.f16.f16.f32 "
        "{%0,%1,%2,%3}, {%4,%5,%6,%7}, {%8,%9}, {%0,%1,%2,%3};"
        : "+f"(d[0]), "+f"(d[1]), "+f"(d[2]), "+f"(d[3])
        : "r"(a[0]), "r"(a[1]), "r"(a[2]), "r"(a[3]), "r"(b[0]), "r"(b[1]));
}
__device__ __forceinline__ void ldsm_x4(uint32_t& r0, uint32_t& r1,
                                        uint32_t& r2, uint32_t& r3, uint32_t addr) {
    asm volatile("ldmatrix.sync.aligned.m8n8.x4.shared.b16 {%0,%1,%2,%3}, [%4];"
        : "=r"(r0), "=r"(r1), "=r"(r2), "=r"(r3) : "r"(addr));
}
__device__ __forceinline__ uint32_t smem_u32(const void* p) {
    uint32_t a;
    asm("{ .reg .u64 t; cvta.to.shared.u64 t, %1; cvt.u32.u64 %0, t; }" : "=r"(a) : "l"(p));
    return a;
}
__device__ __forceinline__ void cp16(uint32_t dst, const void* src, int sz) {
    asm volatile("cp.async.cg.shared.global [%0], [%1], 16, %2;"
                 :: "r"(dst), "l"(src), "r"(sz) : "memory");
}
__device__ __forceinline__ void cp16u(uint32_t dst, const void* src) {
    asm volatile("cp.async.cg.shared.global [%0], [%1], 16;"
                 :: "r"(dst), "l"(src) : "memory");
}

// ===========================================================================
// Small kernels
// ===========================================================================
__global__ void k_hist_nodes(const int* __restrict__ batch, int* __restrict__ ng, int n) {
    __shared__ int sh[NGRAPH];
    if (threadIdx.x < NGRAPH) sh[threadIdx.x] = 0;
    __syncthreads();
    for (int i = blockIdx.x * blockDim.x + threadIdx.x; i < n; i += gridDim.x * blockDim.x)
        atomicAdd(&sh[batch[i]], 1);
    __syncthreads();
    if (threadIdx.x < NGRAPH) atomicAdd(&ng[threadIdx.x], sh[threadIdx.x]);
}

__global__ void k_hist_edges(const int* __restrict__ batch, const int* __restrict__ src,
                             int* __restrict__ eg, int e) {
    __shared__ int sh[NGRAPH];
    if (threadIdx.x < NGRAPH) sh[threadIdx.x] = 0;
    __syncthreads();
    for (int i = blockIdx.x * blockDim.x + threadIdx.x; i < e; i += gridDim.x * blockDim.x)
        atomicAdd(&sh[batch[src[i]]], 1);
    __syncthreads();
    if (threadIdx.x < NGRAPH) atomicAdd(&eg[threadIdx.x], sh[threadIdx.x]);
}

__global__ void k_stru(const int* __restrict__ ng, const int* __restrict__ eg,
                       const float* __restrict__ Wt1, const float* __restrict__ bt1,
                       const float* __restrict__ Wt2, const float* __restrict__ bt2,
                       float* __restrict__ strug) {
    int g = blockIdx.x;
    float fn = log1pf((float)ng[g]);
    float fe = log1pf((float)eg[g]);
    __shared__ float hid[HDIM];
    int j = threadIdx.x;
    hid[j] = fmaxf(fmaf(fn, Wt1[j], fmaf(fe, Wt1[HDIM + j], bt1[j])), 0.0f);
    __syncthreads();
    int w = threadIdx.x >> 5, lane = threadIdx.x & 31;
    if (w < NEXP) {
        float acc = 0.f;
        for (int k = lane; k < HDIM; k += 32) acc = fmaf(hid[k], Wt2[k * NEXP + w], acc);
        #pragma unroll
        for (int off = 16; off; off >>= 1) acc += __shfl_down_sync(0xffffffffu, acc, off);
        if (lane == 0) strug[g * NEXP + w] = acc + bt2[w];
    }
}

__global__ void k_encode(const float* __restrict__ x, const float* __restrict__ W,
                         const float* __restrict__ b, float* __restrict__ h,
                         __half* __restrict__ h16, int n) {
    int node = blockIdx.x;
    if (node >= n) return;
    __shared__ float xs[6];
    if (threadIdx.x < 6) xs[threadIdx.x] = x[node * 10 + 4 + threadIdx.x];
    __syncthreads();
    int j = threadIdx.x;
    float acc = b[j];
    #pragma unroll
    for (int k = 0; k < 6; k++) acc = fmaf(xs[k], W[k * HDIM + j], acc);
    float v = fmaxf(acc, 0.0f);
    h[(size_t)node * HDIM + j] = v;
    h16[(size_t)node * HDIM + j] = __float2half_rn(v);
}

// ===========================================================================
// FFMA fp32 GEMM — router hidden layer only (top-2 selection needs exactness)
// ===========================================================================
#define BMR 128
#define BNR 64
#define BKR 16

__global__ __launch_bounds__(256) void k_gemm(
    const float* __restrict__ A, const float* __restrict__ W1,
    const float* __restrict__ bias, int n, float* __restrict__ C)
{
    __shared__ __align__(16) float As[BKR][BMR + 2];
    __shared__ __align__(16) float Ws[BKR][BNR];

    int m0 = blockIdx.x * BMR;
    int n0 = blockIdx.y * BNR;
    int tid = threadIdx.x;
    int tm = tid >> 4;
    int tn = tid & 15;

    ull acc2[4][4];
    #pragma unroll
    for (int i = 0; i < 4; i++)
        #pragma unroll
        for (int j = 0; j < 4; j++) acc2[i][j] = 0ull;

    for (int kc = 0; kc < HDIM; kc += BKR) {
        #pragma unroll
        for (int u = 0; u < 2; u++) {
            int idx = tid + u * 256;
            int row = idx >> 2;
            int kq  = idx & 3;
            float4 v = make_float4(0.f, 0.f, 0.f, 0.f);
            int gr = m0 + row;
            if (gr < n) v = *(const float4*)(A + (size_t)gr * HDIM + kc + kq * 4);
            As[kq * 4 + 0][row] = v.x;
            As[kq * 4 + 1][row] = v.y;
            As[kq * 4 + 2][row] = v.z;
            As[kq * 4 + 3][row] = v.w;
        }
        {
            int kk = tid >> 4, nq = tid & 15;
            float4 w = *(const float4*)(W1 + (size_t)(kc + kk) * HDIM + n0 + nq * 4);
            *(float4*)&Ws[kk][nq * 4] = w;
        }
        __syncthreads();
        #pragma unroll
        for (int kk = 0; kk < BKR; kk++) {
            ull a2[4];
            #pragma unroll
            for (int i2 = 0; i2 < 4; i2++)
                a2[i2] = *(const ull*)&As[kk][tm * 8 + i2 * 2];
            #pragma unroll
            for (int j = 0; j < 4; j++) {
                float bb = Ws[kk][tn * 4 + j];
                ull b2 = pack2(bb, bb);
                #pragma unroll
                for (int i2 = 0; i2 < 4; i2++) fma2acc(acc2[i2][j], a2[i2], b2);
            }
        }
        __syncthreads();
    }

    float4 bb4 = *(const float4*)&bias[n0 + tn * 4];
    #pragma unroll
    for (int i2 = 0; i2 < 4; i2++) {
        float4 vlo, vhi;
        unpack2(acc2[i2][0], vlo.x, vhi.x);
        unpack2(acc2[i2][1], vlo.y, vhi.y);
        unpack2(acc2[i2][2], vlo.z, vhi.z);
        unpack2(acc2[i2][3], vlo.w, vhi.w);
        #pragma unroll
        for (int rr = 0; rr < 2; rr++) {
            int row = m0 + tm * 8 + i2 * 2 + rr;
            if (row >= n) continue;
            float4 v = rr ? vhi : vlo;
            v.x = fmaxf(v.x + bb4.x, 0.f); v.y = fmaxf(v.y + bb4.y, 0.f);
            v.z = fmaxf(v.z + bb4.z, 0.f); v.w = fmaxf(v.w + bb4.w, 0.f);
            *(float4*)(C + (size_t)row * HDIM + n0 + tn * 4) = v;
        }
    }
}

// ===========================================================================
// Router logits + top-2 sparse gates + per-expert compacted node lists
// ===========================================================================
__global__ void k_logits(const float* __restrict__ hs, const float* __restrict__ Ws2,
                         const float* __restrict__ bs2, const float* __restrict__ strug,
                         const int* __restrict__ batch, float* __restrict__ sparse,
                         int* __restrict__ xidx, int* __restrict__ xcnt, int n) {
    int warp = (blockIdx.x * blockDim.x + threadIdx.x) >> 5;
    int lane = threadIdx.x & 31;
    if (warp >= n) return;
    const float* row = hs + (size_t)warp * HDIM;
    float acc[NEXP];
    #pragma unroll
    for (int o = 0; o < NEXP; o++) acc[o] = 0.f;
    for (int k = lane; k < HDIM; k += 32) {
        float v = row[k];
        const float* w2 = Ws2 + k * NEXP;
        #pragma unroll
        for (int o = 0; o < NEXP; o++) acc[o] = fmaf(v, w2[o], acc[o]);
    }
    #pragma unroll
    for (int o = 0; o < NEXP; o++)
        #pragma unroll
        for (int off = 16; off; off >>= 1) acc[o] += __shfl_down_sync(0xffffffffu, acc[o], off);
    if (lane == 0) {
        int g = batch[warp];
        float lg[NEXP];
        #pragma unroll
        for (int o = 0; o < NEXP; o++)
            lg[o] = 0.5f * (acc[o] + bs2[o]) + 0.5f * strug[g * NEXP + o];
        float m1 = -3.4e38f; int i1 = 0;
        #pragma unroll
        for (int o = 0; o < NEXP; o++) if (lg[o] > m1) { m1 = lg[o]; i1 = o; }
        float m2 = -3.4e38f; int i2 = 0;
        #pragma unroll
        for (int o = 0; o < NEXP; o++) if (o != i1 && lg[o] > m2) { m2 = lg[o]; i2 = o; }
        float e2 = __expf(m2 - m1);
        float inv = 1.0f / (1.0f + e2);
        float* srow = sparse + (size_t)warp * NEXP;
        #pragma unroll
        for (int o = 0; o < NEXP; o++) srow[o] = 0.f;
        srow[i1] = inv;
        srow[i2] = e2 * inv;
        int p1 = atomicAdd(&xcnt[i1], 1);
        xidx[i1 * MAXN + p1] = warp;
        int p2 = atomicAdd(&xcnt[i2], 1);
        xidx[i2 * MAXN + p2] = warp;
    }
}

// ===========================================================================
// CSR build: counting sort by dst with 3-phase multi-block scan
// ===========================================================================
__global__ void k_deg(const int* __restrict__ dst, int* __restrict__ deg, int e) {
    int i = blockIdx.x * blockDim.x + threadIdx.x;
    if (i < e) atomicAdd(&deg[dst[i]], 1);
}

__global__ void k_scan1(const int* __restrict__ deg, int* __restrict__ rowptr,
                        int* __restrict__ bsum, int n) {
    __shared__ int sh[1024];
    int i = blockIdx.x * 1024 + threadIdx.x;
    int v = (i < n) ? deg[i] : 0;
    sh[threadIdx.x] = v;
    __syncthreads();
    #pragma unroll
    for (int off = 1; off < 1024; off <<= 1) {
        int t = (threadIdx.x >= (unsigned)off) ? sh[threadIdx.x - off] : 0;
        __syncthreads();
        sh[threadIdx.x] += t;
        __syncthreads();
    }
    if (i < n) rowptr[i + 1] = sh[threadIdx.x];
    if (threadIdx.x == 1023) bsum[blockIdx.x] = sh[1023];
}

__global__ void k_scan2(const int* __restrict__ bsum, int* __restrict__ boff, int nb) {
    __shared__ int sh[64];
    int i = threadIdx.x;
    int orig = (i < nb) ? bsum[i] : 0;
    sh[i] = orig;
    __syncthreads();
    #pragma unroll
    for (int off = 1; off < 64; off <<= 1) {
        int t = (i >= off) ? sh[i - off] : 0;
        __syncthreads();
        sh[i] += t;
        __syncthreads();
    }
    if (i < nb) boff[i] = sh[i] - orig;
}

__global__ void k_scan3(const int* __restrict__ deg, int* __restrict__ rowptr,
                        const int* __restrict__ boff, int* __restrict__ cursor, int n) {
    int i = blockIdx.x * 1024 + threadIdx.x;
    if (i == 0) rowptr[0] = 0;
    if (i < n) {
        int inc = rowptr[i + 1] + boff[blockIdx.x];
        rowptr[i + 1] = inc;
        cursor[i] = inc - deg[i];
    }
}

__global__ void k_sortedges(const int* __restrict__ src, const int* __restrict__ dst,
                            int* __restrict__ cursor, int* __restrict__ colsrc, int e) {
    int i = blockIdx.x * blockDim.x + threadIdx.x;
    if (i < e) {
        int d = dst[i];
        int p = atomicAdd(&cursor[d], 1);
        colsrc[p] = src[i];
    }
}

// ===========================================================================
// fp16 CSR gather aggregation (fp32 accum); optional compacted node list
// ===========================================================================
__global__ __launch_bounds__(128) void k_agg(const __half2* __restrict__ z,
                                             __half2* __restrict__ agg,
                                             const int* __restrict__ rowptr,
                                             const int* __restrict__ colsrc, int n,
                                             const int* __restrict__ ridx,
                                             const int* __restrict__ cntp) {
    int b = blockIdx.x;
    int node;
    if (ridx != nullptr) {
        if (b >= *cntp) return;
        node = ridx[b];
    } else {
        if (b >= n) return;
        node = b;
    }
    int c = threadIdx.x;
    int s0 = rowptr[node], s1 = rowptr[node + 1];
    float2 a0 = make_float2(0.f, 0.f), a1 = make_float2(0.f, 0.f);
    float2 a2 = make_float2(0.f, 0.f), a3 = make_float2(0.f, 0.f);
    int i = s0;
    for (; i + 3 < s1; i += 4) {
        int sA = colsrc[i], sB = colsrc[i + 1], sC = colsrc[i + 2], sD = colsrc[i + 3];
        float2 vA = __half22float2(z[(size_t)sA * 128 + c]);
        float2 vB = __half22float2(z[(size_t)sB * 128 + c]);
        float2 vC = __half22float2(z[(size_t)sC * 128 + c]);
        float2 vD = __half22float2(z[(size_t)sD * 128 + c]);
        a0.x += vA.x; a0.y += vA.y;
        a1.x += vB.x; a1.y += vB.y;
        a2.x += vC.x; a2.y += vC.y;
        a3.x += vD.x; a3.y += vD.y;
    }
    for (; i < s1; i++) {
        float2 v = __half22float2(z[(size_t)colsrc[i] * 128 + c]);
        a0.x += v.x; a0.y += v.y;
    }
    float rx = (a0.x + a1.x) + (a2.x + a3.x);
    float ry = (a0.y + a1.y) + (a2.y + a3.y);
    agg[(size_t)node * 128 + c] = __floats2half2_rn(rx, ry);
}

// ===========================================================================
// Weight pack
// ===========================================================================
__global__ void k_pack(const float* __restrict__ Wself, const float* __restrict__ Wnei,
                       __half* __restrict__ wTh) {
    int idx = blockIdx.x * 256 + threadIdx.x;
    int k = idx & 511;
    int rem = idx >> 9;
    int nrow = rem & 255;
    int mat = rem >> 8;
    const float* srcp = (k < 256) ? Wself : Wnei;
    int kk = k & 255;
    wTh[idx] = __float2half_rn(srcp[((size_t)mat * 256 + kk) * 256 + nrow]);
}

// ===========================================================================
// Final combine
// ===========================================================================
__global__ void k_combine(const float* __restrict__ p0, const float* __restrict__ p1,
                          const float* __restrict__ p2, const float* __restrict__ p3,
                          float* __restrict__ out, int n4) {
    int i = blockIdx.x * blockDim.x + threadIdx.x;
    if (i >= n4) return;
    float4 a = ((const float4*)p0)[i];
    float4 b = ((const float4*)p1)[i];
    float4 c = ((const float4*)p2)[i];
    float4 d = ((const float4*)p3)[i];
    float4 o;
    o.x = (a.x + b.x) + (c.x + d.x);
    o.y = (a.y + b.y) + (c.y + d.y);
    o.z = (a.z + b.z) + (c.z + d.z);
    o.w = (a.w + b.w) + (c.w + d.w);
    ((float4*)out)[i] = o;
}

// ===========================================================================
// fp16 mma.sync dual GEMM; ldmatrix fragment loads; optional row list
// ===========================================================================
#define PADH 72
#define HBUF (128 * PADH)
#define TM_SMEM (4 * HBUF * 2)

__global__ __launch_bounds__(256, 2) void k_tmma(
    const __half* __restrict__ Az, const __half* __restrict__ Ag,
    const __half* __restrict__ WTh, const float* __restrict__ bias,
    int n, int relu, __half* __restrict__ Ch, float* __restrict__ Cf,
    const float* __restrict__ sparse, int expert, int accum,
    const int* __restrict__ ridx, const int* __restrict__ cntp)
{
    extern __shared__ __half smh[];
    __shared__ int rid_s[128];
    uint32_t sbase = smem_u32(smh);

    int tid = threadIdx.x;
    int warp = tid >> 5, lane = tid & 31;
    int m0 = blockIdx.x * 128;
    int n0 = blockIdx.y * 128;
    int m_off = (warp >> 1) * 32;
    int n_off = (warp & 1) * 64;
    int g = lane >> 2, t = lane & 3;

    int mrows = (cntp != nullptr) ? *cntp : n;
    if (m0 >= mrows) return;

    if (tid < 128) {
        int gr = m0 + tid;
        rid_s[tid] = (gr < mrows) ? ((ridx != nullptr) ? ridx[gr] : gr) : 0;
    }
    __syncthreads();

    float acc[2][8][4];
    #pragma unroll
    for (int i = 0; i < 2; i++)
        #pragma unroll
        for (int j = 0; j < 8; j++)
            #pragma unroll
            for (int r = 0; r < 4; r++) acc[i][j][r] = 0.f;

    auto issue_chunk = [&](int c, int buf) {
        const __half* Asrc = (c < 4) ? Az : Ag;
        int kb = (c & 3) * 64;
        uint32_t abase = sbase + (uint32_t)buf * (HBUF * 2);
        uint32_t bbase = sbase + (uint32_t)(2 + buf) * (HBUF * 2);
        #pragma unroll
        for (int i = 0; i < 4; i++) {
            int idx = tid + i * 256;
            int row = idx >> 3, q = idx & 7;
            int gr = m0 + row;
            int node = rid_s[row];
            cp16(abase + (uint32_t)(row * (PADH * 2) + q * 16),
                 Asrc + (size_t)node * HDIM + kb + q * 8,
                 (gr < mrows) ? 16 : 0);
            cp16u(bbase + (uint32_t)(row * (PADH * 2) + q * 16),
                  WTh + (size_t)(n0 + row) * 512 + c * 64 + q * 8);
        }
        asm volatile("cp.async.commit_group;" ::: "memory");
    };

    // ldmatrix per-lane address components (bytes)
    // A call i: mat = lane>>3; row = m_off + i*16 + (lane&7) + ((lane>>3)&1)*8;
    //           khalf = (lane>>4)*8
    int a_row = m_off + (lane & 7) + ((lane >> 3) & 1) * 8;
    int a_kh  = (lane >> 4) * 8;
    uint32_t a_off0 = (uint32_t)(a_row * PADH + a_kh) * 2;
    // B call q: mat = lane>>3; n-row = n_off + q*16 + ((lane>>4)&1)*8 + (lane&7);
    //           khalf = ((lane>>3)&1)*8
    int b_row = n_off + ((lane >> 4) & 1) * 8 + (lane & 7);
    int b_kh  = ((lane >> 3) & 1) * 8;
    uint32_t b_off0 = (uint32_t)(b_row * PADH + b_kh) * 2;

    issue_chunk(0, 0);

    for (int c = 0; c < 8; c++) {
        int buf = c & 1;
        if (c < 7) {
            issue_chunk(c + 1, buf ^ 1);
            asm volatile("cp.async.wait_group 1;" ::: "memory");
        } else {
            asm volatile("cp.async.wait_group 0;" ::: "memory");
        }
        __syncthreads();

        uint32_t a_sm = sbase + (uint32_t)buf * (HBUF * 2) + a_off0;
        uint32_t b_sm = sbase + (uint32_t)(2 + buf) * (HBUF * 2) + b_off0;
        #pragma unroll
        for (int ks = 0; ks < 4; ks++) {
            uint32_t koff = (uint32_t)(ks * 16) * 2;
            uint32_t af[2][4], bf[8][2];
            ldsm_x4(af[0][0], af[0][1], af[0][2], af[0][3], a_sm + koff);
            ldsm_x4(af[1][0], af[1][1], af[1][2], af[1][3],
                    a_sm + (uint32_t)(16 * PADH) * 2 + koff);
            #pragma unroll
            for (int q = 0; q < 4; q++)
                ldsm_x4(bf[2 * q][0], bf[2 * q][1], bf[2 * q + 1][0], bf[2 * q + 1][1],
                        b_sm + (uint32_t)(q * 16 * PADH) * 2 + koff);
            #pragma unroll
            for (int i = 0; i < 2; i++)
                #pragma unroll
                for (int j = 0; j < 8; j++)
                    mma_f16(acc[i][j], af[i], bf[j]);
        }
        __syncthreads();
    }

    // ---- epilogue ----
    #pragma unroll
    for (int i = 0; i < 2; i++) {
        int l0 = m_off + i * 16 + g;
        int l1 = l0 + 8;
        bool v0r = (m0 + l0) < mrows;
        bool v1r = (m0 + l1) < mrows;
        int node0 = rid_s[l0];
        int node1 = rid_s[l1];
        float s0 = 0.f, s1 = 0.f;
        if (Cf != nullptr) {
            if (v0r) s0 = sparse[(size_t)node0 * NEXP + expert];
            if (v1r) s1 = sparse[(size_t)node1 * NEXP + expert];
        }
        #pragma unroll
        for (int j = 0; j < 8; j++) {
            int col = n0 + n_off + j * 8 + 2 * t;
            float2 bb2 = *(const float2*)(bias + col);
            float2 v0, v1;
            v0.x = acc[i][j][0] + bb2.x; v0.y = acc[i][j][1] + bb2.y;
            v1.x = acc[i][j][2] + bb2.x; v1.y = acc[i][j][3] + bb2.y;
            if (relu) {
                v0.x = fmaxf(v0.x, 0.f); v0.y = fmaxf(v0.y, 0.f);
                v1.x = fmaxf(v1.x, 0.f); v1.y = fmaxf(v1.y, 0.f);
            }
            if (Cf != nullptr) {
                if (v0r) {
                    float2* op = (float2*)(Cf + (size_t)node0 * HDIM + col);
                    float2 o = accum ? *op : make_float2(0.f, 0.f);
                    o.x = fmaf(s0, v0.x, o.x); o.y = fmaf(s0, v0.y, o.y);
                    *op = o;
                }
                if (v1r) {
                    float2* op = (float2*)(Cf + (size_t)node1 * HDIM + col);
                    float2 o = accum ? *op : make_float2(0.f, 0.f);
                    o.x = fmaf(s1, v1.x, o.x); o.y = fmaf(s1, v1.y, o.y);
                    *op = o;
                }
            } else {
                if (v0r) *(__half2*)(Ch + (size_t)node0 * HDIM + col) = __floats2half2_rn(v0.x, v0.y);
                if (v1r) *(__half2*)(Ch + (size_t)node1 * HDIM + col) = __floats2half2_rn(v1.x, v1.y);
            }
        }
    }
}

// ===========================================================================
// host launch
// ===========================================================================
extern "C" void kernel_launch(void* const* d_in, const int* in_sizes, int n_in,
                              void* d_out, int out_size) {
    const float* x      = (const float*)d_in[0];
    const int*   ei     = (const int*)  d_in[1];
    const int*   batch  = (const int*)  d_in[2];
    const float* W_enc  = (const float*)d_in[3];
    const float* b_enc  = (const float*)d_in[4];
    const float* Ws1    = (const float*)d_in[5];
    const float* bs1    = (const float*)d_in[6];
    const float* Ws2    = (const float*)d_in[7];
    const float* bs2    = (const float*)d_in[8];
    const float* Wt1    = (const float*)d_in[9];
    const float* bt1    = (const float*)d_in[10];
    const float* Wt2    = (const float*)d_in[11];
    const float* bt2    = (const float*)d_in[12];
    const float* W_self = (const float*)d_in[13];
    const float* W_nei  = (const float*)d_in[14];
    const float* b_exp  = (const float*)d_in[15];

    int N = in_sizes[0] / 10;
    int E = in_sizes[1] / 2;
    const int* src = ei;
    const int* dst = ei + E;
    float* out = (float*)d_out;

    float *h, *hs, *part, *sparse, *strug;
    __half *h16, *agg0, *zA, *zB, *agT, *wTh;
    int *deg, *rowptr, *cursor, *colsrc, *ng, *eg, *bsum, *boff, *xidx, *xcnt;
    cudaGetSymbolAddress((void**)&h,      g_h);
    cudaGetSymbolAddress((void**)&h16,    g_h16);
    cudaGetSymbolAddress((void**)&hs,     g_hs);
    cudaGetSymbolAddress((void**)&agg0,   g_agg0);
    cudaGetSymbolAddress((void**)&zA,     g_zA);
    cudaGetSymbolAddress((void**)&zB,     g_zB);
    cudaGetSymbolAddress((void**)&agT,    g_agT);
    cudaGetSymbolAddress((void**)&part,   g_part);
    cudaGetSymbolAddress((void**)&sparse, g_sparse);
    cudaGetSymbolAddress((void**)&strug,  g_strug);
    cudaGetSymbolAddress((void**)&wTh,    g_wTh);
    cudaGetSymbolAddress((void**)&deg,    g_deg);
    cudaGetSymbolAddress((void**)&rowptr, g_rowptr);
    cudaGetSymbolAddress((void**)&cursor, g_cursor);
    cudaGetSymbolAddress((void**)&colsrc, g_colsrc);
    cudaGetSymbolAddress((void**)&ng,     g_ng);
    cudaGetSymbolAddress((void**)&eg,     g_eg);
    cudaGetSymbolAddress((void**)&bsum,   g_bsum);
    cudaGetSymbolAddress((void**)&boff,   g_boff);
    cudaGetSymbolAddress((void**)&xidx,   g_xidx);
    cudaGetSymbolAddress((void**)&xcnt,   g_xcnt);

    cudaFuncSetAttribute(k_tmma, cudaFuncAttributeMaxDynamicSharedMemorySize, TM_SMEM);

    const size_t ZSZ = (size_t)MAXN * HDIM;
    int nsb = (N + 1023) / 1024;

    // ---- weight pack runs on the router stream, off the CSR critical path
    k_pack<<<24 * 256 * 512 / 256, 256, 0, g_sp.s[NSTREAM]>>>(W_self, W_nei, wTh);

    // ---- prologue on capture stream (0)
    cudaMemsetAsync(ng,   0, NGRAPH * sizeof(int), 0);
    cudaMemsetAsync(eg,   0, NGRAPH * sizeof(int), 0);
    cudaMemsetAsync(deg,  0, (size_t)N * sizeof(int), 0);
    cudaMemsetAsync(xcnt, 0, NEXP * sizeof(int), 0);

    k_hist_nodes<<<128, 256>>>(batch, ng, N);
    k_hist_edges<<<256, 256>>>(batch, src, eg, E);
    k_stru<<<NGRAPH, 256>>>(ng, eg, Wt1, bt1, Wt2, bt2, strug);
    k_encode<<<N, 256>>>(x, W_enc, b_enc, h, h16, N);

    // fork router path onto s[4] (after k_pack on the same stream)
    cudaEventRecord(g_sp.evA, 0);
    cudaStreamWaitEvent(g_sp.s[NSTREAM], g_sp.evA, 0);
    {
        dim3 rgrid((N + BMR - 1) / BMR, HDIM / BNR);
        k_gemm<<<rgrid, 256, 0, g_sp.s[NSTREAM]>>>(h, Ws1, bs1, N, hs);
        k_logits<<<(N + 7) / 8, 256, 0, g_sp.s[NSTREAM]>>>(hs, Ws2, bs2, strug, batch,
                                                           sparse, xidx, xcnt, N);
        cudaEventRecord(g_sp.evB, g_sp.s[NSTREAM]);
    }

    // meanwhile on stream 0: CSR build + layer-0 agg
    k_deg<<<(E + 255) / 256, 256>>>(dst, deg, E);
    k_scan1<<<nsb, 1024>>>(deg, rowptr, bsum, N);
    k_scan2<<<1, 64>>>(bsum, boff, nsb);
    k_scan3<<<nsb, 1024>>>(deg, rowptr, boff, cursor, N);
    k_sortedges<<<(E + 255) / 256, 256>>>(src, dst, cursor, colsrc, E);
    k_agg<<<N, 128>>>((const __half2*)h16, (__half2*)agg0, rowptr, colsrc, N, nullptr, nullptr);

    cudaEventRecord(g_sp.fork, 0);

    // ---- 4 parallel expert chains, 2 experts each; streams 2,3 staggered
    dim3 mgrid((N + 127) / 128, 2);
    for (int i = 0; i < NSTREAM; i++) {
        cudaStream_t st = g_sp.s[i];
        cudaStreamWaitEvent(st, g_sp.fork, 0);
        cudaStreamWaitEvent(st, g_sp.evB, 0);
        if (i >= 2) cudaStreamWaitEvent(st, g_sp.stg[i - 2], 0);
        __half* zAi = zA + (size_t)i * ZSZ;
        __half* zBi = zB + (size_t)i * ZSZ;
        __half* agi = agT + (size_t)i * ZSZ;
        float*  pti = part + (size_t)i * ZSZ;
        cudaMemsetAsync(pti, 0, ZSZ * sizeof(float), st);   // gated accumulation base
        for (int j = 0; j < 2; j++) {
            int e = i * 2 + j;
            const __half* wt0 = wTh + (size_t)(e * 3 + 0) * 256 * 512;
            const __half* wt1 = wTh + (size_t)(e * 3 + 1) * 256 * 512;
            const __half* wt2 = wTh + (size_t)(e * 3 + 2) * 256 * 512;
            const float* b_l0 = b_exp + (size_t)(e * 3 + 0) * HDIM;
            const float* b_l1 = b_exp + (size_t)(e * 3 + 1) * HDIM;
            const float* b_l2 = b_exp + (size_t)(e * 3 + 2) * HDIM;
            const int* ri = xidx + (size_t)e * MAXN;
            const int* ct = xcnt + e;

            // dense layers 0,1 (all nodes — needed by graph aggregation)
            k_tmma<<<mgrid, 256, TM_SMEM, st>>>(h16, agg0, wt0, b_l0, N, 1, zAi, nullptr,
                                                nullptr, 0, 0, nullptr, nullptr);
            if (j == 0 && i < 2) cudaEventRecord(g_sp.stg[i], st);
            k_agg<<<N, 128, 0, st>>>((const __half2*)zAi, (__half2*)agi, rowptr, colsrc, N,
                                     nullptr, nullptr);
            k_tmma<<<mgrid, 256, TM_SMEM, st>>>(zAi, agi, wt1, b_l1, N, 1, zBi, nullptr,
                                                nullptr, 0, 0, nullptr, nullptr);
            // sparse: second agg + final gated GEMM only over gated nodes
            k_agg<<<N, 128, 0, st>>>((const __half2*)zBi, (__half2*)agi, rowptr, colsrc, N,
                                     ri, ct);
            k_tmma<<<mgrid, 256, TM_SMEM, st>>>(zBi, agi, wt2, b_l2, N, 0, nullptr, pti,
                                                sparse, e, 1, ri, ct);
        }
        cudaEventRecord(g_sp.join[i], st);
    }

    // ---- join + combine
    for (int i = 0; i < NSTREAM; i++) cudaStreamWaitEvent(0, g_sp.join[i], 0);
    int n4 = N * HDIM / 4;
    k_combine<<<(n4 + 255) / 256, 256>>>(part, part + ZSZ, part + 2 * ZSZ, part + 3 * ZSZ, out, n4);
}

// round 13
// speedup vs baseline: 7.9438x; 1.1784x over previous
#include <cuda_runtime.h>
#include <cuda_fp16.h>
#include <cstdint>
#include <cstddef>

// ---------------------------------------------------------------------------
// GraphMoEDualRouter — GB300 sm_103a.
// Round 12: warp-per-node agg (LDG.128 lanes, 4x fewer load instrs,
// bit-identical sums); prologue re-plumbed so CSR build starts immediately
// and the router path is fully off the dense critical path (evB waited
// mid-chain, right before the first sparse kernel).
// ---------------------------------------------------------------------------

#define HDIM 256
#define NEXP 8
#define NGRAPH 64
#define MAXN 50176
#define MAXE 1600000
#define NSTREAM 4

typedef unsigned long long ull;

// ---- scratch (static device memory; allocation is forbidden) ----
__device__ float  g_h    [MAXN * HDIM];                 // fp32 h (router)
__device__ __half g_h16  [MAXN * HDIM];                 // fp16 h (experts)
__device__ float  g_hs   [MAXN * HDIM];                 // router hidden
__device__ __half g_agg0 [MAXN * HDIM];
__device__ __half g_zA   [NSTREAM][MAXN * HDIM];
__device__ __half g_zB   [NSTREAM][MAXN * HDIM];
__device__ __half g_agT  [NSTREAM][MAXN * HDIM];
__device__ float  g_part [NSTREAM][MAXN * HDIM];
__device__ float  g_sparse[MAXN * NEXP];
__device__ int    g_xidx  [NEXP][MAXN];                 // per-expert gated nodes
__device__ int    g_xcnt  [NEXP];
__device__ int    g_deg   [MAXN];
__device__ int    g_rowptr[MAXN + 1];
__device__ int    g_cursor[MAXN];
__device__ int    g_colsrc[MAXE];
__device__ int    g_bsum  [64];
__device__ int    g_boff  [64];
__device__ int    g_ng[NGRAPH];
__device__ int    g_eg[NGRAPH];
__device__ float  g_strug[NGRAPH * NEXP];
// packed transposed fp16 weights: [24 mats][256 nrows][512 k]
__device__ __half g_wTh[24 * 256 * 512];

// ---- host-side streams/events (created once, pre-main; host resources only)
struct StreamPool {
    cudaStream_t s[NSTREAM + 1];
    cudaEvent_t evA, evB, evE, fork, join[NSTREAM], stg[2];
    StreamPool() {
        for (int i = 0; i <= NSTREAM; i++)
            cudaStreamCreateWithFlags(&s[i], cudaStreamNonBlocking);
        cudaEventCreateWithFlags(&evA,  cudaEventDisableTiming);
        cudaEventCreateWithFlags(&evB,  cudaEventDisableTiming);
        cudaEventCreateWithFlags(&evE,  cudaEventDisableTiming);
        cudaEventCreateWithFlags(&fork, cudaEventDisableTiming);
        for (int i = 0; i < NSTREAM; i++)
            cudaEventCreateWithFlags(&join[i], cudaEventDisableTiming);
        cudaEventCreateWithFlags(&stg[0], cudaEventDisableTiming);
        cudaEventCreateWithFlags(&stg[1], cudaEventDisableTiming);
    }
};
static StreamPool g_sp;

// ---- helpers ----
__device__ __forceinline__ ull pack2(float lo, float hi) {
    ull r; asm("mov.b64 %0, {%1, %2};" : "=l"(r) : "f"(lo), "f"(hi)); return r;
}
__device__ __forceinline__ void fma2acc(ull& d, ull a, ull b) {
    asm("fma.rn.f32x2 %0, %1, %2, %0;" : "+l"(d) : "l"(a), "l"(b));
}
__device__ __forceinline__ void unpack2(ull v, float& lo, float& hi) {
    asm("mov.b64 {%0, %1}, %2;" : "=f"(lo), "=f"(hi) : "l"(v));
}
__device__ __forceinline__ void mma_f16(float* d, const uint32_t* a, const uint32_t* b) {
    asm volatile(
        "mma.sync.aligned.m16n8k16.row.col.f32.f16.f16.f32 "
        "{%0,%1,%2,%3}, {%4,%5,%6,%7}, {%8,%9}, {%0,%1,%2,%3};"
        : "+f"(d[0]), "+f"(d[1]), "+f"(d[2]), "+f"(d[3])
        : "r"(a[0]), "r"(a[1]), "r"(a[2]), "r"(a[3]), "r"(b[0]), "r"(b[1]));
}
__device__ __forceinline__ void ldsm_x4(uint32_t& r0, uint32_t& r1,
                                        uint32_t& r2, uint32_t& r3, uint32_t addr) {
    asm volatile("ldmatrix.sync.aligned.m8n8.x4.shared.b16 {%0,%1,%2,%3}, [%4];"
        : "=r"(r0), "=r"(r1), "=r"(r2), "=r"(r3) : "r"(addr));
}
__device__ __forceinline__ uint32_t smem_u32(const void* p) {
    uint32_t a;
    asm("{ .reg .u64 t; cvta.to.shared.u64 t, %1; cvt.u32.u64 %0, t; }" : "=r"(a) : "l"(p));
    return a;
}
__device__ __forceinline__ void cp16(uint32_t dst, const void* src, int sz) {
    asm volatile("cp.async.cg.shared.global [%0], [%1], 16, %2;"
                 :: "r"(dst), "l"(src), "r"(sz) : "memory");
}
__device__ __forceinline__ void cp16u(uint32_t dst, const void* src) {
    asm volatile("cp.async.cg.shared.global [%0], [%1], 16;"
                 :: "r"(dst), "l"(src) : "memory");
}
__device__ __forceinline__ void acc8(float* a, uint4 v) {
    const __half2* p = (const __half2*)&v;
    #pragma unroll
    for (int q = 0; q < 4; q++) {
        float2 f = __half22float2(p[q]);
        a[2 * q]     += f.x;
        a[2 * q + 1] += f.y;
    }
}

// ===========================================================================
// Small kernels
// ===========================================================================
__global__ void k_hist_nodes(const int* __restrict__ batch, int* __restrict__ ng, int n) {
    __shared__ int sh[NGRAPH];
    if (threadIdx.x < NGRAPH) sh[threadIdx.x] = 0;
    __syncthreads();
    for (int i = blockIdx.x * blockDim.x + threadIdx.x; i < n; i += gridDim.x * blockDim.x)
        atomicAdd(&sh[batch[i]], 1);
    __syncthreads();
    if (threadIdx.x < NGRAPH) atomicAdd(&ng[threadIdx.x], sh[threadIdx.x]);
}

__global__ void k_hist_edges(const int* __restrict__ batch, const int* __restrict__ src,
                             int* __restrict__ eg, int e) {
    __shared__ int sh[NGRAPH];
    if (threadIdx.x < NGRAPH) sh[threadIdx.x] = 0;
    __syncthreads();
    for (int i = blockIdx.x * blockDim.x + threadIdx.x; i < e; i += gridDim.x * blockDim.x)
        atomicAdd(&sh[batch[src[i]]], 1);
    __syncthreads();
    if (threadIdx.x < NGRAPH) atomicAdd(&eg[threadIdx.x], sh[threadIdx.x]);
}

__global__ void k_stru(const int* __restrict__ ng, const int* __restrict__ eg,
                       const float* __restrict__ Wt1, const float* __restrict__ bt1,
                       const float* __restrict__ Wt2, const float* __restrict__ bt2,
                       float* __restrict__ strug) {
    int g = blockIdx.x;
    float fn = log1pf((float)ng[g]);
    float fe = log1pf((float)eg[g]);
    __shared__ float hid[HDIM];
    int j = threadIdx.x;
    hid[j] = fmaxf(fmaf(fn, Wt1[j], fmaf(fe, Wt1[HDIM + j], bt1[j])), 0.0f);
    __syncthreads();
    int w = threadIdx.x >> 5, lane = threadIdx.x & 31;
    if (w < NEXP) {
        float acc = 0.f;
        for (int k = lane; k < HDIM; k += 32) acc = fmaf(hid[k], Wt2[k * NEXP + w], acc);
        #pragma unroll
        for (int off = 16; off; off >>= 1) acc += __shfl_down_sync(0xffffffffu, acc, off);
        if (lane == 0) strug[g * NEXP + w] = acc + bt2[w];
    }
}

__global__ void k_encode(const float* __restrict__ x, const float* __restrict__ W,
                         const float* __restrict__ b, float* __restrict__ h,
                         __half* __restrict__ h16, int n) {
    int node = blockIdx.x;
    if (node >= n) return;
    __shared__ float xs[6];
    if (threadIdx.x < 6) xs[threadIdx.x] = x[node * 10 + 4 + threadIdx.x];
    __syncthreads();
    int j = threadIdx.x;
    float acc = b[j];
    #pragma unroll
    for (int k = 0; k < 6; k++) acc = fmaf(xs[k], W[k * HDIM + j], acc);
    float v = fmaxf(acc, 0.0f);
    h[(size_t)node * HDIM + j] = v;
    h16[(size_t)node * HDIM + j] = __float2half_rn(v);
}

// ===========================================================================
// FFMA fp32 GEMM — router hidden layer only (top-2 selection needs exactness)
// ===========================================================================
#define BMR 128
#define BNR 64
#define BKR 16

__global__ __launch_bounds__(256) void k_gemm(
    const float* __restrict__ A, const float* __restrict__ W1,
    const float* __restrict__ bias, int n, float* __restrict__ C)
{
    __shared__ __align__(16) float As[BKR][BMR + 2];
    __shared__ __align__(16) float Ws[BKR][BNR];

    int m0 = blockIdx.x * BMR;
    int n0 = blockIdx.y * BNR;
    int tid = threadIdx.x;
    int tm = tid >> 4;
    int tn = tid & 15;

    ull acc2[4][4];
    #pragma unroll
    for (int i = 0; i < 4; i++)
        #pragma unroll
        for (int j = 0; j < 4; j++) acc2[i][j] = 0ull;

    for (int kc = 0; kc < HDIM; kc += BKR) {
        #pragma unroll
        for (int u = 0; u < 2; u++) {
            int idx = tid + u * 256;
            int row = idx >> 2;
            int kq  = idx & 3;
            float4 v = make_float4(0.f, 0.f, 0.f, 0.f);
            int gr = m0 + row;
            if (gr < n) v = *(const float4*)(A + (size_t)gr * HDIM + kc + kq * 4);
            As[kq * 4 + 0][row] = v.x;
            As[kq * 4 + 1][row] = v.y;
            As[kq * 4 + 2][row] = v.z;
            As[kq * 4 + 3][row] = v.w;
        }
        {
            int kk = tid >> 4, nq = tid & 15;
            float4 w = *(const float4*)(W1 + (size_t)(kc + kk) * HDIM + n0 + nq * 4);
            *(float4*)&Ws[kk][nq * 4] = w;
        }
        __syncthreads();
        #pragma unroll
        for (int kk = 0; kk < BKR; kk++) {
            ull a2[4];
            #pragma unroll
            for (int i2 = 0; i2 < 4; i2++)
                a2[i2] = *(const ull*)&As[kk][tm * 8 + i2 * 2];
            #pragma unroll
            for (int j = 0; j < 4; j++) {
                float bb = Ws[kk][tn * 4 + j];
                ull b2 = pack2(bb, bb);
                #pragma unroll
                for (int i2 = 0; i2 < 4; i2++) fma2acc(acc2[i2][j], a2[i2], b2);
            }
        }
        __syncthreads();
    }

    float4 bb4 = *(const float4*)&bias[n0 + tn * 4];
    #pragma unroll
    for (int i2 = 0; i2 < 4; i2++) {
        float4 vlo, vhi;
        unpack2(acc2[i2][0], vlo.x, vhi.x);
        unpack2(acc2[i2][1], vlo.y, vhi.y);
        unpack2(acc2[i2][2], vlo.z, vhi.z);
        unpack2(acc2[i2][3], vlo.w, vhi.w);
        #pragma unroll
        for (int rr = 0; rr < 2; rr++) {
            int row = m0 + tm * 8 + i2 * 2 + rr;
            if (row >= n) continue;
            float4 v = rr ? vhi : vlo;
            v.x = fmaxf(v.x + bb4.x, 0.f); v.y = fmaxf(v.y + bb4.y, 0.f);
            v.z = fmaxf(v.z + bb4.z, 0.f); v.w = fmaxf(v.w + bb4.w, 0.f);
            *(float4*)(C + (size_t)row * HDIM + n0 + tn * 4) = v;
        }
    }
}

// ===========================================================================
// Router logits + top-2 sparse gates + per-expert compacted node lists
// ===========================================================================
__global__ void k_logits(const float* __restrict__ hs, const float* __restrict__ Ws2,
                         const float* __restrict__ bs2, const float* __restrict__ strug,
                         const int* __restrict__ batch, float* __restrict__ sparse,
                         int* __restrict__ xidx, int* __restrict__ xcnt, int n) {
    int warp = (blockIdx.x * blockDim.x + threadIdx.x) >> 5;
    int lane = threadIdx.x & 31;
    if (warp >= n) return;
    const float* row = hs + (size_t)warp * HDIM;
    float acc[NEXP];
    #pragma unroll
    for (int o = 0; o < NEXP; o++) acc[o] = 0.f;
    for (int k = lane; k < HDIM; k += 32) {
        float v = row[k];
        const float* w2 = Ws2 + k * NEXP;
        #pragma unroll
        for (int o = 0; o < NEXP; o++) acc[o] = fmaf(v, w2[o], acc[o]);
    }
    #pragma unroll
    for (int o = 0; o < NEXP; o++)
        #pragma unroll
        for (int off = 16; off; off >>= 1) acc[o] += __shfl_down_sync(0xffffffffu, acc[o], off);
    if (lane == 0) {
        int g = batch[warp];
        float lg[NEXP];
        #pragma unroll
        for (int o = 0; o < NEXP; o++)
            lg[o] = 0.5f * (acc[o] + bs2[o]) + 0.5f * strug[g * NEXP + o];
        float m1 = -3.4e38f; int i1 = 0;
        #pragma unroll
        for (int o = 0; o < NEXP; o++) if (lg[o] > m1) { m1 = lg[o]; i1 = o; }
        float m2 = -3.4e38f; int i2 = 0;
        #pragma unroll
        for (int o = 0; o < NEXP; o++) if (o != i1 && lg[o] > m2) { m2 = lg[o]; i2 = o; }
        float e2 = __expf(m2 - m1);
        float inv = 1.0f / (1.0f + e2);
        float* srow = sparse + (size_t)warp * NEXP;
        #pragma unroll
        for (int o = 0; o < NEXP; o++) srow[o] = 0.f;
        srow[i1] = inv;
        srow[i2] = e2 * inv;
        int p1 = atomicAdd(&xcnt[i1], 1);
        xidx[i1 * MAXN + p1] = warp;
        int p2 = atomicAdd(&xcnt[i2], 1);
        xidx[i2 * MAXN + p2] = warp;
    }
}

// ===========================================================================
// CSR build: counting sort by dst with 3-phase multi-block scan
// ===========================================================================
__global__ void k_deg(const int* __restrict__ dst, int* __restrict__ deg, int e) {
    int i = blockIdx.x * blockDim.x + threadIdx.x;
    if (i < e) atomicAdd(&deg[dst[i]], 1);
}

__global__ void k_scan1(const int* __restrict__ deg, int* __restrict__ rowptr,
                        int* __restrict__ bsum, int n) {
    __shared__ int sh[1024];
    int i = blockIdx.x * 1024 + threadIdx.x;
    int v = (i < n) ? deg[i] : 0;
    sh[threadIdx.x] = v;
    __syncthreads();
    #pragma unroll
    for (int off = 1; off < 1024; off <<= 1) {
        int t = (threadIdx.x >= (unsigned)off) ? sh[threadIdx.x - off] : 0;
        __syncthreads();
        sh[threadIdx.x] += t;
        __syncthreads();
    }
    if (i < n) rowptr[i + 1] = sh[threadIdx.x];
    if (threadIdx.x == 1023) bsum[blockIdx.x] = sh[1023];
}

__global__ void k_scan2(const int* __restrict__ bsum, int* __restrict__ boff, int nb) {
    __shared__ int sh[64];
    int i = threadIdx.x;
    int orig = (i < nb) ? bsum[i] : 0;
    sh[i] = orig;
    __syncthreads();
    #pragma unroll
    for (int off = 1; off < 64; off <<= 1) {
        int t = (i >= off) ? sh[i - off] : 0;
        __syncthreads();
        sh[i] += t;
        __syncthreads();
    }
    if (i < nb) boff[i] = sh[i] - orig;
}

__global__ void k_scan3(const int* __restrict__ deg, int* __restrict__ rowptr,
                        const int* __restrict__ boff, int* __restrict__ cursor, int n) {
    int i = blockIdx.x * 1024 + threadIdx.x;
    if (i == 0) rowptr[0] = 0;
    if (i < n) {
        int inc = rowptr[i + 1] + boff[blockIdx.x];
        rowptr[i + 1] = inc;
        cursor[i] = inc - deg[i];
    }
}

__global__ void k_sortedges(const int* __restrict__ src, const int* __restrict__ dst,
                            int* __restrict__ cursor, int* __restrict__ colsrc, int e) {
    int i = blockIdx.x * blockDim.x + threadIdx.x;
    if (i < e) {
        int d = dst[i];
        int p = atomicAdd(&cursor[d], 1);
        colsrc[p] = src[i];
    }
}

// ===========================================================================
// fp16 CSR gather aggregation (fp32 accum) — warp per node, LDG.128 lanes.
// Per-column accumulation order identical to previous rounds (a0..a3 cyclic,
// (a0+a1)+(a2+a3), remainder into a0) -> bit-identical output.
// ===========================================================================
__global__ __launch_bounds__(256) void k_agg(const uint4* __restrict__ z,
                                             uint4* __restrict__ agg,
                                             const int* __restrict__ rowptr,
                                             const int* __restrict__ colsrc, int n,
                                             const int* __restrict__ ridx,
                                             const int* __restrict__ cntp) {
    int w = blockIdx.x * 8 + (threadIdx.x >> 5);
    int lane = threadIdx.x & 31;
    int cnt = (ridx != nullptr) ? *cntp : n;
    if (w >= cnt) return;
    int node = (ridx != nullptr) ? ridx[w] : w;
    int s0 = rowptr[node], s1 = rowptr[node + 1];

    float a0[8], a1[8], a2[8], a3[8];
    #pragma unroll
    for (int k = 0; k < 8; k++) { a0[k] = a1[k] = a2[k] = a3[k] = 0.f; }

    int i = s0;
    for (; i + 3 < s1; i += 4) {
        int sA = colsrc[i], sB = colsrc[i + 1], sC = colsrc[i + 2], sD = colsrc[i + 3];
        uint4 vA = z[(size_t)sA * 32 + lane];
        uint4 vB = z[(size_t)sB * 32 + lane];
        uint4 vC = z[(size_t)sC * 32 + lane];
        uint4 vD = z[(size_t)sD * 32 + lane];
        acc8(a0, vA); acc8(a1, vB); acc8(a2, vC); acc8(a3, vD);
    }
    for (; i < s1; i++) acc8(a0, z[(size_t)colsrc[i] * 32 + lane]);

    uint4 o;
    __half2* op = (__half2*)&o;
    #pragma unroll
    for (int q = 0; q < 4; q++) {
        float rx = (a0[2 * q]     + a1[2 * q])     + (a2[2 * q]     + a3[2 * q]);
        float ry = (a0[2 * q + 1] + a1[2 * q + 1]) + (a2[2 * q + 1] + a3[2 * q + 1]);
        op[q] = __floats2half2_rn(rx, ry);
    }
    agg[(size_t)node * 32 + lane] = o;
}

// ===========================================================================
// Weight pack
// ===========================================================================
__global__ void k_pack(const float* __restrict__ Wself, const float* __restrict__ Wnei,
                       __half* __restrict__ wTh) {
    int idx = blockIdx.x * 256 + threadIdx.x;
    int k = idx & 511;
    int rem = idx >> 9;
    int nrow = rem & 255;
    int mat = rem >> 8;
    const float* srcp = (k < 256) ? Wself : Wnei;
    int kk = k & 255;
    wTh[idx] = __float2half_rn(srcp[((size_t)mat * 256 + kk) * 256 + nrow]);
}

// ===========================================================================
// Final combine
// ===========================================================================
__global__ void k_combine(const float* __restrict__ p0, const float* __restrict__ p1,
                          const float* __restrict__ p2, const float* __restrict__ p3,
                          float* __restrict__ out, int n4) {
    int i = blockIdx.x * blockDim.x + threadIdx.x;
    if (i >= n4) return;
    float4 a = ((const float4*)p0)[i];
    float4 b = ((const float4*)p1)[i];
    float4 c = ((const float4*)p2)[i];
    float4 d = ((const float4*)p3)[i];
    float4 o;
    o.x = (a.x + b.x) + (c.x + d.x);
    o.y = (a.y + b.y) + (c.y + d.y);
    o.z = (a.z + b.z) + (c.z + d.z);
    o.w = (a.w + b.w) + (c.w + d.w);
    ((float4*)out)[i] = o;
}

// ===========================================================================
// fp16 mma.sync dual GEMM; ldmatrix fragment loads; optional row list
// ===========================================================================
#define PADH 72
#define HBUF (128 * PADH)
#define TM_SMEM (4 * HBUF * 2)

__global__ __launch_bounds__(256, 2) void k_tmma(
    const __half* __restrict__ Az, const __half* __restrict__ Ag,
    const __half* __restrict__ WTh, const float* __restrict__ bias,
    int n, int relu, __half* __restrict__ Ch, float* __restrict__ Cf,
    const float* __restrict__ sparse, int expert, int accum,
    const int* __restrict__ ridx, const int* __restrict__ cntp)
{
    extern __shared__ __half smh[];
    __shared__ int rid_s[128];
    uint32_t sbase = smem_u32(smh);

    int tid = threadIdx.x;
    int warp = tid >> 5, lane = tid & 31;
    int m0 = blockIdx.x * 128;
    int n0 = blockIdx.y * 128;
    int m_off = (warp >> 1) * 32;
    int n_off = (warp & 1) * 64;
    int g = lane >> 2, t = lane & 3;

    int mrows = (cntp != nullptr) ? *cntp : n;
    if (m0 >= mrows) return;

    if (tid < 128) {
        int gr = m0 + tid;
        rid_s[tid] = (gr < mrows) ? ((ridx != nullptr) ? ridx[gr] : gr) : 0;
    }
    __syncthreads();

    float acc[2][8][4];
    #pragma unroll
    for (int i = 0; i < 2; i++)
        #pragma unroll
        for (int j = 0; j < 8; j++)
            #pragma unroll
            for (int r = 0; r < 4; r++) acc[i][j][r] = 0.f;

    auto issue_chunk = [&](int c, int buf) {
        const __half* Asrc = (c < 4) ? Az : Ag;
        int kb = (c & 3) * 64;
        uint32_t abase = sbase + (uint32_t)buf * (HBUF * 2);
        uint32_t bbase = sbase + (uint32_t)(2 + buf) * (HBUF * 2);
        #pragma unroll
        for (int i = 0; i < 4; i++) {
            int idx = tid + i * 256;
            int row = idx >> 3, q = idx & 7;
            int gr = m0 + row;
            int node = rid_s[row];
            cp16(abase + (uint32_t)(row * (PADH * 2) + q * 16),
                 Asrc + (size_t)node * HDIM + kb + q * 8,
                 (gr < mrows) ? 16 : 0);
            cp16u(bbase + (uint32_t)(row * (PADH * 2) + q * 16),
                  WTh + (size_t)(n0 + row) * 512 + c * 64 + q * 8);
        }
        asm volatile("cp.async.commit_group;" ::: "memory");
    };

    int a_row = m_off + (lane & 7) + ((lane >> 3) & 1) * 8;
    int a_kh  = (lane >> 4) * 8;
    uint32_t a_off0 = (uint32_t)(a_row * PADH + a_kh) * 2;
    int b_row = n_off + ((lane >> 4) & 1) * 8 + (lane & 7);
    int b_kh  = ((lane >> 3) & 1) * 8;
    uint32_t b_off0 = (uint32_t)(b_row * PADH + b_kh) * 2;

    issue_chunk(0, 0);

    for (int c = 0; c < 8; c++) {
        int buf = c & 1;
        if (c < 7) {
            issue_chunk(c + 1, buf ^ 1);
            asm volatile("cp.async.wait_group 1;" ::: "memory");
        } else {
            asm volatile("cp.async.wait_group 0;" ::: "memory");
        }
        __syncthreads();

        uint32_t a_sm = sbase + (uint32_t)buf * (HBUF * 2) + a_off0;
        uint32_t b_sm = sbase + (uint32_t)(2 + buf) * (HBUF * 2) + b_off0;
        #pragma unroll
        for (int ks = 0; ks < 4; ks++) {
            uint32_t koff = (uint32_t)(ks * 16) * 2;
            uint32_t af[2][4], bf[8][2];
            ldsm_x4(af[0][0], af[0][1], af[0][2], af[0][3], a_sm + koff);
            ldsm_x4(af[1][0], af[1][1], af[1][2], af[1][3],
                    a_sm + (uint32_t)(16 * PADH) * 2 + koff);
            #pragma unroll
            for (int q = 0; q < 4; q++)
                ldsm_x4(bf[2 * q][0], bf[2 * q][1], bf[2 * q + 1][0], bf[2 * q + 1][1],
                        b_sm + (uint32_t)(q * 16 * PADH) * 2 + koff);
            #pragma unroll
            for (int i = 0; i < 2; i++)
                #pragma unroll
                for (int j = 0; j < 8; j++)
                    mma_f16(acc[i][j], af[i], bf[j]);
        }
        __syncthreads();
    }

    // ---- epilogue ----
    #pragma unroll
    for (int i = 0; i < 2; i++) {
        int l0 = m_off + i * 16 + g;
        int l1 = l0 + 8;
        bool v0r = (m0 + l0) < mrows;
        bool v1r = (m0 + l1) < mrows;
        int node0 = rid_s[l0];
        int node1 = rid_s[l1];
        float s0 = 0.f, s1 = 0.f;
        if (Cf != nullptr) {
            if (v0r) s0 = sparse[(size_t)node0 * NEXP + expert];
            if (v1r) s1 = sparse[(size_t)node1 * NEXP + expert];
        }
        #pragma unroll
        for (int j = 0; j < 8; j++) {
            int col = n0 + n_off + j * 8 + 2 * t;
            float2 bb2 = *(const float2*)(bias + col);
            float2 v0, v1;
            v0.x = acc[i][j][0] + bb2.x; v0.y = acc[i][j][1] + bb2.y;
            v1.x = acc[i][j][2] + bb2.x; v1.y = acc[i][j][3] + bb2.y;
            if (relu) {
                v0.x = fmaxf(v0.x, 0.f); v0.y = fmaxf(v0.y, 0.f);
                v1.x = fmaxf(v1.x, 0.f); v1.y = fmaxf(v1.y, 0.f);
            }
            if (Cf != nullptr) {
                if (v0r) {
                    float2* op = (float2*)(Cf + (size_t)node0 * HDIM + col);
                    float2 o = accum ? *op : make_float2(0.f, 0.f);
                    o.x = fmaf(s0, v0.x, o.x); o.y = fmaf(s0, v0.y, o.y);
                    *op = o;
                }
                if (v1r) {
                    float2* op = (float2*)(Cf + (size_t)node1 * HDIM + col);
                    float2 o = accum ? *op : make_float2(0.f, 0.f);
                    o.x = fmaf(s1, v1.x, o.x); o.y = fmaf(s1, v1.y, o.y);
                    *op = o;
                }
            } else {
                if (v0r) *(__half2*)(Ch + (size_t)node0 * HDIM + col) = __floats2half2_rn(v0.x, v0.y);
                if (v1r) *(__half2*)(Ch + (size_t)node1 * HDIM + col) = __floats2half2_rn(v1.x, v1.y);
            }
        }
    }
}

// ===========================================================================
// host launch
// ===========================================================================
extern "C" void kernel_launch(void* const* d_in, const int* in_sizes, int n_in,
                              void* d_out, int out_size) {
    const float* x      = (const float*)d_in[0];
    const int*   ei     = (const int*)  d_in[1];
    const int*   batch  = (const int*)  d_in[2];
    const float* W_enc  = (const float*)d_in[3];
    const float* b_enc  = (const float*)d_in[4];
    const float* Ws1    = (const float*)d_in[5];
    const float* bs1    = (const float*)d_in[6];
    const float* Ws2    = (const float*)d_in[7];
    const float* bs2    = (const float*)d_in[8];
    const float* Wt1    = (const float*)d_in[9];
    const float* bt1    = (const float*)d_in[10];
    const float* Wt2    = (const float*)d_in[11];
    const float* bt2    = (const float*)d_in[12];
    const float* W_self = (const float*)d_in[13];
    const float* W_nei  = (const float*)d_in[14];
    const float* b_exp  = (const float*)d_in[15];

    int N = in_sizes[0] / 10;
    int E = in_sizes[1] / 2;
    const int* src = ei;
    const int* dst = ei + E;
    float* out = (float*)d_out;

    float *h, *hs, *part, *sparse, *strug;
    __half *h16, *agg0, *zA, *zB, *agT, *wTh;
    int *deg, *rowptr, *cursor, *colsrc, *ng, *eg, *bsum, *boff, *xidx, *xcnt;
    cudaGetSymbolAddress((void**)&h,      g_h);
    cudaGetSymbolAddress((void**)&h16,    g_h16);
    cudaGetSymbolAddress((void**)&hs,     g_hs);
    cudaGetSymbolAddress((void**)&agg0,   g_agg0);
    cudaGetSymbolAddress((void**)&zA,     g_zA);
    cudaGetSymbolAddress((void**)&zB,     g_zB);
    cudaGetSymbolAddress((void**)&agT,    g_agT);
    cudaGetSymbolAddress((void**)&part,   g_part);
    cudaGetSymbolAddress((void**)&sparse, g_sparse);
    cudaGetSymbolAddress((void**)&strug,  g_strug);
    cudaGetSymbolAddress((void**)&wTh,    g_wTh);
    cudaGetSymbolAddress((void**)&deg,    g_deg);
    cudaGetSymbolAddress((void**)&rowptr, g_rowptr);
    cudaGetSymbolAddress((void**)&cursor, g_cursor);
    cudaGetSymbolAddress((void**)&colsrc, g_colsrc);
    cudaGetSymbolAddress((void**)&ng,     g_ng);
    cudaGetSymbolAddress((void**)&eg,     g_eg);
    cudaGetSymbolAddress((void**)&bsum,   g_bsum);
    cudaGetSymbolAddress((void**)&boff,   g_boff);
    cudaGetSymbolAddress((void**)&xidx,   g_xidx);
    cudaGetSymbolAddress((void**)&xcnt,   g_xcnt);

    cudaFuncSetAttribute(k_tmma, cudaFuncAttributeMaxDynamicSharedMemorySize, TM_SMEM);

    const size_t ZSZ = (size_t)MAXN * HDIM;
    int nsb = (N + 1023) / 1024;
    int agrid = (N + 7) / 8;

    // ---- capture-root fork: all secondary streams join via evA
    cudaEventRecord(g_sp.evA, 0);

    // encode stream (s[3] is idle until fork): h + h16
    cudaStreamWaitEvent(g_sp.s[3], g_sp.evA, 0);
    k_encode<<<N, 256, 0, g_sp.s[3]>>>(x, W_enc, b_enc, h, h16, N);
    cudaEventRecord(g_sp.evE, g_sp.s[3]);

    // router stream: pack + histograms + structural + (wait h) gemm + gates
    cudaStream_t rs = g_sp.s[NSTREAM];
    cudaStreamWaitEvent(rs, g_sp.evA, 0);
    cudaMemsetAsync(ng,   0, NGRAPH * sizeof(int), rs);
    cudaMemsetAsync(eg,   0, NGRAPH * sizeof(int), rs);
    cudaMemsetAsync(xcnt, 0, NEXP * sizeof(int), rs);
    k_pack<<<24 * 256 * 512 / 256, 256, 0, rs>>>(W_self, W_nei, wTh);
    k_hist_nodes<<<128, 256, 0, rs>>>(batch, ng, N);
    k_hist_edges<<<256, 256, 0, rs>>>(batch, src, eg, E);
    k_stru<<<NGRAPH, 256, 0, rs>>>(ng, eg, Wt1, bt1, Wt2, bt2, strug);
    cudaStreamWaitEvent(rs, g_sp.evE, 0);
    {
        dim3 rgrid((N + BMR - 1) / BMR, HDIM / BNR);
        k_gemm<<<rgrid, 256, 0, rs>>>(h, Ws1, bs1, N, hs);
        k_logits<<<(N + 7) / 8, 256, 0, rs>>>(hs, Ws2, bs2, strug, batch,
                                              sparse, xidx, xcnt, N);
        cudaEventRecord(g_sp.evB, rs);
    }

    // stream 0: CSR build starts immediately (depends only on edge_index)
    cudaMemsetAsync(deg, 0, (size_t)N * sizeof(int), 0);
    k_deg<<<(E + 255) / 256, 256>>>(dst, deg, E);
    k_scan1<<<nsb, 1024>>>(deg, rowptr, bsum, N);
    k_scan2<<<1, 64>>>(bsum, boff, nsb);
    k_scan3<<<nsb, 1024>>>(deg, rowptr, boff, cursor, N);
    k_sortedges<<<(E + 255) / 256, 256>>>(src, dst, cursor, colsrc, E);
    cudaStreamWaitEvent(0, g_sp.evE, 0);
    k_agg<<<agrid, 256>>>((const uint4*)h16, (uint4*)agg0, rowptr, colsrc, N, nullptr, nullptr);

    cudaEventRecord(g_sp.fork, 0);

    // ---- 4 parallel expert chains, 2 experts each; streams 2,3 staggered.
    // Dense layers need only `fork`; evB (gates) is waited mid-chain, right
    // before the first kernel that reads sparse/xidx/xcnt.
    dim3 mgrid((N + 127) / 128, 2);
    for (int i = 0; i < NSTREAM; i++) {
        cudaStream_t st = g_sp.s[i];
        cudaStreamWaitEvent(st, g_sp.fork, 0);
        if (i >= 2) cudaStreamWaitEvent(st, g_sp.stg[i - 2], 0);
        __half* zAi = zA + (size_t)i * ZSZ;
        __half* zBi = zB + (size_t)i * ZSZ;
        __half* agi = agT + (size_t)i * ZSZ;
        float*  pti = part + (size_t)i * ZSZ;
        cudaMemsetAsync(pti, 0, ZSZ * sizeof(float), st);   // gated accumulation base
        for (int j = 0; j < 2; j++) {
            int e = i * 2 + j;
            const __half* wt0 = wTh + (size_t)(e * 3 + 0) * 256 * 512;
            const __half* wt1 = wTh + (size_t)(e * 3 + 1) * 256 * 512;
            const __half* wt2 = wTh + (size_t)(e * 3 + 2) * 256 * 512;
            const float* b_l0 = b_exp + (size_t)(e * 3 + 0) * HDIM;
            const float* b_l1 = b_exp + (size_t)(e * 3 + 1) * HDIM;
            const float* b_l2 = b_exp + (size_t)(e * 3 + 2) * HDIM;
            const int* ri = xidx + (size_t)e * MAXN;
            const int* ct = xcnt + e;

            // dense layers 0,1 (all nodes — needed by graph aggregation)
            k_tmma<<<mgrid, 256, TM_SMEM, st>>>(h16, agg0, wt0, b_l0, N, 1, zAi, nullptr,
                                                nullptr, 0, 0, nullptr, nullptr);
            if (j == 0 && i < 2) cudaEventRecord(g_sp.stg[i], st);
            k_agg<<<agrid, 256, 0, st>>>((const uint4*)zAi, (uint4*)agi, rowptr, colsrc, N,
                                         nullptr, nullptr);
            k_tmma<<<mgrid, 256, TM_SMEM, st>>>(zAi, agi, wt1, b_l1, N, 1, zBi, nullptr,
                                                nullptr, 0, 0, nullptr, nullptr);
            // gates needed from here on
            if (j == 0) cudaStreamWaitEvent(st, g_sp.evB, 0);
            k_agg<<<agrid, 256, 0, st>>>((const uint4*)zBi, (uint4*)agi, rowptr, colsrc, N,
                                         ri, ct);
            k_tmma<<<mgrid, 256, TM_SMEM, st>>>(zBi, agi, wt2, b_l2, N, 0, nullptr, pti,
                                                sparse, e, 1, ri, ct);
        }
        cudaEventRecord(g_sp.join[i], st);
    }

    // ---- join + combine
    for (int i = 0; i < NSTREAM; i++) cudaStreamWaitEvent(0, g_sp.join[i], 0);
    int n4 = N * HDIM / 4;
    k_combine<<<(n4 + 255) / 256, 256>>>(part, part + ZSZ, part + 2 * ZSZ, part + 3 * ZSZ, out, n4);
}

// round 15
// speedup vs baseline: 8.4269x; 1.0608x over previous
#include <cuda_runtime.h>
#include <cuda_fp16.h>
#include <cstdint>
#include <cstddef>

// ---------------------------------------------------------------------------
// GraphMoEDualRouter — GB300 sm_103a.
// Round 14 (= round 13 resubmit after infra failure):
// 8 streams x 1 expert; final gated GEMM accumulates directly into out via
// fp32 atomicAdd (exactly 2 contributions per element -> commutative ->
// deterministic, bit-identical to the old part/combine tree). part buffers,
// their memsets, and k_combine deleted. Everything else from round 12.
// ---------------------------------------------------------------------------

#define HDIM 256
#define NEXP 8
#define NGRAPH 64
#define MAXN 50176
#define MAXE 1600000

typedef unsigned long long ull;

// ---- scratch (static device memory; allocation is forbidden) ----
__device__ float  g_h    [MAXN * HDIM];                 // fp32 h (router)
__device__ __half g_h16  [MAXN * HDIM];                 // fp16 h (experts)
__device__ float  g_hs   [MAXN * HDIM];                 // router hidden
__device__ __half g_agg0 [MAXN * HDIM];
__device__ __half g_zA   [NEXP][MAXN * HDIM];
__device__ __half g_zB   [NEXP][MAXN * HDIM];
__device__ __half g_agT  [NEXP][MAXN * HDIM];
__device__ float  g_sparse[MAXN * NEXP];
__device__ int    g_xidx  [NEXP][MAXN];                 // per-expert gated nodes
__device__ int    g_xcnt  [NEXP];
__device__ int    g_deg   [MAXN];
__device__ int    g_rowptr[MAXN + 1];
__device__ int    g_cursor[MAXN];
__device__ int    g_colsrc[MAXE];
__device__ int    g_bsum  [64];
__device__ int    g_boff  [64];
__device__ int    g_ng[NGRAPH];
__device__ int    g_eg[NGRAPH];
__device__ float  g_strug[NGRAPH * NEXP];
// packed transposed fp16 weights: [24 mats][256 nrows][512 k]
__device__ __half g_wTh[24 * 256 * 512];

// ---- host-side streams/events (created once, pre-main; host resources only)
struct StreamPool {
    cudaStream_t s[10];       // 0-7 expert chains, 8 router, 9 encode
    cudaEvent_t evA, evB, evE, fork, join[NEXP];
    StreamPool() {
        for (int i = 0; i < 10; i++)
            cudaStreamCreateWithFlags(&s[i], cudaStreamNonBlocking);
        cudaEventCreateWithFlags(&evA,  cudaEventDisableTiming);
        cudaEventCreateWithFlags(&evB,  cudaEventDisableTiming);
        cudaEventCreateWithFlags(&evE,  cudaEventDisableTiming);
        cudaEventCreateWithFlags(&fork, cudaEventDisableTiming);
        for (int i = 0; i < NEXP; i++)
            cudaEventCreateWithFlags(&join[i], cudaEventDisableTiming);
    }
};
static StreamPool g_sp;

// ---- helpers ----
__device__ __forceinline__ ull pack2(float lo, float hi) {
    ull r; asm("mov.b64 %0, {%1, %2};" : "=l"(r) : "f"(lo), "f"(hi)); return r;
}
__device__ __forceinline__ void fma2acc(ull& d, ull a, ull b) {
    asm("fma.rn.f32x2 %0, %1, %2, %0;" : "+l"(d) : "l"(a), "l"(b));
}
__device__ __forceinline__ void unpack2(ull v, float& lo, float& hi) {
    asm("mov.b64 {%0, %1}, %2;" : "=f"(lo), "=f"(hi) : "l"(v));
}
__device__ __forceinline__ void mma_f16(float* d, const uint32_t* a, const uint32_t* b) {
    asm volatile(
        "mma.sync.aligned.m16n8k16.row.col.f32.f16.f16.f32 "
        "{%0,%1,%2,%3}, {%4,%5,%6,%7}, {%8,%9}, {%0,%1,%2,%3};"
        : "+f"(d[0]), "+f"(d[1]), "+f"(d[2]), "+f"(d[3])
        : "r"(a[0]), "r"(a[1]), "r"(a[2]), "r"(a[3]), "r"(b[0]), "r"(b[1]));
}
__device__ __forceinline__ void ldsm_x4(uint32_t& r0, uint32_t& r1,
                                        uint32_t& r2, uint32_t& r3, uint32_t addr) {
    asm volatile("ldmatrix.sync.aligned.m8n8.x4.shared.b16 {%0,%1,%2,%3}, [%4];"
        : "=r"(r0), "=r"(r1), "=r"(r2), "=r"(r3) : "r"(addr));
}
__device__ __forceinline__ uint32_t smem_u32(const void* p) {
    uint32_t a;
    asm("{ .reg .u64 t; cvta.to.shared.u64 t, %1; cvt.u32.u64 %0, t; }" : "=r"(a) : "l"(p));
    return a;
}
__device__ __forceinline__ void cp16(uint32_t dst, const void* src, int sz) {
    asm volatile("cp.async.cg.shared.global [%0], [%1], 16, %2;"
                 :: "r"(dst), "l"(src), "r"(sz) : "memory");
}
__device__ __forceinline__ void cp16u(uint32_t dst, const void* src) {
    asm volatile("cp.async.cg.shared.global [%0], [%1], 16;"
                 :: "r"(dst), "l"(src) : "memory");
}
__device__ __forceinline__ void acc8(float* a, uint4 v) {
    const __half2* p = (const __half2*)&v;
    #pragma unroll
    for (int q = 0; q < 4; q++) {
        float2 f = __half22float2(p[q]);
        a[2 * q]     += f.x;
        a[2 * q + 1] += f.y;
    }
}

// ===========================================================================
// Small kernels
// ===========================================================================
__global__ void k_hist_nodes(const int* __restrict__ batch, int* __restrict__ ng, int n) {
    __shared__ int sh[NGRAPH];
    if (threadIdx.x < NGRAPH) sh[threadIdx.x] = 0;
    __syncthreads();
    for (int i = blockIdx.x * blockDim.x + threadIdx.x; i < n; i += gridDim.x * blockDim.x)
        atomicAdd(&sh[batch[i]], 1);
    __syncthreads();
    if (threadIdx.x < NGRAPH) atomicAdd(&ng[threadIdx.x], sh[threadIdx.x]);
}

__global__ void k_hist_edges(const int* __restrict__ batch, const int* __restrict__ src,
                             int* __restrict__ eg, int e) {
    __shared__ int sh[NGRAPH];
    if (threadIdx.x < NGRAPH) sh[threadIdx.x] = 0;
    __syncthreads();
    for (int i = blockIdx.x * blockDim.x + threadIdx.x; i < e; i += gridDim.x * blockDim.x)
        atomicAdd(&sh[batch[src[i]]], 1);
    __syncthreads();
    if (threadIdx.x < NGRAPH) atomicAdd(&eg[threadIdx.x], sh[threadIdx.x]);
}

__global__ void k_stru(const int* __restrict__ ng, const int* __restrict__ eg,
                       const float* __restrict__ Wt1, const float* __restrict__ bt1,
                       const float* __restrict__ Wt2, const float* __restrict__ bt2,
                       float* __restrict__ strug) {
    int g = blockIdx.x;
    float fn = log1pf((float)ng[g]);
    float fe = log1pf((float)eg[g]);
    __shared__ float hid[HDIM];
    int j = threadIdx.x;
    hid[j] = fmaxf(fmaf(fn, Wt1[j], fmaf(fe, Wt1[HDIM + j], bt1[j])), 0.0f);
    __syncthreads();
    int w = threadIdx.x >> 5, lane = threadIdx.x & 31;
    if (w < NEXP) {
        float acc = 0.f;
        for (int k = lane; k < HDIM; k += 32) acc = fmaf(hid[k], Wt2[k * NEXP + w], acc);
        #pragma unroll
        for (int off = 16; off; off >>= 1) acc += __shfl_down_sync(0xffffffffu, acc, off);
        if (lane == 0) strug[g * NEXP + w] = acc + bt2[w];
    }
}

__global__ void k_encode(const float* __restrict__ x, const float* __restrict__ W,
                         const float* __restrict__ b, float* __restrict__ h,
                         __half* __restrict__ h16, int n) {
    int node = blockIdx.x;
    if (node >= n) return;
    __shared__ float xs[6];
    if (threadIdx.x < 6) xs[threadIdx.x] = x[node * 10 + 4 + threadIdx.x];
    __syncthreads();
    int j = threadIdx.x;
    float acc = b[j];
    #pragma unroll
    for (int k = 0; k < 6; k++) acc = fmaf(xs[k], W[k * HDIM + j], acc);
    float v = fmaxf(acc, 0.0f);
    h[(size_t)node * HDIM + j] = v;
    h16[(size_t)node * HDIM + j] = __float2half_rn(v);
}

// ===========================================================================
// FFMA fp32 GEMM — router hidden layer only (top-2 selection needs exactness)
// ===========================================================================
#define BMR 128
#define BNR 64
#define BKR 16

__global__ __launch_bounds__(256) void k_gemm(
    const float* __restrict__ A, const float* __restrict__ W1,
    const float* __restrict__ bias, int n, float* __restrict__ C)
{
    __shared__ __align__(16) float As[BKR][BMR + 2];
    __shared__ __align__(16) float Ws[BKR][BNR];

    int m0 = blockIdx.x * BMR;
    int n0 = blockIdx.y * BNR;
    int tid = threadIdx.x;
    int tm = tid >> 4;
    int tn = tid & 15;

    ull acc2[4][4];
    #pragma unroll
    for (int i = 0; i < 4; i++)
        #pragma unroll
        for (int j = 0; j < 4; j++) acc2[i][j] = 0ull;

    for (int kc = 0; kc < HDIM; kc += BKR) {
        #pragma unroll
        for (int u = 0; u < 2; u++) {
            int idx = tid + u * 256;
            int row = idx >> 2;
            int kq  = idx & 3;
            float4 v = make_float4(0.f, 0.f, 0.f, 0.f);
            int gr = m0 + row;
            if (gr < n) v = *(const float4*)(A + (size_t)gr * HDIM + kc + kq * 4);
            As[kq * 4 + 0][row] = v.x;
            As[kq * 4 + 1][row] = v.y;
            As[kq * 4 + 2][row] = v.z;
            As[kq * 4 + 3][row] = v.w;
        }
        {
            int kk = tid >> 4, nq = tid & 15;
            float4 w = *(const float4*)(W1 + (size_t)(kc + kk) * HDIM + n0 + nq * 4);
            *(float4*)&Ws[kk][nq * 4] = w;
        }
        __syncthreads();
        #pragma unroll
        for (int kk = 0; kk < BKR; kk++) {
            ull a2[4];
            #pragma unroll
            for (int i2 = 0; i2 < 4; i2++)
                a2[i2] = *(const ull*)&As[kk][tm * 8 + i2 * 2];
            #pragma unroll
            for (int j = 0; j < 4; j++) {
                float bb = Ws[kk][tn * 4 + j];
                ull b2 = pack2(bb, bb);
                #pragma unroll
                for (int i2 = 0; i2 < 4; i2++) fma2acc(acc2[i2][j], a2[i2], b2);
            }
        }
        __syncthreads();
    }

    float4 bb4 = *(const float4*)&bias[n0 + tn * 4];
    #pragma unroll
    for (int i2 = 0; i2 < 4; i2++) {
        float4 vlo, vhi;
        unpack2(acc2[i2][0], vlo.x, vhi.x);
        unpack2(acc2[i2][1], vlo.y, vhi.y);
        unpack2(acc2[i2][2], vlo.z, vhi.z);
        unpack2(acc2[i2][3], vlo.w, vhi.w);
        #pragma unroll
        for (int rr = 0; rr < 2; rr++) {
            int row = m0 + tm * 8 + i2 * 2 + rr;
            if (row >= n) continue;
            float4 v = rr ? vhi : vlo;
            v.x = fmaxf(v.x + bb4.x, 0.f); v.y = fmaxf(v.y + bb4.y, 0.f);
            v.z = fmaxf(v.z + bb4.z, 0.f); v.w = fmaxf(v.w + bb4.w, 0.f);
            *(float4*)(C + (size_t)row * HDIM + n0 + tn * 4) = v;
        }
    }
}

// ===========================================================================
// Router logits + top-2 sparse gates + per-expert compacted node lists
// ===========================================================================
__global__ void k_logits(const float* __restrict__ hs, const float* __restrict__ Ws2,
                         const float* __restrict__ bs2, const float* __restrict__ strug,
                         const int* __restrict__ batch, float* __restrict__ sparse,
                         int* __restrict__ xidx, int* __restrict__ xcnt, int n) {
    int warp = (blockIdx.x * blockDim.x + threadIdx.x) >> 5;
    int lane = threadIdx.x & 31;
    if (warp >= n) return;
    const float* row = hs + (size_t)warp * HDIM;
    float acc[NEXP];
    #pragma unroll
    for (int o = 0; o < NEXP; o++) acc[o] = 0.f;
    for (int k = lane; k < HDIM; k += 32) {
        float v = row[k];
        const float* w2 = Ws2 + k * NEXP;
        #pragma unroll
        for (int o = 0; o < NEXP; o++) acc[o] = fmaf(v, w2[o], acc[o]);
    }
    #pragma unroll
    for (int o = 0; o < NEXP; o++)
        #pragma unroll
        for (int off = 16; off; off >>= 1) acc[o] += __shfl_down_sync(0xffffffffu, acc[o], off);
    if (lane == 0) {
        int g = batch[warp];
        float lg[NEXP];
        #pragma unroll
        for (int o = 0; o < NEXP; o++)
            lg[o] = 0.5f * (acc[o] + bs2[o]) + 0.5f * strug[g * NEXP + o];
        float m1 = -3.4e38f; int i1 = 0;
        #pragma unroll
        for (int o = 0; o < NEXP; o++) if (lg[o] > m1) { m1 = lg[o]; i1 = o; }
        float m2 = -3.4e38f; int i2 = 0;
        #pragma unroll
        for (int o = 0; o < NEXP; o++) if (o != i1 && lg[o] > m2) { m2 = lg[o]; i2 = o; }
        float e2 = __expf(m2 - m1);
        float inv = 1.0f / (1.0f + e2);
        float* srow = sparse + (size_t)warp * NEXP;
        #pragma unroll
        for (int o = 0; o < NEXP; o++) srow[o] = 0.f;
        srow[i1] = inv;
        srow[i2] = e2 * inv;
        int p1 = atomicAdd(&xcnt[i1], 1);
        xidx[i1 * MAXN + p1] = warp;
        int p2 = atomicAdd(&xcnt[i2], 1);
        xidx[i2 * MAXN + p2] = warp;
    }
}

// ===========================================================================
// CSR build: counting sort by dst with 3-phase multi-block scan
// ===========================================================================
__global__ void k_deg(const int* __restrict__ dst, int* __restrict__ deg, int e) {
    int i = blockIdx.x * blockDim.x + threadIdx.x;
    if (i < e) atomicAdd(&deg[dst[i]], 1);
}

__global__ void k_scan1(const int* __restrict__ deg, int* __restrict__ rowptr,
                        int* __restrict__ bsum, int n) {
    __shared__ int sh[1024];
    int i = blockIdx.x * 1024 + threadIdx.x;
    int v = (i < n) ? deg[i] : 0;
    sh[threadIdx.x] = v;
    __syncthreads();
    #pragma unroll
    for (int off = 1; off < 1024; off <<= 1) {
        int t = (threadIdx.x >= (unsigned)off) ? sh[threadIdx.x - off] : 0;
        __syncthreads();
        sh[threadIdx.x] += t;
        __syncthreads();
    }
    if (i < n) rowptr[i + 1] = sh[threadIdx.x];
    if (threadIdx.x == 1023) bsum[blockIdx.x] = sh[1023];
}

__global__ void k_scan2(const int* __restrict__ bsum, int* __restrict__ boff, int nb) {
    __shared__ int sh[64];
    int i = threadIdx.x;
    int orig = (i < nb) ? bsum[i] : 0;
    sh[i] = orig;
    __syncthreads();
    #pragma unroll
    for (int off = 1; off < 64; off <<= 1) {
        int t = (i >= off) ? sh[i - off] : 0;
        __syncthreads();
        sh[i] += t;
        __syncthreads();
    }
    if (i < nb) boff[i] = sh[i] - orig;
}

__global__ void k_scan3(const int* __restrict__ deg, int* __restrict__ rowptr,
                        const int* __restrict__ boff, int* __restrict__ cursor, int n) {
    int i = blockIdx.x * 1024 + threadIdx.x;
    if (i == 0) rowptr[0] = 0;
    if (i < n) {
        int inc = rowptr[i + 1] + boff[blockIdx.x];
        rowptr[i + 1] = inc;
        cursor[i] = inc - deg[i];
    }
}

__global__ void k_sortedges(const int* __restrict__ src, const int* __restrict__ dst,
                            int* __restrict__ cursor, int* __restrict__ colsrc, int e) {
    int i = blockIdx.x * blockDim.x + threadIdx.x;
    if (i < e) {
        int d = dst[i];
        int p = atomicAdd(&cursor[d], 1);
        colsrc[p] = src[i];
    }
}

// ===========================================================================
// fp16 CSR gather aggregation (fp32 accum) — warp per node, LDG.128 lanes.
// ===========================================================================
__global__ __launch_bounds__(256) void k_agg(const uint4* __restrict__ z,
                                             uint4* __restrict__ agg,
                                             const int* __restrict__ rowptr,
                                             const int* __restrict__ colsrc, int n,
                                             const int* __restrict__ ridx,
                                             const int* __restrict__ cntp) {
    int w = blockIdx.x * 8 + (threadIdx.x >> 5);
    int lane = threadIdx.x & 31;
    int cnt = (ridx != nullptr) ? *cntp : n;
    if (w >= cnt) return;
    int node = (ridx != nullptr) ? ridx[w] : w;
    int s0 = rowptr[node], s1 = rowptr[node + 1];

    float a0[8], a1[8], a2[8], a3[8];
    #pragma unroll
    for (int k = 0; k < 8; k++) { a0[k] = a1[k] = a2[k] = a3[k] = 0.f; }

    int i = s0;
    for (; i + 3 < s1; i += 4) {
        int sA = colsrc[i], sB = colsrc[i + 1], sC = colsrc[i + 2], sD = colsrc[i + 3];
        uint4 vA = z[(size_t)sA * 32 + lane];
        uint4 vB = z[(size_t)sB * 32 + lane];
        uint4 vC = z[(size_t)sC * 32 + lane];
        uint4 vD = z[(size_t)sD * 32 + lane];
        acc8(a0, vA); acc8(a1, vB); acc8(a2, vC); acc8(a3, vD);
    }
    for (; i < s1; i++) acc8(a0, z[(size_t)colsrc[i] * 32 + lane]);

    uint4 o;
    __half2* op = (__half2*)&o;
    #pragma unroll
    for (int q = 0; q < 4; q++) {
        float rx = (a0[2 * q]     + a1[2 * q])     + (a2[2 * q]     + a3[2 * q]);
        float ry = (a0[2 * q + 1] + a1[2 * q + 1]) + (a2[2 * q + 1] + a3[2 * q + 1]);
        op[q] = __floats2half2_rn(rx, ry);
    }
    agg[(size_t)node * 32 + lane] = o;
}

// ===========================================================================
// Weight pack
// ===========================================================================
__global__ void k_pack(const float* __restrict__ Wself, const float* __restrict__ Wnei,
                       __half* __restrict__ wTh) {
    int idx = blockIdx.x * 256 + threadIdx.x;
    int k = idx & 511;
    int rem = idx >> 9;
    int nrow = rem & 255;
    int mat = rem >> 8;
    const float* srcp = (k < 256) ? Wself : Wnei;
    int kk = k & 255;
    wTh[idx] = __float2half_rn(srcp[((size_t)mat * 256 + kk) * 256 + nrow]);
}

// ===========================================================================
// fp16 mma.sync dual GEMM; ldmatrix fragment loads; optional row list.
// Final mode (Cf != null): out[node] += gate * val via fp32 atomicAdd —
// each out element receives exactly 2 contributions total (top-2 gating),
// and fp32 add is commutative, so the result is order-independent.
// ===========================================================================
#define PADH 72
#define HBUF (128 * PADH)
#define TM_SMEM (4 * HBUF * 2)

__global__ __launch_bounds__(256, 2) void k_tmma(
    const __half* __restrict__ Az, const __half* __restrict__ Ag,
    const __half* __restrict__ WTh, const float* __restrict__ bias,
    int n, int relu, __half* __restrict__ Ch, float* __restrict__ Cf,
    const float* __restrict__ sparse, int expert,
    const int* __restrict__ ridx, const int* __restrict__ cntp)
{
    extern __shared__ __half smh[];
    __shared__ int rid_s[128];
    uint32_t sbase = smem_u32(smh);

    int tid = threadIdx.x;
    int warp = tid >> 5, lane = tid & 31;
    int m0 = blockIdx.x * 128;
    int n0 = blockIdx.y * 128;
    int m_off = (warp >> 1) * 32;
    int n_off = (warp & 1) * 64;
    int g = lane >> 2, t = lane & 3;

    int mrows = (cntp != nullptr) ? *cntp : n;
    if (m0 >= mrows) return;

    if (tid < 128) {
        int gr = m0 + tid;
        rid_s[tid] = (gr < mrows) ? ((ridx != nullptr) ? ridx[gr] : gr) : 0;
    }
    __syncthreads();

    float acc[2][8][4];
    #pragma unroll
    for (int i = 0; i < 2; i++)
        #pragma unroll
        for (int j = 0; j < 8; j++)
            #pragma unroll
            for (int r = 0; r < 4; r++) acc[i][j][r] = 0.f;

    auto issue_chunk = [&](int c, int buf) {
        const __half* Asrc = (c < 4) ? Az : Ag;
        int kb = (c & 3) * 64;
        uint32_t abase = sbase + (uint32_t)buf * (HBUF * 2);
        uint32_t bbase = sbase + (uint32_t)(2 + buf) * (HBUF * 2);
        #pragma unroll
        for (int i = 0; i < 4; i++) {
            int idx = tid + i * 256;
            int row = idx >> 3, q = idx & 7;
            int gr = m0 + row;
            int node = rid_s[row];
            cp16(abase + (uint32_t)(row * (PADH * 2) + q * 16),
                 Asrc + (size_t)node * HDIM + kb + q * 8,
                 (gr < mrows) ? 16 : 0);
            cp16u(bbase + (uint32_t)(row * (PADH * 2) + q * 16),
                  WTh + (size_t)(n0 + row) * 512 + c * 64 + q * 8);
        }
        asm volatile("cp.async.commit_group;" ::: "memory");
    };

    int a_row = m_off + (lane & 7) + ((lane >> 3) & 1) * 8;
    int a_kh  = (lane >> 4) * 8;
    uint32_t a_off0 = (uint32_t)(a_row * PADH + a_kh) * 2;
    int b_row = n_off + ((lane >> 4) & 1) * 8 + (lane & 7);
    int b_kh  = ((lane >> 3) & 1) * 8;
    uint32_t b_off0 = (uint32_t)(b_row * PADH + b_kh) * 2;

    issue_chunk(0, 0);

    for (int c = 0; c < 8; c++) {
        int buf = c & 1;
        if (c < 7) {
            issue_chunk(c + 1, buf ^ 1);
            asm volatile("cp.async.wait_group 1;" ::: "memory");
        } else {
            asm volatile("cp.async.wait_group 0;" ::: "memory");
        }
        __syncthreads();

        uint32_t a_sm = sbase + (uint32_t)buf * (HBUF * 2) + a_off0;
        uint32_t b_sm = sbase + (uint32_t)(2 + buf) * (HBUF * 2) + b_off0;
        #pragma unroll
        for (int ks = 0; ks < 4; ks++) {
            uint32_t koff = (uint32_t)(ks * 16) * 2;
            uint32_t af[2][4], bf[8][2];
            ldsm_x4(af[0][0], af[0][1], af[0][2], af[0][3], a_sm + koff);
            ldsm_x4(af[1][0], af[1][1], af[1][2], af[1][3],
                    a_sm + (uint32_t)(16 * PADH) * 2 + koff);
            #pragma unroll
            for (int q = 0; q < 4; q++)
                ldsm_x4(bf[2 * q][0], bf[2 * q][1], bf[2 * q + 1][0], bf[2 * q + 1][1],
                        b_sm + (uint32_t)(q * 16 * PADH) * 2 + koff);
            #pragma unroll
            for (int i = 0; i < 2; i++)
                #pragma unroll
                for (int j = 0; j < 8; j++)
                    mma_f16(acc[i][j], af[i], bf[j]);
        }
        __syncthreads();
    }

    // ---- epilogue ----
    #pragma unroll
    for (int i = 0; i < 2; i++) {
        int l0 = m_off + i * 16 + g;
        int l1 = l0 + 8;
        bool v0r = (m0 + l0) < mrows;
        bool v1r = (m0 + l1) < mrows;
        int node0 = rid_s[l0];
        int node1 = rid_s[l1];
        float s0 = 0.f, s1 = 0.f;
        if (Cf != nullptr) {
            if (v0r) s0 = sparse[(size_t)node0 * NEXP + expert];
            if (v1r) s1 = sparse[(size_t)node1 * NEXP + expert];
        }
        #pragma unroll
        for (int j = 0; j < 8; j++) {
            int col = n0 + n_off + j * 8 + 2 * t;
            float2 bb2 = *(const float2*)(bias + col);
            float2 v0, v1;
            v0.x = acc[i][j][0] + bb2.x; v0.y = acc[i][j][1] + bb2.y;
            v1.x = acc[i][j][2] + bb2.x; v1.y = acc[i][j][3] + bb2.y;
            if (relu) {
                v0.x = fmaxf(v0.x, 0.f); v0.y = fmaxf(v0.y, 0.f);
                v1.x = fmaxf(v1.x, 0.f); v1.y = fmaxf(v1.y, 0.f);
            }
            if (Cf != nullptr) {
                if (v0r) {
                    float* op = Cf + (size_t)node0 * HDIM + col;
                    atomicAdd(op,     s0 * v0.x);
                    atomicAdd(op + 1, s0 * v0.y);
                }
                if (v1r) {
                    float* op = Cf + (size_t)node1 * HDIM + col;
                    atomicAdd(op,     s1 * v1.x);
                    atomicAdd(op + 1, s1 * v1.y);
                }
            } else {
                if (v0r) *(__half2*)(Ch + (size_t)node0 * HDIM + col) = __floats2half2_rn(v0.x, v0.y);
                if (v1r) *(__half2*)(Ch + (size_t)node1 * HDIM + col) = __floats2half2_rn(v1.x, v1.y);
            }
        }
    }
}

// ===========================================================================
// host launch
// ===========================================================================
extern "C" void kernel_launch(void* const* d_in, const int* in_sizes, int n_in,
                              void* d_out, int out_size) {
    const float* x      = (const float*)d_in[0];
    const int*   ei     = (const int*)  d_in[1];
    const int*   batch  = (const int*)  d_in[2];
    const float* W_enc  = (const float*)d_in[3];
    const float* b_enc  = (const float*)d_in[4];
    const float* Ws1    = (const float*)d_in[5];
    const float* bs1    = (const float*)d_in[6];
    const float* Ws2    = (const float*)d_in[7];
    const float* bs2    = (const float*)d_in[8];
    const float* Wt1    = (const float*)d_in[9];
    const float* bt1    = (const float*)d_in[10];
    const float* Wt2    = (const float*)d_in[11];
    const float* bt2    = (const float*)d_in[12];
    const float* W_self = (const float*)d_in[13];
    const float* W_nei  = (const float*)d_in[14];
    const float* b_exp  = (const float*)d_in[15];

    int N = in_sizes[0] / 10;
    int E = in_sizes[1] / 2;
    const int* src = ei;
    const int* dst = ei + E;
    float* out = (float*)d_out;

    float *h, *hs, *sparse, *strug;
    __half *h16, *agg0, *zA, *zB, *agT, *wTh;
    int *deg, *rowptr, *cursor, *colsrc, *ng, *eg, *bsum, *boff, *xidx, *xcnt;
    cudaGetSymbolAddress((void**)&h,      g_h);
    cudaGetSymbolAddress((void**)&h16,    g_h16);
    cudaGetSymbolAddress((void**)&hs,     g_hs);
    cudaGetSymbolAddress((void**)&agg0,   g_agg0);
    cudaGetSymbolAddress((void**)&zA,     g_zA);
    cudaGetSymbolAddress((void**)&zB,     g_zB);
    cudaGetSymbolAddress((void**)&agT,    g_agT);
    cudaGetSymbolAddress((void**)&sparse, g_sparse);
    cudaGetSymbolAddress((void**)&strug,  g_strug);
    cudaGetSymbolAddress((void**)&wTh,    g_wTh);
    cudaGetSymbolAddress((void**)&deg,    g_deg);
    cudaGetSymbolAddress((void**)&rowptr, g_rowptr);
    cudaGetSymbolAddress((void**)&cursor, g_cursor);
    cudaGetSymbolAddress((void**)&colsrc, g_colsrc);
    cudaGetSymbolAddress((void**)&ng,     g_ng);
    cudaGetSymbolAddress((void**)&eg,     g_eg);
    cudaGetSymbolAddress((void**)&bsum,   g_bsum);
    cudaGetSymbolAddress((void**)&boff,   g_boff);
    cudaGetSymbolAddress((void**)&xidx,   g_xidx);
    cudaGetSymbolAddress((void**)&xcnt,   g_xcnt);

    cudaFuncSetAttribute(k_tmma, cudaFuncAttributeMaxDynamicSharedMemorySize, TM_SMEM);

    const size_t ZSZ = (size_t)MAXN * HDIM;
    int nsb = (N + 1023) / 1024;
    int agrid = (N + 7) / 8;

    // ---- capture-root fork
    cudaEventRecord(g_sp.evA, 0);

    // encode stream: h + h16
    cudaStreamWaitEvent(g_sp.s[9], g_sp.evA, 0);
    k_encode<<<N, 256, 0, g_sp.s[9]>>>(x, W_enc, b_enc, h, h16, N);
    cudaEventRecord(g_sp.evE, g_sp.s[9]);

    // router stream: pack + histograms + structural + (wait h) gemm + gates
    cudaStream_t rs = g_sp.s[8];
    cudaStreamWaitEvent(rs, g_sp.evA, 0);
    cudaMemsetAsync(ng,   0, NGRAPH * sizeof(int), rs);
    cudaMemsetAsync(eg,   0, NGRAPH * sizeof(int), rs);
    cudaMemsetAsync(xcnt, 0, NEXP * sizeof(int), rs);
    k_pack<<<24 * 256 * 512 / 256, 256, 0, rs>>>(W_self, W_nei, wTh);
    k_hist_nodes<<<128, 256, 0, rs>>>(batch, ng, N);
    k_hist_edges<<<256, 256, 0, rs>>>(batch, src, eg, E);
    k_stru<<<NGRAPH, 256, 0, rs>>>(ng, eg, Wt1, bt1, Wt2, bt2, strug);
    cudaStreamWaitEvent(rs, g_sp.evE, 0);
    {
        dim3 rgrid((N + BMR - 1) / BMR, HDIM / BNR);
        k_gemm<<<rgrid, 256, 0, rs>>>(h, Ws1, bs1, N, hs);
        k_logits<<<(N + 7) / 8, 256, 0, rs>>>(hs, Ws2, bs2, strug, batch,
                                              sparse, xidx, xcnt, N);
        cudaEventRecord(g_sp.evB, rs);
    }

    // stream 0: out zero + CSR build (depends only on edge_index)
    cudaMemsetAsync(out, 0, (size_t)out_size * sizeof(float), 0);
    cudaMemsetAsync(deg, 0, (size_t)N * sizeof(int), 0);
    k_deg<<<(E + 255) / 256, 256>>>(dst, deg, E);
    k_scan1<<<nsb, 1024>>>(deg, rowptr, bsum, N);
    k_scan2<<<1, 64>>>(bsum, boff, nsb);
    k_scan3<<<nsb, 1024>>>(deg, rowptr, boff, cursor, N);
    k_sortedges<<<(E + 255) / 256, 256>>>(src, dst, cursor, colsrc, E);
    cudaStreamWaitEvent(0, g_sp.evE, 0);
    k_agg<<<agrid, 256>>>((const uint4*)h16, (uint4*)agg0, rowptr, colsrc, N, nullptr, nullptr);

    cudaEventRecord(g_sp.fork, 0);

    // ---- 8 parallel expert chains, one expert each
    dim3 mgrid((N + 127) / 128, 2);
    for (int e = 0; e < NEXP; e++) {
        cudaStream_t st = g_sp.s[e];
        cudaStreamWaitEvent(st, g_sp.fork, 0);
        __half* zAi = zA + (size_t)e * ZSZ;
        __half* zBi = zB + (size_t)e * ZSZ;
        __half* agi = agT + (size_t)e * ZSZ;
        const __half* wt0 = wTh + (size_t)(e * 3 + 0) * 256 * 512;
        const __half* wt1 = wTh + (size_t)(e * 3 + 1) * 256 * 512;
        const __half* wt2 = wTh + (size_t)(e * 3 + 2) * 256 * 512;
        const float* b_l0 = b_exp + (size_t)(e * 3 + 0) * HDIM;
        const float* b_l1 = b_exp + (size_t)(e * 3 + 1) * HDIM;
        const float* b_l2 = b_exp + (size_t)(e * 3 + 2) * HDIM;
        const int* ri = xidx + (size_t)e * MAXN;
        const int* ct = xcnt + e;

        // dense layers 0,1 (all nodes — needed by graph aggregation)
        k_tmma<<<mgrid, 256, TM_SMEM, st>>>(h16, agg0, wt0, b_l0, N, 1, zAi, nullptr,
                                            nullptr, 0, nullptr, nullptr);
        k_agg<<<agrid, 256, 0, st>>>((const uint4*)zAi, (uint4*)agi, rowptr, colsrc, N,
                                     nullptr, nullptr);
        k_tmma<<<mgrid, 256, TM_SMEM, st>>>(zAi, agi, wt1, b_l1, N, 1, zBi, nullptr,
                                            nullptr, 0, nullptr, nullptr);
        // gates needed from here on
        cudaStreamWaitEvent(st, g_sp.evB, 0);
        k_agg<<<agrid, 256, 0, st>>>((const uint4*)zBi, (uint4*)agi, rowptr, colsrc, N,
                                     ri, ct);
        k_tmma<<<mgrid, 256, TM_SMEM, st>>>(zBi, agi, wt2, b_l2, N, 0, nullptr, out,
                                            sparse, e, ri, ct);
        cudaEventRecord(g_sp.join[e], st);
    }

    // ---- join back to capture stream
    for (int e = 0; e < NEXP; e++) cudaStreamWaitEvent(0, g_sp.join[e], 0);
}